// round 1
// baseline (speedup 1.0000x reference)
#include <cuda_runtime.h>
#include <cstdint>

// ---------------------------------------------------------------------------
// GraphAttentionLayer: out = relu( softmax( mask( leakyrelu( (X W1)(X W2)^T ), adj ) ) @ (X W3) )
// B=8, N=2048, C=256. All GEMMs via mma.sync m16n8k8 tf32 with 3xTF32 (hi/lo
// split) for ~fp32 accuracy. e materialized in __device__ scratch, softmax as
// a separate row kernel.
// ---------------------------------------------------------------------------

#define ALPHA_SLOPE 0.2f
#define NEG_INF_F  -1.0e12f

#define BB   8
#define NSEQ 2048
#define CDIM 256
#define M_ALL (BB * NSEQ)        // 16384

// scratch (no cudaMalloc allowed): 3 x [B,N,C] projections + [B,N,N] scores
__device__ float g_h[3ull * BB * NSEQ * CDIM];      // ~50 MB
__device__ float g_e[(unsigned long long)BB * NSEQ * NSEQ]; // 134 MB

#define BM 128
#define BN 128
#define BK 32
#define NTHR 256

// ---------------- mma helpers ----------------
__device__ __forceinline__ void mma_tf32(float c[4],
                                         uint32_t a0, uint32_t a1, uint32_t a2, uint32_t a3,
                                         uint32_t b0, uint32_t b1) {
    asm volatile(
        "mma.sync.aligned.m16n8k8.row.col.f32.tf32.tf32.f32 "
        "{%0,%1,%2,%3}, {%4,%5,%6,%7}, {%8,%9}, {%0,%1,%2,%3};\n"
        : "+f"(c[0]), "+f"(c[1]), "+f"(c[2]), "+f"(c[3])
        : "r"(a0), "r"(a1), "r"(a2), "r"(a3), "r"(b0), "r"(b1));
}

// 3xTF32 split: x ~= hi + lo, each representable in tf32
__device__ __forceinline__ void split_tf32(float x, uint32_t &hi, uint32_t &lo) {
    uint32_t h;
    asm("cvt.rna.tf32.f32 %0, %1;" : "=r"(h) : "f"(x));
    float r = x - __uint_as_float(h);
    uint32_t l;
    asm("cvt.rna.tf32.f32 %0, %1;" : "=r"(l) : "f"(r));
    hi = h; lo = l;
}

// ---------------- GEMM kernel ----------------
// MODE 0: proj   C[m,n] = sum_k A[m,k] * W_z[k,n]          (B NN layout, z picks W1/W2/W3)
// MODE 1: scores C[n,m] = sum_k h1[n,k] * h2[m,k]           (B NT layout) + leakyrelu + adj mask
// MODE 2: AV     C[n,d] = sum_m attn[n,m] * h3[m,d]         (B NN layout) + relu
template<int MODE>
__global__ void __launch_bounds__(NTHR)
gemm3x_kernel(const float* __restrict__ A,
              const float* __restrict__ B0, const float* __restrict__ B1, const float* __restrict__ B2,
              const int* __restrict__ adj, float* __restrict__ C,
              int K, int lda, int ldb, int ldc,
              long long strideA, long long strideB, long long strideC)
{
    __shared__ float As[BM][36];     // padded: conflict-free fragment reads
    __shared__ float Bs[BK][132];    // padded: conflict-free fragment reads

    const int tid  = threadIdx.x;
    const int lane = tid & 31;
    const int warp = tid >> 5;
    const int wm   = warp & 3;   // 4 warps along M
    const int wn   = warp >> 2;  // 2 warps along N
    const int lr   = lane >> 2;
    const int lc   = lane & 3;

    const int n0 = blockIdx.x * BN;
    const int m0 = blockIdx.y * BM;
    const int z  = blockIdx.z;

    const float* Ap = A + (long long)z * strideA;
    const float* Bp;
    if (MODE == 0) Bp = (z == 0) ? B0 : (z == 1) ? B1 : B2;
    else           Bp = B0 + (long long)z * strideB;
    float* Cp = C + (long long)z * strideC;

    float acc[2][8][4];
    #pragma unroll
    for (int i = 0; i < 2; i++)
        #pragma unroll
        for (int j = 0; j < 8; j++)
            #pragma unroll
            for (int q = 0; q < 4; q++) acc[i][j][q] = 0.f;

    for (int k0 = 0; k0 < K; k0 += BK) {
        // ---- load A tile [BM x BK] (row-major M,K) ----
        {
            const int m  = tid >> 3;
            const int c4 = (tid & 7) << 2;
            #pragma unroll
            for (int i = 0; i < 4; i++) {
                float4 v = *(const float4*)(Ap + (long long)(m0 + m + i * 32) * lda + k0 + c4);
                *(float4*)&As[m + i * 32][c4] = v;
            }
        }
        // ---- load B tile into Bs[k][n] ----
        if (MODE == 1) {
            // B stored (N,K) row-major: Bs[k][n] = B[(n0+n)*ldb + k0+k]
            const int n  = tid >> 3;
            const int c4 = (tid & 7) << 2;
            #pragma unroll
            for (int i = 0; i < 4; i++) {
                float4 v = *(const float4*)(Bp + (long long)(n0 + n + i * 32) * ldb + k0 + c4);
                Bs[c4 + 0][n + i * 32] = v.x;
                Bs[c4 + 1][n + i * 32] = v.y;
                Bs[c4 + 2][n + i * 32] = v.z;
                Bs[c4 + 3][n + i * 32] = v.w;
            }
        } else {
            // B stored (K,N) row-major
            const int kk = tid >> 5;
            const int c4 = (tid & 31) << 2;
            #pragma unroll
            for (int i = 0; i < 4; i++) {
                float4 v = *(const float4*)(Bp + (long long)(k0 + kk + i * 8) * ldb + n0 + c4);
                *(float4*)&Bs[kk + i * 8][c4] = v;
            }
        }
        __syncthreads();

        #pragma unroll
        for (int ks = 0; ks < 4; ks++) {
            const int kb = ks * 8;
            uint32_t aH[2][4], aL[2][4];
            #pragma unroll
            for (int mt = 0; mt < 2; mt++) {
                const int mb = wm * 32 + mt * 16;
                split_tf32(As[mb + lr    ][kb + lc    ], aH[mt][0], aL[mt][0]);
                split_tf32(As[mb + 8 + lr][kb + lc    ], aH[mt][1], aL[mt][1]);
                split_tf32(As[mb + lr    ][kb + 4 + lc], aH[mt][2], aL[mt][2]);
                split_tf32(As[mb + 8 + lr][kb + 4 + lc], aH[mt][3], aL[mt][3]);
            }
            #pragma unroll
            for (int nt = 0; nt < 8; nt++) {
                const int nb = wn * 64 + nt * 8;
                uint32_t bH0, bL0, bH1, bL1;
                split_tf32(Bs[kb + lc    ][nb + lr], bH0, bL0);
                split_tf32(Bs[kb + 4 + lc][nb + lr], bH1, bL1);
                #pragma unroll
                for (int mt = 0; mt < 2; mt++) {
                    // D += Ahi*Blo + Alo*Bhi + Ahi*Bhi  (3xTF32 ~ fp32)
                    mma_tf32(acc[mt][nt], aH[mt][0], aH[mt][1], aH[mt][2], aH[mt][3], bL0, bL1);
                    mma_tf32(acc[mt][nt], aL[mt][0], aL[mt][1], aL[mt][2], aL[mt][3], bH0, bH1);
                    mma_tf32(acc[mt][nt], aH[mt][0], aH[mt][1], aH[mt][2], aH[mt][3], bH0, bH1);
                }
            }
        }
        __syncthreads();
    }

    // ---- epilogue ----
    #pragma unroll
    for (int mt = 0; mt < 2; mt++) {
        #pragma unroll
        for (int nt = 0; nt < 8; nt++) {
            const int r0 = m0 + wm * 32 + mt * 16 + lr;
            const int c0 = n0 + wn * 64 + nt * 8 + lc * 2;
            #pragma unroll
            for (int q = 0; q < 4; q++) {
                const int r = r0 + (q >> 1) * 8;
                const int c = c0 + (q & 1);
                float v = acc[mt][nt][q];
                if (MODE == 1) {
                    v = (v > 0.f) ? v : ALPHA_SLOPE * v;
                    const int a = adj[(long long)r * NSEQ + c];
                    v = (a > 0) ? v : NEG_INF_F;
                } else if (MODE == 2) {
                    v = (v > 0.f) ? v : 0.f;
                }
                Cp[(long long)r * ldc + c] = v;
            }
        }
    }
}

// ---------------- row softmax over g_e ----------------
__global__ void __launch_bounds__(256)
softmax_kernel(float* __restrict__ e)
{
    const long long row = blockIdx.x;
    float4* p4 = (float4*)(e + row * (long long)NSEQ);
    const int tid = threadIdx.x;

    float4 v0 = p4[tid];
    float4 v1 = p4[tid + 256];

    float m = fmaxf(fmaxf(fmaxf(v0.x, v0.y), fmaxf(v0.z, v0.w)),
                    fmaxf(fmaxf(v1.x, v1.y), fmaxf(v1.z, v1.w)));

    __shared__ float red[8];
    #pragma unroll
    for (int o = 16; o > 0; o >>= 1) m = fmaxf(m, __shfl_xor_sync(0xffffffffu, m, o));
    if ((tid & 31) == 0) red[tid >> 5] = m;
    __syncthreads();
    m = red[0];
    #pragma unroll
    for (int i = 1; i < 8; i++) m = fmaxf(m, red[i]);
    __syncthreads();

    v0.x = __expf(v0.x - m); v0.y = __expf(v0.y - m);
    v0.z = __expf(v0.z - m); v0.w = __expf(v0.w - m);
    v1.x = __expf(v1.x - m); v1.y = __expf(v1.y - m);
    v1.z = __expf(v1.z - m); v1.w = __expf(v1.w - m);

    float s = v0.x + v0.y + v0.z + v0.w + v1.x + v1.y + v1.z + v1.w;
    #pragma unroll
    for (int o = 16; o > 0; o >>= 1) s += __shfl_xor_sync(0xffffffffu, s, o);
    if ((tid & 31) == 0) red[tid >> 5] = s;
    __syncthreads();
    s = red[0] + red[1] + red[2] + red[3] + red[4] + red[5] + red[6] + red[7];

    const float inv = 1.0f / s;
    v0.x *= inv; v0.y *= inv; v0.z *= inv; v0.w *= inv;
    v1.x *= inv; v1.y *= inv; v1.z *= inv; v1.w *= inv;

    p4[tid]       = v0;
    p4[tid + 256] = v1;
}

// ---------------- launcher ----------------
extern "C" void kernel_launch(void* const* d_in, const int* in_sizes, int n_in,
                              void* d_out, int out_size)
{
    const float* inp = (const float*)d_in[0];   // [8,2048,256] f32
    const int*   adj = (const int*)d_in[1];     // [2048,2048] i32
    const float* W1  = (const float*)d_in[2];   // [256,256] f32
    const float* W2  = (const float*)d_in[3];
    const float* W3  = (const float*)d_in[4];
    float* out = (float*)d_out;                 // [8,2048,256] f32

    float *h, *e;
    cudaGetSymbolAddress((void**)&h, g_h);
    cudaGetSymbolAddress((void**)&e, g_e);

    const long long HS = (long long)BB * NSEQ * CDIM;       // 4194304 per projection
    const long long BS = (long long)NSEQ * CDIM;            // per-batch h stride
    const long long ES = (long long)NSEQ * NSEQ;             // per-batch e stride

    // 1) projections: h_z = X @ W_z  (M=16384, N=256, K=256), z in {0,1,2}
    {
        dim3 g(CDIM / BN, M_ALL / BM, 3);
        gemm3x_kernel<0><<<g, NTHR>>>(inp, W1, W2, W3, nullptr, h,
                                      CDIM, CDIM, CDIM, CDIM,
                                      0LL, 0LL, HS);
    }
    // 2) scores: e[b] = leakyrelu(h1[b] @ h2[b]^T) masked by adj  (M=N=2048, K=256)
    {
        dim3 g(NSEQ / BN, NSEQ / BM, BB);
        gemm3x_kernel<1><<<g, NTHR>>>(h /*h1*/, h + HS /*h2*/, nullptr, nullptr, adj, e,
                                      CDIM, CDIM, CDIM, NSEQ,
                                      BS, BS, ES);
    }
    // 3) row softmax over e
    softmax_kernel<<<BB * NSEQ, 256>>>(e);
    // 4) out[b] = relu(attn[b] @ h3[b])  (M=2048, N=256, K=2048)
    {
        dim3 g(CDIM / BN, NSEQ / BM, BB);
        gemm3x_kernel<2><<<g, NTHR>>>(e, h + 2 * HS /*h3*/, nullptr, nullptr, nullptr, out,
                                      NSEQ, NSEQ, CDIM, CDIM,
                                      ES, BS, BS);
    }
}

// round 2
// speedup vs baseline: 1.0161x; 1.0161x over previous
#include <cuda_runtime.h>
#include <cstdint>

// ---------------------------------------------------------------------------
// GraphAttentionLayer: out = relu( softmax( mask( leakyrelu( (X W1)(X W2)^T ), adj ) ) @ (X W3) )
// B=8, N=2048, C=256.
// All GEMMs: mma.sync m16n8k8 tf32, 3xTF32 (hi/lo) for ~fp32 accuracy.
// This version: hi/lo splitting fully hoisted out of GEMM mainloops.
// Operands are pre-split in global memory (split kernels / fused epilogues);
// GEMM inner loop is pure LDS + mma.
// ---------------------------------------------------------------------------

#define ALPHA_SLOPE 0.2f
#define NEG_INF_F  -1.0e12f

#define BB   8
#define NSEQ 2048
#define CDIM 256
#define M_ALL (BB * NSEQ)        // 16384

#define BM 128
#define BN 128
#define BK 32
#define NTHR 256

#define APAD 36        // row stride (words) for m-major tiles: 36 mod 32 = 4 -> bijective banks
#define BPAD 136       // row stride (words) for k-major B tiles: 136 mod 32 = 8 -> bijective banks

// dynamic smem layout (words)
#define OFF_AH 0
#define OFF_AL (BM * APAD)                 // 4608
#define OFF_BH (2 * BM * APAD)             // 9216
#define OFF_BL (2 * BM * APAD + BM * APAD) // 13824 (B region sized for max(128*36, 32*136)=4608)
#define SMEM_WORDS (4 * BM * APAD)         // 18432 words = 73728 B
#define SMEM_BYTES (SMEM_WORDS * 4)

// ---- global scratch (no cudaMalloc allowed) ----
__device__ float g_xH[(size_t)BB * NSEQ * CDIM];
__device__ float g_xL[(size_t)BB * NSEQ * CDIM];
__device__ float g_wH[3 * CDIM * CDIM];
__device__ float g_wL[3 * CDIM * CDIM];
__device__ float g_hH[3ull * BB * NSEQ * CDIM];
__device__ float g_hL[3ull * BB * NSEQ * CDIM];
__device__ float g_e[(size_t)BB * NSEQ * NSEQ];      // e, then attn_hi in place
__device__ float g_attnL[(size_t)BB * NSEQ * NSEQ];  // attn_lo

// ---------------- helpers ----------------
__device__ __forceinline__ void mma_tf32(float c[4],
                                         uint32_t a0, uint32_t a1, uint32_t a2, uint32_t a3,
                                         uint32_t b0, uint32_t b1) {
    asm volatile(
        "mma.sync.aligned.m16n8k8.row.col.f32.tf32.tf32.f32 "
        "{%0,%1,%2,%3}, {%4,%5,%6,%7}, {%8,%9}, {%0,%1,%2,%3};\n"
        : "+f"(c[0]), "+f"(c[1]), "+f"(c[2]), "+f"(c[3])
        : "r"(a0), "r"(a1), "r"(a2), "r"(a3), "r"(b0), "r"(b1));
}

__device__ __forceinline__ void split2(float x, float &hi, float &lo) {
    uint32_t h;
    asm("cvt.rna.tf32.f32 %0, %1;" : "=r"(h) : "f"(x));
    float r = x - __uint_as_float(h);
    uint32_t l;
    asm("cvt.rna.tf32.f32 %0, %1;" : "=r"(l) : "f"(r));
    hi = __uint_as_float(h);
    lo = __uint_as_float(l);
}

__device__ __forceinline__ uint32_t fu(float x) { return __float_as_uint(x); }

// ---------------- split kernel (X, W) ----------------
__global__ void __launch_bounds__(256)
split_kernel(const float* __restrict__ src, float* __restrict__ H, float* __restrict__ L, int n4)
{
    int i = blockIdx.x * blockDim.x + threadIdx.x;
    if (i >= n4) return;
    float4 v = ((const float4*)src)[i];
    float4 h4, l4;
    split2(v.x, h4.x, l4.x); split2(v.y, h4.y, l4.y);
    split2(v.z, h4.z, l4.z); split2(v.w, h4.w, l4.w);
    ((float4*)H)[i] = h4;
    ((float4*)L)[i] = l4;
}

// ---------------- GEMM kernel (pure mma mainloop) ----------------
// MODE 0: proj   C = X @ W_z  (B tile K-major), epilogue splits into CH/CL
// MODE 1: scores C[n,m] = h1[n,:]·h2[m,:] (B tile n-major), + leakyrelu + adj mask -> e
// MODE 2: AV     C = attn @ h3 (B tile K-major), + relu -> out
template<int MODE>
__global__ void __launch_bounds__(NTHR, 2)
gemm3x_kernel(const float* __restrict__ AH, const float* __restrict__ AL,
              const float* __restrict__ BH, const float* __restrict__ BL,
              const int* __restrict__ adj,
              float* __restrict__ CH, float* __restrict__ CL,
              int K, int lda, int ldb, int ldc,
              long long sA, long long sB, long long sC)
{
    extern __shared__ __align__(16) float smem[];
    float* AsH = smem + OFF_AH;
    float* AsL = smem + OFF_AL;
    float* BsH = smem + OFF_BH;
    float* BsL = smem + OFF_BL;

    const int tid  = threadIdx.x;
    const int lane = tid & 31;
    const int warp = tid >> 5;
    const int wm   = warp & 3;   // 4 warps along M
    const int wn   = warp >> 2;  // 2 warps along N
    const int lr   = lane >> 2;
    const int lc   = lane & 3;

    const int n0 = blockIdx.x * BN;
    const int m0 = blockIdx.y * BM;
    const int z  = blockIdx.z;

    const float* ApH = AH + (long long)z * sA;
    const float* ApL = AL + (long long)z * sA;
    const float* BpH = BH + (long long)z * sB;
    const float* BpL = BL + (long long)z * sB;
    float* CpH = CH + (long long)z * sC;
    float* CpL = (MODE == 0) ? (CL + (long long)z * sC) : nullptr;

    float acc[2][8][4];
    #pragma unroll
    for (int i = 0; i < 2; i++)
        #pragma unroll
        for (int j = 0; j < 8; j++)
            #pragma unroll
            for (int q = 0; q < 4; q++) acc[i][j][q] = 0.f;

    // loader indices
    const int am  = tid >> 3;            // 0..31
    const int ac4 = (tid & 7) << 2;      // 0..28
    const int bk  = tid >> 5;            // 0..7
    const int bc4 = (tid & 31) << 2;     // 0..124

    for (int k0 = 0; k0 < K; k0 += BK) {
        // ---- A tile [BM x BK], m-major ----
        #pragma unroll
        for (int i = 0; i < 4; i++) {
            const long long go = (long long)(m0 + am + i * 32) * lda + k0 + ac4;
            *(float4*)&AsH[(am + i * 32) * APAD + ac4] = *(const float4*)(ApH + go);
            *(float4*)&AsL[(am + i * 32) * APAD + ac4] = *(const float4*)(ApL + go);
        }
        // ---- B tile ----
        if (MODE == 1) {
            // B stored (N,K) row-major -> keep n-major in smem: Bs[n][k]
            #pragma unroll
            for (int i = 0; i < 4; i++) {
                const long long go = (long long)(n0 + am + i * 32) * ldb + k0 + ac4;
                *(float4*)&BsH[(am + i * 32) * APAD + ac4] = *(const float4*)(BpH + go);
                *(float4*)&BsL[(am + i * 32) * APAD + ac4] = *(const float4*)(BpL + go);
            }
        } else {
            // B stored (K,N) row-major -> k-major in smem: Bs[k][n]
            #pragma unroll
            for (int i = 0; i < 4; i++) {
                const long long go = (long long)(k0 + bk + i * 8) * ldb + n0 + bc4;
                *(float4*)&BsH[(bk + i * 8) * BPAD + bc4] = *(const float4*)(BpH + go);
                *(float4*)&BsL[(bk + i * 8) * BPAD + bc4] = *(const float4*)(BpL + go);
            }
        }
        __syncthreads();

        #pragma unroll
        for (int ks = 0; ks < 4; ks++) {
            const int kb = ks * 8;
            uint32_t aH[2][4], aL[2][4];
            #pragma unroll
            for (int mt = 0; mt < 2; mt++) {
                const int mb = (wm * 32 + mt * 16) * APAD;
                aH[mt][0] = fu(AsH[mb +      lr  * APAD + kb + lc    ]);
                aH[mt][1] = fu(AsH[mb + (8 + lr) * APAD + kb + lc    ]);
                aH[mt][2] = fu(AsH[mb +      lr  * APAD + kb + 4 + lc]);
                aH[mt][3] = fu(AsH[mb + (8 + lr) * APAD + kb + 4 + lc]);
                aL[mt][0] = fu(AsL[mb +      lr  * APAD + kb + lc    ]);
                aL[mt][1] = fu(AsL[mb + (8 + lr) * APAD + kb + lc    ]);
                aL[mt][2] = fu(AsL[mb +      lr  * APAD + kb + 4 + lc]);
                aL[mt][3] = fu(AsL[mb + (8 + lr) * APAD + kb + 4 + lc]);
            }
            #pragma unroll
            for (int nt = 0; nt < 8; nt++) {
                const int nb = wn * 64 + nt * 8;
                uint32_t bH0, bH1, bL0, bL1;
                if (MODE == 1) {
                    const int nbase = (nb + lr) * APAD + kb + lc;
                    bH0 = fu(BsH[nbase]);     bH1 = fu(BsH[nbase + 4]);
                    bL0 = fu(BsL[nbase]);     bL1 = fu(BsL[nbase + 4]);
                } else {
                    const int kbase = (kb + lc) * BPAD + nb + lr;
                    bH0 = fu(BsH[kbase]);             bH1 = fu(BsH[kbase + 4 * BPAD]);
                    bL0 = fu(BsL[kbase]);             bL1 = fu(BsL[kbase + 4 * BPAD]);
                }
                #pragma unroll
                for (int mt = 0; mt < 2; mt++) {
                    mma_tf32(acc[mt][nt], aH[mt][0], aH[mt][1], aH[mt][2], aH[mt][3], bL0, bL1);
                    mma_tf32(acc[mt][nt], aL[mt][0], aL[mt][1], aL[mt][2], aL[mt][3], bH0, bH1);
                    mma_tf32(acc[mt][nt], aH[mt][0], aH[mt][1], aH[mt][2], aH[mt][3], bH0, bH1);
                }
            }
        }
        __syncthreads();
    }

    // ---- epilogue ----
    #pragma unroll
    for (int mt = 0; mt < 2; mt++) {
        #pragma unroll
        for (int nt = 0; nt < 8; nt++) {
            const int r0 = m0 + wm * 32 + mt * 16 + lr;
            const int c0 = n0 + wn * 64 + nt * 8 + lc * 2;
            #pragma unroll
            for (int q = 0; q < 4; q++) {
                const int r = r0 + (q >> 1) * 8;
                const int c = c0 + (q & 1);
                float v = acc[mt][nt][q];
                const long long co = (long long)r * ldc + c;
                if (MODE == 0) {
                    float hi, lo;
                    split2(v, hi, lo);
                    CpH[co] = hi;
                    CpL[co] = lo;
                } else if (MODE == 1) {
                    v = (v > 0.f) ? v : ALPHA_SLOPE * v;
                    const int a = adj[(long long)r * NSEQ + c];
                    CpH[co] = (a > 0) ? v : NEG_INF_F;
                } else {
                    CpH[co] = (v > 0.f) ? v : 0.f;
                }
            }
        }
    }
}

// ---------------- row softmax: e -> attn (split hi/lo) ----------------
__global__ void __launch_bounds__(256)
softmax_kernel(float* __restrict__ e, float* __restrict__ attnL)
{
    const long long row = blockIdx.x;
    float4* pH = (float4*)(e + row * (long long)NSEQ);
    float4* pL = (float4*)(attnL + row * (long long)NSEQ);
    const int tid = threadIdx.x;

    float4 v0 = pH[tid];
    float4 v1 = pH[tid + 256];

    float m = fmaxf(fmaxf(fmaxf(v0.x, v0.y), fmaxf(v0.z, v0.w)),
                    fmaxf(fmaxf(v1.x, v1.y), fmaxf(v1.z, v1.w)));

    __shared__ float red[8];
    #pragma unroll
    for (int o = 16; o > 0; o >>= 1) m = fmaxf(m, __shfl_xor_sync(0xffffffffu, m, o));
    if ((tid & 31) == 0) red[tid >> 5] = m;
    __syncthreads();
    m = red[0];
    #pragma unroll
    for (int i = 1; i < 8; i++) m = fmaxf(m, red[i]);
    __syncthreads();

    v0.x = __expf(v0.x - m); v0.y = __expf(v0.y - m);
    v0.z = __expf(v0.z - m); v0.w = __expf(v0.w - m);
    v1.x = __expf(v1.x - m); v1.y = __expf(v1.y - m);
    v1.z = __expf(v1.z - m); v1.w = __expf(v1.w - m);

    float s = v0.x + v0.y + v0.z + v0.w + v1.x + v1.y + v1.z + v1.w;
    #pragma unroll
    for (int o = 16; o > 0; o >>= 1) s += __shfl_xor_sync(0xffffffffu, s, o);
    if ((tid & 31) == 0) red[tid >> 5] = s;
    __syncthreads();
    s = red[0] + red[1] + red[2] + red[3] + red[4] + red[5] + red[6] + red[7];

    const float inv = 1.0f / s;
    float4 h0, l0, h1, l1;
    split2(v0.x * inv, h0.x, l0.x); split2(v0.y * inv, h0.y, l0.y);
    split2(v0.z * inv, h0.z, l0.z); split2(v0.w * inv, h0.w, l0.w);
    split2(v1.x * inv, h1.x, l1.x); split2(v1.y * inv, h1.y, l1.y);
    split2(v1.z * inv, h1.z, l1.z); split2(v1.w * inv, h1.w, l1.w);

    pH[tid]       = h0;
    pH[tid + 256] = h1;
    pL[tid]       = l0;
    pL[tid + 256] = l1;
}

// ---------------- launcher ----------------
extern "C" void kernel_launch(void* const* d_in, const int* in_sizes, int n_in,
                              void* d_out, int out_size)
{
    const float* inp = (const float*)d_in[0];   // [8,2048,256] f32
    const int*   adj = (const int*)d_in[1];     // [2048,2048] i32
    const float* W1  = (const float*)d_in[2];   // [256,256] f32
    const float* W2  = (const float*)d_in[3];
    const float* W3  = (const float*)d_in[4];
    float* out = (float*)d_out;                 // [8,2048,256] f32

    float *xH, *xL, *wH, *wL, *hH, *hL, *e, *aL;
    cudaGetSymbolAddress((void**)&xH, g_xH);
    cudaGetSymbolAddress((void**)&xL, g_xL);
    cudaGetSymbolAddress((void**)&wH, g_wH);
    cudaGetSymbolAddress((void**)&wL, g_wL);
    cudaGetSymbolAddress((void**)&hH, g_hH);
    cudaGetSymbolAddress((void**)&hL, g_hL);
    cudaGetSymbolAddress((void**)&e,  g_e);
    cudaGetSymbolAddress((void**)&aL, g_attnL);

    cudaFuncSetAttribute(gemm3x_kernel<0>, cudaFuncAttributeMaxDynamicSharedMemorySize, SMEM_BYTES);
    cudaFuncSetAttribute(gemm3x_kernel<1>, cudaFuncAttributeMaxDynamicSharedMemorySize, SMEM_BYTES);
    cudaFuncSetAttribute(gemm3x_kernel<2>, cudaFuncAttributeMaxDynamicSharedMemorySize, SMEM_BYTES);

    const long long HS = (long long)BB * NSEQ * CDIM;  // per-projection stride in h
    const long long BS = (long long)NSEQ * CDIM;       // per-batch h stride
    const long long ES = (long long)NSEQ * NSEQ;       // per-batch e stride
    const int WSZ = CDIM * CDIM;

    // 0) pre-split X and W
    {
        const int xn4 = (int)(HS / 4);                  // X has BB*NSEQ*CDIM elems
        split_kernel<<<(xn4 + 255) / 256, 256>>>(inp, xH, xL, xn4);
        const int wn4 = WSZ / 4;
        split_kernel<<<(wn4 + 255) / 256, 256>>>(W1, wH,           wL,           wn4);
        split_kernel<<<(wn4 + 255) / 256, 256>>>(W2, wH + WSZ,     wL + WSZ,     wn4);
        split_kernel<<<(wn4 + 255) / 256, 256>>>(W3, wH + 2 * WSZ, wL + 2 * WSZ, wn4);
    }
    // 1) projections: h_z = X @ W_z  (M=16384, N=256, K=256), z in {0,1,2}; split output
    {
        dim3 g(CDIM / BN, M_ALL / BM, 3);
        gemm3x_kernel<0><<<g, NTHR, SMEM_BYTES>>>(xH, xL, wH, wL, nullptr, hH, hL,
                                                  CDIM, CDIM, CDIM, CDIM,
                                                  0LL, (long long)WSZ, HS);
    }
    // 2) scores: e[b] = leakyrelu(h1[b] @ h2[b]^T) masked by adj  (M=N=2048, K=256)
    {
        dim3 g(NSEQ / BN, NSEQ / BM, BB);
        gemm3x_kernel<1><<<g, NTHR, SMEM_BYTES>>>(hH, hL, hH + HS, hL + HS, adj, e, nullptr,
                                                  CDIM, CDIM, CDIM, NSEQ,
                                                  BS, BS, ES);
    }
    // 3) row softmax over e -> attn hi (in place) + attn lo
    softmax_kernel<<<BB * NSEQ, 256>>>(e, aL);
    // 4) out[b] = relu(attn[b] @ h3[b])  (M=2048, N=256, K=2048)
    {
        dim3 g(CDIM / BN, NSEQ / BM, BB);
        gemm3x_kernel<2><<<g, NTHR, SMEM_BYTES>>>(e, aL, hH + 2 * HS, hL + 2 * HS, nullptr, out, nullptr,
                                                  NSEQ, NSEQ, CDIM, CDIM,
                                                  ES, BS, BS);
    }
}

// round 3
// speedup vs baseline: 1.3746x; 1.3528x over previous
#include <cuda_runtime.h>
#include <cstdint>

// ---------------------------------------------------------------------------
// GraphAttentionLayer on GB300.
// GEMMs: mma.sync m16n8k8 tf32. Projections + scores use 3xTF32 (hi/lo) for
// ~fp32 accuracy; AV uses single-TF32 (error budget allows). Mainloops are
// multi-stage cp.async pipelines (BK=16) with one barrier per k-tile.
// ---------------------------------------------------------------------------

#define ALPHA_SLOPE 0.2f
#define NEG_INF_F  -1.0e12f

#define BB   8
#define NSEQ 2048
#define CDIM 256
#define M_ALL (BB * NSEQ)        // 16384

#define BM 128
#define BN 128
#define BK 16
#define NTHR 256

#define APAD 20        // m/n-major tile row stride (words): r*20 % 32 bijective over 8 rows
#define BPAD 136       // k-major tile row stride (words)
#define TILEA (BM * APAD)            // 2560 words

// HL-stage layout (MODE 0/1)
#define OFF_AH 0
#define OFF_AL TILEA
#define OFF_BH (2 * TILEA)
#define OFF_BL (3 * TILEA)
#define STG_HL (4 * TILEA)           // 10240 words / stage
// single-precision-operand stage layout (MODE 2)
#define SOFF_A 0
#define SOFF_B TILEA
#define STG_S  (2 * TILEA)           // 5120 words / stage

// ---- global scratch (no cudaMalloc allowed) ----
__device__ float g_xH[(size_t)M_ALL * CDIM];
__device__ float g_xL[(size_t)M_ALL * CDIM];
__device__ float g_wH[3 * CDIM * CDIM];
__device__ float g_wL[3 * CDIM * CDIM];
__device__ float g_hH[3ull * M_ALL * CDIM];
__device__ float g_hL[3ull * M_ALL * CDIM];
__device__ float g_e[(size_t)BB * NSEQ * NSEQ];   // e -> attn (tf32-rounded) in place

// ---------------- helpers ----------------
__device__ __forceinline__ void mma_tf32(float c[4],
                                         uint32_t a0, uint32_t a1, uint32_t a2, uint32_t a3,
                                         uint32_t b0, uint32_t b1) {
    asm volatile(
        "mma.sync.aligned.m16n8k8.row.col.f32.tf32.tf32.f32 "
        "{%0,%1,%2,%3}, {%4,%5,%6,%7}, {%8,%9}, {%0,%1,%2,%3};\n"
        : "+f"(c[0]), "+f"(c[1]), "+f"(c[2]), "+f"(c[3])
        : "r"(a0), "r"(a1), "r"(a2), "r"(a3), "r"(b0), "r"(b1));
}

__device__ __forceinline__ void split2(float x, float &hi, float &lo) {
    uint32_t h;
    asm("cvt.rna.tf32.f32 %0, %1;" : "=r"(h) : "f"(x));
    float r = x - __uint_as_float(h);
    uint32_t l;
    asm("cvt.rna.tf32.f32 %0, %1;" : "=r"(l) : "f"(r));
    hi = __uint_as_float(h);
    lo = __uint_as_float(l);
}

__device__ __forceinline__ float tf32r(float x) {
    uint32_t u;
    asm("cvt.rna.tf32.f32 %0, %1;" : "=r"(u) : "f"(x));
    return __uint_as_float(u);
}

__device__ __forceinline__ uint32_t fu(float x) { return __float_as_uint(x); }

__device__ __forceinline__ void cpa16(uint32_t dst, const void* src) {
    asm volatile("cp.async.cg.shared.global [%0], [%1], 16;\n" :: "r"(dst), "l"(src) : "memory");
}
__device__ __forceinline__ void cpa_commit() {
    asm volatile("cp.async.commit_group;\n" ::: "memory");
}
template<int N>
__device__ __forceinline__ void cpa_wait() {
    asm volatile("cp.async.wait_group %0;\n" :: "n"(N) : "memory");
}

// ---------------- split kernel (X, W) ----------------
__global__ void __launch_bounds__(256)
split_kernel(const float* __restrict__ src, float* __restrict__ H, float* __restrict__ L, int n4)
{
    int i = blockIdx.x * blockDim.x + threadIdx.x;
    if (i >= n4) return;
    float4 v = ((const float4*)src)[i];
    float4 h4, l4;
    split2(v.x, h4.x, l4.x); split2(v.y, h4.y, l4.y);
    split2(v.z, h4.z, l4.z); split2(v.w, h4.w, l4.w);
    ((float4*)H)[i] = h4;
    ((float4*)L)[i] = l4;
}

// ---------------- pipelined GEMM ----------------
// MODE 0: proj   C = X @ W_z  (B k-major, 3xTF32), epilogue split -> CH/CL
// MODE 1: scores C[n,m] = h1·h2^T (B n-major, 3xTF32), leakyrelu + adj mask -> e
// MODE 2: AV     C = attn @ h3 (B k-major, single TF32), relu -> out
template<int MODE, int STAGES>
__global__ void __launch_bounds__(NTHR, 2)
gemm_pipe(const float* __restrict__ AH_, const float* __restrict__ AL_,
          const float* __restrict__ BH_, const float* __restrict__ BL_,
          const int* __restrict__ adj,
          float* __restrict__ CH, float* __restrict__ CL,
          int K, int lda, int ldb, int ldc,
          long long sA, long long sB, long long sC)
{
    extern __shared__ __align__(16) float smem[];
    constexpr int STG = (MODE == 2) ? STG_S : STG_HL;

    const int tid  = threadIdx.x;
    const int lane = tid & 31;
    const int warp = tid >> 5;
    const int wm = warp & 3, wn = warp >> 2;
    const int lr = lane >> 2, lc = lane & 3;
    const int n0 = blockIdx.x * BN;
    const int m0 = blockIdx.y * BM;
    const int z  = blockIdx.z;

    const float* ApH = AH_ + (long long)z * sA + (long long)m0 * lda;
    const float* ApL = (MODE != 2) ? (AL_ + (long long)z * sA + (long long)m0 * lda) : nullptr;
    const float* BpH;
    const float* BpL = nullptr;
    if (MODE == 1) {
        BpH = BH_ + (long long)z * sB + (long long)n0 * ldb;
        BpL = BL_ + (long long)z * sB + (long long)n0 * ldb;
    } else {
        BpH = BH_ + (long long)z * sB + n0;
        if (MODE == 0) BpL = BL_ + (long long)z * sB + n0;
    }

    uint32_t sbase;
    asm("{ .reg .u64 t; cvta.to.shared.u64 t, %1; cvt.u32.u64 %0, t; }" : "=r"(sbase) : "l"(smem));

    // loader indices
    const int arow = tid >> 2;            // 0..63
    const int acol = (tid & 3) << 2;      // 0,4,8,12
    const int bkr  = tid >> 5;            // 0..7
    const int bcol = lane << 2;           // 0..124

    auto issue = [&](int t) {
        const int buf = t % STAGES;
        const uint32_t sb = sbase + (uint32_t)(buf * STG) * 4u;
        const int kofs = t * BK;
        #pragma unroll
        for (int i = 0; i < 2; i++) {
            const int r = arow + i * 64;
            const long long go = (long long)r * lda + kofs + acol;
            cpa16(sb + (uint32_t)((MODE == 2 ? SOFF_A : OFF_AH) + r * APAD + acol) * 4u, ApH + go);
            if (MODE != 2)
                cpa16(sb + (uint32_t)(OFF_AL + r * APAD + acol) * 4u, ApL + go);
        }
        if (MODE == 1) {
            #pragma unroll
            for (int i = 0; i < 2; i++) {
                const int r = arow + i * 64;
                const long long go = (long long)r * ldb + kofs + acol;
                cpa16(sb + (uint32_t)(OFF_BH + r * APAD + acol) * 4u, BpH + go);
                cpa16(sb + (uint32_t)(OFF_BL + r * APAD + acol) * 4u, BpL + go);
            }
        } else {
            #pragma unroll
            for (int i = 0; i < 2; i++) {
                const int kk = bkr + i * 8;
                const long long go = (long long)(kofs + kk) * ldb + bcol;
                cpa16(sb + (uint32_t)((MODE == 2 ? SOFF_B : OFF_BH) + kk * BPAD + bcol) * 4u, BpH + go);
                if (MODE == 0)
                    cpa16(sb + (uint32_t)(OFF_BL + kk * BPAD + bcol) * 4u, BpL + go);
            }
        }
        cpa_commit();
    };

    float acc[2][8][4];
    #pragma unroll
    for (int i = 0; i < 2; i++)
        #pragma unroll
        for (int j = 0; j < 8; j++)
            #pragma unroll
            for (int q = 0; q < 4; q++) acc[i][j][q] = 0.f;

    const int T = K / BK;
    #pragma unroll
    for (int s = 0; s < STAGES - 1; s++) issue(s);

    for (int t = 0; t < T; t++) {
        if (STAGES == 2) { cpa_wait<0>(); }
        else             { if (t < T - 1) cpa_wait<1>(); else cpa_wait<0>(); }
        __syncthreads();

        const int buf = t % STAGES;
        const float* S   = smem + buf * STG;
        const float* AsH = S + (MODE == 2 ? SOFF_A : OFF_AH);
        const float* AsL = S + OFF_AL;
        const float* BsH = S + (MODE == 2 ? SOFF_B : OFF_BH);
        const float* BsL = S + OFF_BL;

        #pragma unroll
        for (int ks = 0; ks < 2; ks++) {
            const int kb = ks * 8;
            uint32_t aH[2][4], aL[2][4];
            #pragma unroll
            for (int mt = 0; mt < 2; mt++) {
                const int mb = (wm * 32 + mt * 16) * APAD;
                aH[mt][0] = fu(AsH[mb +      lr  * APAD + kb + lc    ]);
                aH[mt][1] = fu(AsH[mb + (8 + lr) * APAD + kb + lc    ]);
                aH[mt][2] = fu(AsH[mb +      lr  * APAD + kb + 4 + lc]);
                aH[mt][3] = fu(AsH[mb + (8 + lr) * APAD + kb + 4 + lc]);
                if (MODE != 2) {
                    aL[mt][0] = fu(AsL[mb +      lr  * APAD + kb + lc    ]);
                    aL[mt][1] = fu(AsL[mb + (8 + lr) * APAD + kb + lc    ]);
                    aL[mt][2] = fu(AsL[mb +      lr  * APAD + kb + 4 + lc]);
                    aL[mt][3] = fu(AsL[mb + (8 + lr) * APAD + kb + 4 + lc]);
                }
            }
            #pragma unroll
            for (int nt = 0; nt < 8; nt++) {
                const int nb = wn * 64 + nt * 8;
                uint32_t bH0, bH1, bL0 = 0, bL1 = 0;
                if (MODE == 1) {
                    const int base = (nb + lr) * APAD + kb + lc;
                    bH0 = fu(BsH[base]);      bH1 = fu(BsH[base + 4]);
                    bL0 = fu(BsL[base]);      bL1 = fu(BsL[base + 4]);
                } else {
                    const int base = (kb + lc) * BPAD + nb + lr;
                    bH0 = fu(BsH[base]);      bH1 = fu(BsH[base + 4 * BPAD]);
                    if (MODE == 0) {
                        bL0 = fu(BsL[base]);  bL1 = fu(BsL[base + 4 * BPAD]);
                    }
                }
                #pragma unroll
                for (int mt = 0; mt < 2; mt++) {
                    if (MODE == 2) {
                        mma_tf32(acc[mt][nt], aH[mt][0], aH[mt][1], aH[mt][2], aH[mt][3], bH0, bH1);
                    } else {
                        mma_tf32(acc[mt][nt], aH[mt][0], aH[mt][1], aH[mt][2], aH[mt][3], bL0, bL1);
                        mma_tf32(acc[mt][nt], aL[mt][0], aL[mt][1], aL[mt][2], aL[mt][3], bH0, bH1);
                        mma_tf32(acc[mt][nt], aH[mt][0], aH[mt][1], aH[mt][2], aH[mt][3], bH0, bH1);
                    }
                }
            }
        }
        const int tn = t + STAGES - 1;
        if (tn < T) issue(tn);
    }

    // ---- epilogue ----
    float* CpH = CH + (long long)z * sC;
    float* CpL = (MODE == 0) ? (CL + (long long)z * sC) : nullptr;
    #pragma unroll
    for (int mt = 0; mt < 2; mt++) {
        #pragma unroll
        for (int nt = 0; nt < 8; nt++) {
            const int r0 = m0 + wm * 32 + mt * 16 + lr;
            const int c0 = n0 + wn * 64 + nt * 8 + lc * 2;
            #pragma unroll
            for (int q = 0; q < 4; q++) {
                const int r = r0 + (q >> 1) * 8;
                const int c = c0 + (q & 1);
                float v = acc[mt][nt][q];
                const long long co = (long long)r * ldc + c;
                if (MODE == 0) {
                    float hi, lo;
                    split2(v, hi, lo);
                    CpH[co] = hi;
                    CpL[co] = lo;
                } else if (MODE == 1) {
                    v = (v > 0.f) ? v : ALPHA_SLOPE * v;
                    const int a = adj[(long long)r * NSEQ + c];
                    CpH[co] = (a > 0) ? v : NEG_INF_F;
                } else {
                    CpH[co] = (v > 0.f) ? v : 0.f;
                }
            }
        }
    }
}

// ---------------- row softmax: e -> tf32-rounded attn, in place ----------------
__global__ void __launch_bounds__(256)
softmax_kernel(float* __restrict__ e)
{
    const long long row = blockIdx.x;
    float4* p4 = (float4*)(e + row * (long long)NSEQ);
    const int tid = threadIdx.x;

    float4 v0 = p4[tid];
    float4 v1 = p4[tid + 256];

    float m = fmaxf(fmaxf(fmaxf(v0.x, v0.y), fmaxf(v0.z, v0.w)),
                    fmaxf(fmaxf(v1.x, v1.y), fmaxf(v1.z, v1.w)));

    __shared__ float red[8];
    #pragma unroll
    for (int o = 16; o > 0; o >>= 1) m = fmaxf(m, __shfl_xor_sync(0xffffffffu, m, o));
    if ((tid & 31) == 0) red[tid >> 5] = m;
    __syncthreads();
    m = red[0];
    #pragma unroll
    for (int i = 1; i < 8; i++) m = fmaxf(m, red[i]);
    __syncthreads();

    v0.x = __expf(v0.x - m); v0.y = __expf(v0.y - m);
    v0.z = __expf(v0.z - m); v0.w = __expf(v0.w - m);
    v1.x = __expf(v1.x - m); v1.y = __expf(v1.y - m);
    v1.z = __expf(v1.z - m); v1.w = __expf(v1.w - m);

    float s = v0.x + v0.y + v0.z + v0.w + v1.x + v1.y + v1.z + v1.w;
    #pragma unroll
    for (int o = 16; o > 0; o >>= 1) s += __shfl_xor_sync(0xffffffffu, s, o);
    if ((tid & 31) == 0) red[tid >> 5] = s;
    __syncthreads();
    s = red[0] + red[1] + red[2] + red[3] + red[4] + red[5] + red[6] + red[7];

    const float inv = 1.0f / s;
    v0.x = tf32r(v0.x * inv); v0.y = tf32r(v0.y * inv);
    v0.z = tf32r(v0.z * inv); v0.w = tf32r(v0.w * inv);
    v1.x = tf32r(v1.x * inv); v1.y = tf32r(v1.y * inv);
    v1.z = tf32r(v1.z * inv); v1.w = tf32r(v1.w * inv);

    p4[tid]       = v0;
    p4[tid + 256] = v1;
}

// ---------------- launcher ----------------
extern "C" void kernel_launch(void* const* d_in, const int* in_sizes, int n_in,
                              void* d_out, int out_size)
{
    const float* inp = (const float*)d_in[0];   // [8,2048,256] f32
    const int*   adj = (const int*)d_in[1];     // [2048,2048] i32
    const float* W1  = (const float*)d_in[2];   // [256,256] f32
    const float* W2  = (const float*)d_in[3];
    const float* W3  = (const float*)d_in[4];
    float* out = (float*)d_out;                 // [8,2048,256] f32

    float *xH, *xL, *wH, *wL, *hH, *hL, *e;
    cudaGetSymbolAddress((void**)&xH, g_xH);
    cudaGetSymbolAddress((void**)&xL, g_xL);
    cudaGetSymbolAddress((void**)&wH, g_wH);
    cudaGetSymbolAddress((void**)&wL, g_wL);
    cudaGetSymbolAddress((void**)&hH, g_hH);
    cudaGetSymbolAddress((void**)&hL, g_hL);
    cudaGetSymbolAddress((void**)&e,  g_e);

    const int SM_HL = STG_HL * 2 * 4;  // 81920 B (2 stages)
    const int SM_S  = STG_S  * 3 * 4;  // 61440 B (3 stages)
    cudaFuncSetAttribute(gemm_pipe<0,2>, cudaFuncAttributeMaxDynamicSharedMemorySize, SM_HL);
    cudaFuncSetAttribute(gemm_pipe<1,2>, cudaFuncAttributeMaxDynamicSharedMemorySize, SM_HL);
    cudaFuncSetAttribute(gemm_pipe<2,3>, cudaFuncAttributeMaxDynamicSharedMemorySize, SM_S);

    const long long HS = (long long)M_ALL * CDIM;   // per-projection h stride
    const long long BS = (long long)NSEQ * CDIM;    // per-batch h stride
    const long long ES = (long long)NSEQ * NSEQ;    // per-batch e stride
    const int WSZ = CDIM * CDIM;

    // 0) pre-split X and W
    {
        const int xn4 = (int)(HS / 4);
        split_kernel<<<(xn4 + 255) / 256, 256>>>(inp, xH, xL, xn4);
        const int wn4 = WSZ / 4;
        split_kernel<<<(wn4 + 255) / 256, 256>>>(W1, wH,           wL,           wn4);
        split_kernel<<<(wn4 + 255) / 256, 256>>>(W2, wH + WSZ,     wL + WSZ,     wn4);
        split_kernel<<<(wn4 + 255) / 256, 256>>>(W3, wH + 2 * WSZ, wL + 2 * WSZ, wn4);
    }
    // 1) projections: h_z = X @ W_z (split epilogue)
    {
        dim3 g(CDIM / BN, M_ALL / BM, 3);
        gemm_pipe<0,2><<<g, NTHR, SM_HL>>>(xH, xL, wH, wL, nullptr, hH, hL,
                                           CDIM, CDIM, CDIM, CDIM,
                                           0LL, (long long)WSZ, HS);
    }
    // 2) scores: e = mask(leakyrelu(h1 h2^T))
    {
        dim3 g(NSEQ / BN, NSEQ / BM, BB);
        gemm_pipe<1,2><<<g, NTHR, SM_HL>>>(hH, hL, hH + HS, hL + HS, adj, e, nullptr,
                                           CDIM, CDIM, CDIM, NSEQ,
                                           BS, BS, ES);
    }
    // 3) softmax rows -> tf32-rounded attn in place
    softmax_kernel<<<BB * NSEQ, 256>>>(e);
    // 4) out = relu(attn @ h3), single-TF32
    {
        dim3 g(CDIM / BN, NSEQ / BM, BB);
        gemm_pipe<2,3><<<g, NTHR, SM_S>>>(e, nullptr, hH + 2 * HS, nullptr, nullptr, out, nullptr,
                                          NSEQ, NSEQ, CDIM, CDIM,
                                          ES, BS, BS);
    }
}

// round 4
// speedup vs baseline: 1.6580x; 1.2061x over previous
#include <cuda_runtime.h>
#include <cuda_bf16.h>
#include <cstdint>

// ---------------------------------------------------------------------------
// GraphAttentionLayer on GB300 (sm_103a).
//  proj   : 3xTF32 mma m16n8k8, epilogue emits h1/h2 as bf16 hi/lo, h3 as tf32
//  scores : 3x-bf16 mma m16n8k16 (aH*bL + aL*bH + aH*bH), leakyrelu + adj mask
//  softmax: fp32 row softmax, result tf32-rounded in place
//  AV     : single-TF32 mma m16n8k8, relu
// All GEMM mainloops: cp.async multistage with true load/compute overlap
// (wait -> sync -> issue(t+S-1) -> mma(t), empty-commit tail padding).
// ---------------------------------------------------------------------------

#define ALPHA_SLOPE 0.2f
#define NEG_INF_F  -1.0e12f

#define BB   8
#define NSEQ 2048
#define CDIM 256
#define M_ALL (BB * NSEQ)        // 16384

#define BM 128
#define BN 128
#define NTHR 256

// ---- fp32 tile geometry (proj / AV), BK=16 ----
#define BKF 16
#define APAD 20
#define BPAD 136
#define TILEA (BM * APAD)        // 2560 words
#define OFF_AH 0
#define OFF_AL TILEA
#define OFF_BH (2 * TILEA)
#define OFF_BL (3 * TILEA)
#define STG_HL (4 * TILEA)       // proj stage: 10240 words
#define SOFF_A 0
#define SOFF_B TILEA
#define STG_S  (2 * TILEA)       // AV stage: 5120 words

// ---- bf16 scores tile geometry, BK=32 ----
#define BKS 32
#define SP  40                   // bf16 pitch per row (80B)
#define STILE (BM * SP)          // 5120 bf16 per array
#define SA_H 0
#define SA_L STILE
#define SB_H (2 * STILE)
#define SB_L (3 * STILE)
#define SSTG (4 * STILE)         // 20480 bf16 = 40960 B / stage

// ---- global scratch ----
__device__ float g_xH[(size_t)M_ALL * CDIM];
__device__ float g_xL[(size_t)M_ALL * CDIM];
__device__ float g_wH[3 * CDIM * CDIM];
__device__ float g_wL[3 * CDIM * CDIM];
__device__ __nv_bfloat16 g_hbH[2ull * M_ALL * CDIM];   // h1,h2 bf16 hi
__device__ __nv_bfloat16 g_hbL[2ull * M_ALL * CDIM];   // h1,h2 bf16 lo
__device__ float g_h3[(size_t)M_ALL * CDIM];           // h3 (tf32-rounded)
__device__ float g_e[(size_t)BB * NSEQ * NSEQ];        // e -> attn in place

// ---------------- helpers ----------------
__device__ __forceinline__ void mma_tf32(float c[4],
                                         uint32_t a0, uint32_t a1, uint32_t a2, uint32_t a3,
                                         uint32_t b0, uint32_t b1) {
    asm volatile(
        "mma.sync.aligned.m16n8k8.row.col.f32.tf32.tf32.f32 "
        "{%0,%1,%2,%3}, {%4,%5,%6,%7}, {%8,%9}, {%0,%1,%2,%3};\n"
        : "+f"(c[0]), "+f"(c[1]), "+f"(c[2]), "+f"(c[3])
        : "r"(a0), "r"(a1), "r"(a2), "r"(a3), "r"(b0), "r"(b1));
}

__device__ __forceinline__ void mma_bf16(float c[4],
                                         uint32_t a0, uint32_t a1, uint32_t a2, uint32_t a3,
                                         uint32_t b0, uint32_t b1) {
    asm volatile(
        "mma.sync.aligned.m16n8k16.row.col.f32.bf16.bf16.f32 "
        "{%0,%1,%2,%3}, {%4,%5,%6,%7}, {%8,%9}, {%0,%1,%2,%3};\n"
        : "+f"(c[0]), "+f"(c[1]), "+f"(c[2]), "+f"(c[3])
        : "r"(a0), "r"(a1), "r"(a2), "r"(a3), "r"(b0), "r"(b1));
}

__device__ __forceinline__ void split2(float x, float &hi, float &lo) {
    uint32_t h;
    asm("cvt.rna.tf32.f32 %0, %1;" : "=r"(h) : "f"(x));
    float r = x - __uint_as_float(h);
    uint32_t l;
    asm("cvt.rna.tf32.f32 %0, %1;" : "=r"(l) : "f"(r));
    hi = __uint_as_float(h);
    lo = __uint_as_float(l);
}

__device__ __forceinline__ float tf32r(float x) {
    uint32_t u;
    asm("cvt.rna.tf32.f32 %0, %1;" : "=r"(u) : "f"(x));
    return __uint_as_float(u);
}

__device__ __forceinline__ uint32_t fu(float x) { return __float_as_uint(x); }

__device__ __forceinline__ void cpa16(uint32_t dst, const void* src) {
    asm volatile("cp.async.cg.shared.global [%0], [%1], 16;\n" :: "r"(dst), "l"(src) : "memory");
}
__device__ __forceinline__ void cpa_commit() {
    asm volatile("cp.async.commit_group;\n" ::: "memory");
}
template<int N>
__device__ __forceinline__ void cpa_wait() {
    asm volatile("cp.async.wait_group %0;\n" :: "n"(N) : "memory");
}

// ---------------- split kernel (X, W -> fp32 hi/lo) ----------------
__global__ void __launch_bounds__(256)
split_kernel(const float* __restrict__ src, float* __restrict__ H, float* __restrict__ L, int n4)
{
    int i = blockIdx.x * blockDim.x + threadIdx.x;
    if (i >= n4) return;
    float4 v = ((const float4*)src)[i];
    float4 h4, l4;
    split2(v.x, h4.x, l4.x); split2(v.y, h4.y, l4.y);
    split2(v.z, h4.z, l4.z); split2(v.w, h4.w, l4.w);
    ((float4*)H)[i] = h4;
    ((float4*)L)[i] = l4;
}

// ---------------- proj / AV pipelined GEMM (tf32) ----------------
// MODE 0: proj  C = X @ W_z, 3xTF32; z<2 -> bf16 split to CbH/CbL; z==2 -> tf32 to Cf
// MODE 2: AV    C = attn @ h3, single TF32; relu -> Cf
template<int MODE, int STAGES>
__global__ void __launch_bounds__(NTHR, 2)
gemm_pipe(const float* __restrict__ AH_, const float* __restrict__ AL_,
          const float* __restrict__ BH_, const float* __restrict__ BL_,
          float* __restrict__ Cf,
          __nv_bfloat16* __restrict__ CbH, __nv_bfloat16* __restrict__ CbL,
          int K, int lda, int ldb, int ldc,
          long long sA, long long sB, long long sC)
{
    extern __shared__ __align__(16) float smem[];
    constexpr int STG = (MODE == 2) ? STG_S : STG_HL;

    const int tid  = threadIdx.x;
    const int lane = tid & 31;
    const int warp = tid >> 5;
    const int wm = warp & 3, wn = warp >> 2;
    const int lr = lane >> 2, lc = lane & 3;
    const int n0 = blockIdx.x * BN;
    const int m0 = blockIdx.y * BM;
    const int z  = blockIdx.z;

    const float* ApH = AH_ + (long long)z * sA + (long long)m0 * lda;
    const float* ApL = (MODE == 0) ? (AL_ + (long long)z * sA + (long long)m0 * lda) : nullptr;
    const float* BpH = BH_ + (long long)z * sB + n0;
    const float* BpL = (MODE == 0) ? (BL_ + (long long)z * sB + n0) : nullptr;

    uint32_t sbase;
    asm("{ .reg .u64 t; cvta.to.shared.u64 t, %1; cvt.u32.u64 %0, t; }" : "=r"(sbase) : "l"(smem));

    const int arow = tid >> 2;            // 0..63
    const int acol = (tid & 3) << 2;      // 0,4,8,12
    const int bkr  = tid >> 5;            // 0..7
    const int bcol = lane << 2;           // 0..124

    auto issue = [&](int t) {
        const int buf = t % STAGES;
        const uint32_t sb = sbase + (uint32_t)(buf * STG) * 4u;
        const int kofs = t * BKF;
        #pragma unroll
        for (int i = 0; i < 2; i++) {
            const int r = arow + i * 64;
            const long long go = (long long)r * lda + kofs + acol;
            cpa16(sb + (uint32_t)((MODE == 2 ? SOFF_A : OFF_AH) + r * APAD + acol) * 4u, ApH + go);
            if (MODE == 0)
                cpa16(sb + (uint32_t)(OFF_AL + r * APAD + acol) * 4u, ApL + go);
        }
        #pragma unroll
        for (int i = 0; i < 2; i++) {
            const int kk = bkr + i * 8;
            const long long go = (long long)(kofs + kk) * ldb + bcol;
            cpa16(sb + (uint32_t)((MODE == 2 ? SOFF_B : OFF_BH) + kk * BPAD + bcol) * 4u, BpH + go);
            if (MODE == 0)
                cpa16(sb + (uint32_t)(OFF_BL + kk * BPAD + bcol) * 4u, BpL + go);
        }
        cpa_commit();
    };

    float acc[2][8][4];
    #pragma unroll
    for (int i = 0; i < 2; i++)
        #pragma unroll
        for (int j = 0; j < 8; j++)
            #pragma unroll
            for (int q = 0; q < 4; q++) acc[i][j][q] = 0.f;

    const int T = K / BKF;
    #pragma unroll
    for (int s = 0; s < STAGES - 1; s++) issue(s);

    for (int t = 0; t < T; t++) {
        cpa_wait<STAGES - 2>();          // oldest group (tile t) complete
        __syncthreads();
        const int tn = t + STAGES - 1;
        if (tn < T) issue(tn); else cpa_commit();   // keep group count constant

        const int buf = t % STAGES;
        const float* S   = smem + buf * STG;
        const float* AsH = S + (MODE == 2 ? SOFF_A : OFF_AH);
        const float* AsL = S + OFF_AL;
        const float* BsH = S + (MODE == 2 ? SOFF_B : OFF_BH);
        const float* BsL = S + OFF_BL;

        #pragma unroll
        for (int ks = 0; ks < 2; ks++) {
            const int kb = ks * 8;
            uint32_t aH[2][4], aL[2][4];
            #pragma unroll
            for (int mt = 0; mt < 2; mt++) {
                const int mb = (wm * 32 + mt * 16) * APAD;
                aH[mt][0] = fu(AsH[mb +      lr  * APAD + kb + lc    ]);
                aH[mt][1] = fu(AsH[mb + (8 + lr) * APAD + kb + lc    ]);
                aH[mt][2] = fu(AsH[mb +      lr  * APAD + kb + 4 + lc]);
                aH[mt][3] = fu(AsH[mb + (8 + lr) * APAD + kb + 4 + lc]);
                if (MODE == 0) {
                    aL[mt][0] = fu(AsL[mb +      lr  * APAD + kb + lc    ]);
                    aL[mt][1] = fu(AsL[mb + (8 + lr) * APAD + kb + lc    ]);
                    aL[mt][2] = fu(AsL[mb +      lr  * APAD + kb + 4 + lc]);
                    aL[mt][3] = fu(AsL[mb + (8 + lr) * APAD + kb + 4 + lc]);
                }
            }
            #pragma unroll
            for (int nt = 0; nt < 8; nt++) {
                const int nb = wn * 64 + nt * 8;
                const int base = (kb + lc) * BPAD + nb + lr;
                uint32_t bH0 = fu(BsH[base]);
                uint32_t bH1 = fu(BsH[base + 4 * BPAD]);
                #pragma unroll
                for (int mt = 0; mt < 2; mt++) {
                    if (MODE == 2) {
                        mma_tf32(acc[mt][nt], aH[mt][0], aH[mt][1], aH[mt][2], aH[mt][3], bH0, bH1);
                    } else {
                        uint32_t bL0 = fu(BsL[base]);
                        uint32_t bL1 = fu(BsL[base + 4 * BPAD]);
                        mma_tf32(acc[mt][nt], aH[mt][0], aH[mt][1], aH[mt][2], aH[mt][3], bL0, bL1);
                        mma_tf32(acc[mt][nt], aL[mt][0], aL[mt][1], aL[mt][2], aL[mt][3], bH0, bH1);
                        mma_tf32(acc[mt][nt], aH[mt][0], aH[mt][1], aH[mt][2], aH[mt][3], bH0, bH1);
                    }
                }
            }
        }
    }

    // ---- epilogue ----
    #pragma unroll
    for (int mt = 0; mt < 2; mt++) {
        #pragma unroll
        for (int nt = 0; nt < 8; nt++) {
            const int r0 = m0 + wm * 32 + mt * 16 + lr;
            const int c0 = n0 + wn * 64 + nt * 8 + lc * 2;
            if (MODE == 0 && z < 2) {
                // bf16 hi/lo split, packed bf162 stores
                __nv_bfloat16* DH = CbH + (size_t)z * M_ALL * CDIM;
                __nv_bfloat16* DL = CbL + (size_t)z * M_ALL * CDIM;
                #pragma unroll
                for (int rq = 0; rq < 2; rq++) {
                    const int r = r0 + rq * 8;
                    float v0 = acc[mt][nt][rq * 2 + 0];
                    float v1 = acc[mt][nt][rq * 2 + 1];
                    __nv_bfloat16 h0 = __float2bfloat16_rn(v0);
                    __nv_bfloat16 h1 = __float2bfloat16_rn(v1);
                    __nv_bfloat16 l0 = __float2bfloat16_rn(v0 - __bfloat162float(h0));
                    __nv_bfloat16 l1 = __float2bfloat16_rn(v1 - __bfloat162float(h1));
                    const size_t o = (size_t)r * ldc + c0;
                    *(__nv_bfloat162*)(DH + o) = __nv_bfloat162(h0, h1);
                    *(__nv_bfloat162*)(DL + o) = __nv_bfloat162(l0, l1);
                }
            } else {
                float* D = Cf + ((MODE == 2) ? (long long)z * sC : 0LL);
                #pragma unroll
                for (int q = 0; q < 4; q++) {
                    const int r = r0 + (q >> 1) * 8;
                    const int c = c0 + (q & 1);
                    float v = acc[mt][nt][q];
                    if (MODE == 2) v = (v > 0.f) ? v : 0.f;
                    else           v = tf32r(v);            // h3 for tf32 AV
                    D[(long long)r * ldc + c] = v;
                }
            }
        }
    }
}

// ---------------- scores GEMM: 3x-bf16 m16n8k16 ----------------
// e[b][n][m] = mask(leakyrelu( h1[b][n,:] . h2[b][m,:] ))
__global__ void __launch_bounds__(NTHR, 2)
scores_bf16(const __nv_bfloat16* __restrict__ h1H, const __nv_bfloat16* __restrict__ h1L,
            const __nv_bfloat16* __restrict__ h2H, const __nv_bfloat16* __restrict__ h2L,
            const int* __restrict__ adj, float* __restrict__ e)
{
    extern __shared__ __align__(16) __nv_bfloat16 smb[];
    constexpr int STAGES = 2;

    const int tid  = threadIdx.x;
    const int lane = tid & 31;
    const int warp = tid >> 5;
    const int wm = warp & 3, wn = warp >> 2;
    const int lr = lane >> 2, lc = lane & 3;
    const int n0 = blockIdx.x * BN;
    const int m0 = blockIdx.y * BM;
    const int z  = blockIdx.z;

    const long long BS = (long long)NSEQ * CDIM;
    const __nv_bfloat16* A_H = h1H + z * BS + (long long)m0 * CDIM;
    const __nv_bfloat16* A_L = h1L + z * BS + (long long)m0 * CDIM;
    const __nv_bfloat16* B_H = h2H + z * BS + (long long)n0 * CDIM;
    const __nv_bfloat16* B_L = h2L + z * BS + (long long)n0 * CDIM;

    uint32_t sbase;
    asm("{ .reg .u64 t; cvta.to.shared.u64 t, %1; cvt.u32.u64 %0, t; }" : "=r"(sbase) : "l"(smb));

    const int lrow = tid >> 1;            // 0..127
    const int lcb  = (tid & 1) * 16;      // bf16 col offset {0,16}

    auto issue = [&](int t) {
        const int buf = t % STAGES;
        const uint32_t sb = sbase + (uint32_t)(buf * SSTG) * 2u;
        const int kofs = t * BKS;
        const long long go0 = (long long)lrow * CDIM + kofs + lcb;
        const uint32_t d0 = (uint32_t)(lrow * SP + lcb) * 2u;
        cpa16(sb + (SA_H * 2u) + d0,      A_H + go0);
        cpa16(sb + (SA_H * 2u) + d0 + 16, A_H + go0 + 8);
        cpa16(sb + (SA_L * 2u) + d0,      A_L + go0);
        cpa16(sb + (SA_L * 2u) + d0 + 16, A_L + go0 + 8);
        cpa16(sb + (SB_H * 2u) + d0,      B_H + go0);
        cpa16(sb + (SB_H * 2u) + d0 + 16, B_H + go0 + 8);
        cpa16(sb + (SB_L * 2u) + d0,      B_L + go0);
        cpa16(sb + (SB_L * 2u) + d0 + 16, B_L + go0 + 8);
        cpa_commit();
    };

    float acc[2][8][4];
    #pragma unroll
    for (int i = 0; i < 2; i++)
        #pragma unroll
        for (int j = 0; j < 8; j++)
            #pragma unroll
            for (int q = 0; q < 4; q++) acc[i][j][q] = 0.f;

    const int T = CDIM / BKS;   // 8
    issue(0);

    for (int t = 0; t < T; t++) {
        cpa_wait<0>();
        __syncthreads();
        if (t + 1 < T) issue(t + 1); else cpa_commit();

        const int buf = t % STAGES;
        const __nv_bfloat16* S   = smb + buf * SSTG;
        const __nv_bfloat16* AsH = S + SA_H;
        const __nv_bfloat16* AsL = S + SA_L;
        const __nv_bfloat16* BsH = S + SB_H;
        const __nv_bfloat16* BsL = S + SB_L;

        #pragma unroll
        for (int ks = 0; ks < 2; ks++) {
            const int kb = ks * 16;
            uint32_t aH[2][4], aL[2][4];
            #pragma unroll
            for (int mt = 0; mt < 2; mt++) {
                const int mr = wm * 32 + mt * 16 + lr;
                const int o0 =  mr      * SP + kb + 2 * lc;
                const int o1 = (mr + 8) * SP + kb + 2 * lc;
                aH[mt][0] = *(const uint32_t*)(AsH + o0);
                aH[mt][1] = *(const uint32_t*)(AsH + o1);
                aH[mt][2] = *(const uint32_t*)(AsH + o0 + 8);
                aH[mt][3] = *(const uint32_t*)(AsH + o1 + 8);
                aL[mt][0] = *(const uint32_t*)(AsL + o0);
                aL[mt][1] = *(const uint32_t*)(AsL + o1);
                aL[mt][2] = *(const uint32_t*)(AsL + o0 + 8);
                aL[mt][3] = *(const uint32_t*)(AsL + o1 + 8);
            }
            #pragma unroll
            for (int nt = 0; nt < 8; nt++) {
                const int nr = wn * 64 + nt * 8 + lr;
                const int ob = nr * SP + kb + 2 * lc;
                uint32_t bH0 = *(const uint32_t*)(BsH + ob);
                uint32_t bH1 = *(const uint32_t*)(BsH + ob + 8);
                uint32_t bL0 = *(const uint32_t*)(BsL + ob);
                uint32_t bL1 = *(const uint32_t*)(BsL + ob + 8);
                #pragma unroll
                for (int mt = 0; mt < 2; mt++) {
                    mma_bf16(acc[mt][nt], aH[mt][0], aH[mt][1], aH[mt][2], aH[mt][3], bL0, bL1);
                    mma_bf16(acc[mt][nt], aL[mt][0], aL[mt][1], aL[mt][2], aL[mt][3], bH0, bH1);
                    mma_bf16(acc[mt][nt], aH[mt][0], aH[mt][1], aH[mt][2], aH[mt][3], bH0, bH1);
                }
            }
        }
    }

    // ---- epilogue: leakyrelu + adj mask ----
    float* Cp = e + (long long)z * NSEQ * NSEQ;
    #pragma unroll
    for (int mt = 0; mt < 2; mt++) {
        #pragma unroll
        for (int nt = 0; nt < 8; nt++) {
            const int r0 = m0 + wm * 32 + mt * 16 + lr;
            const int c0 = n0 + wn * 64 + nt * 8 + lc * 2;
            #pragma unroll
            for (int q = 0; q < 4; q++) {
                const int r = r0 + (q >> 1) * 8;
                const int c = c0 + (q & 1);
                float v = acc[mt][nt][q];
                v = (v > 0.f) ? v : ALPHA_SLOPE * v;
                const int a = adj[(long long)r * NSEQ + c];
                Cp[(long long)r * NSEQ + c] = (a > 0) ? v : NEG_INF_F;
            }
        }
    }
}

// ---------------- row softmax: e -> tf32-rounded attn, in place ----------------
__global__ void __launch_bounds__(256)
softmax_kernel(float* __restrict__ e)
{
    const long long row = blockIdx.x;
    float4* p4 = (float4*)(e + row * (long long)NSEQ);
    const int tid = threadIdx.x;

    float4 v0 = p4[tid];
    float4 v1 = p4[tid + 256];

    float m = fmaxf(fmaxf(fmaxf(v0.x, v0.y), fmaxf(v0.z, v0.w)),
                    fmaxf(fmaxf(v1.x, v1.y), fmaxf(v1.z, v1.w)));

    __shared__ float red[8];
    #pragma unroll
    for (int o = 16; o > 0; o >>= 1) m = fmaxf(m, __shfl_xor_sync(0xffffffffu, m, o));
    if ((tid & 31) == 0) red[tid >> 5] = m;
    __syncthreads();
    m = red[0];
    #pragma unroll
    for (int i = 1; i < 8; i++) m = fmaxf(m, red[i]);
    __syncthreads();

    v0.x = __expf(v0.x - m); v0.y = __expf(v0.y - m);
    v0.z = __expf(v0.z - m); v0.w = __expf(v0.w - m);
    v1.x = __expf(v1.x - m); v1.y = __expf(v1.y - m);
    v1.z = __expf(v1.z - m); v1.w = __expf(v1.w - m);

    float s = v0.x + v0.y + v0.z + v0.w + v1.x + v1.y + v1.z + v1.w;
    #pragma unroll
    for (int o = 16; o > 0; o >>= 1) s += __shfl_xor_sync(0xffffffffu, s, o);
    if ((tid & 31) == 0) red[tid >> 5] = s;
    __syncthreads();
    s = red[0] + red[1] + red[2] + red[3] + red[4] + red[5] + red[6] + red[7];

    const float inv = 1.0f / s;
    v0.x = tf32r(v0.x * inv); v0.y = tf32r(v0.y * inv);
    v0.z = tf32r(v0.z * inv); v0.w = tf32r(v0.w * inv);
    v1.x = tf32r(v1.x * inv); v1.y = tf32r(v1.y * inv);
    v1.z = tf32r(v1.z * inv); v1.w = tf32r(v1.w * inv);

    p4[tid]       = v0;
    p4[tid + 256] = v1;
}

// ---------------- launcher ----------------
extern "C" void kernel_launch(void* const* d_in, const int* in_sizes, int n_in,
                              void* d_out, int out_size)
{
    const float* inp = (const float*)d_in[0];   // [8,2048,256] f32
    const int*   adj = (const int*)d_in[1];     // [2048,2048] i32
    const float* W1  = (const float*)d_in[2];   // [256,256] f32
    const float* W2  = (const float*)d_in[3];
    const float* W3  = (const float*)d_in[4];
    float* out = (float*)d_out;                 // [8,2048,256] f32

    float *xH, *xL, *wH, *wL, *h3, *e;
    __nv_bfloat16 *hbH, *hbL;
    cudaGetSymbolAddress((void**)&xH,  g_xH);
    cudaGetSymbolAddress((void**)&xL,  g_xL);
    cudaGetSymbolAddress((void**)&wH,  g_wH);
    cudaGetSymbolAddress((void**)&wL,  g_wL);
    cudaGetSymbolAddress((void**)&hbH, g_hbH);
    cudaGetSymbolAddress((void**)&hbL, g_hbL);
    cudaGetSymbolAddress((void**)&h3,  g_h3);
    cudaGetSymbolAddress((void**)&e,   g_e);

    const int SM_HL = STG_HL * 2 * 4;   // 81920 B (proj, 2 stages)
    const int SM_S  = STG_S  * 3 * 4;   // 61440 B (AV, 3 stages)
    const int SM_BF = SSTG   * 2 * 2;   // 81920 B (scores, 2 stages)
    cudaFuncSetAttribute(gemm_pipe<0,2>, cudaFuncAttributeMaxDynamicSharedMemorySize, SM_HL);
    cudaFuncSetAttribute(gemm_pipe<2,3>, cudaFuncAttributeMaxDynamicSharedMemorySize, SM_S);
    cudaFuncSetAttribute(scores_bf16,    cudaFuncAttributeMaxDynamicSharedMemorySize, SM_BF);

    const long long BS = (long long)NSEQ * CDIM;
    const long long ES = (long long)NSEQ * NSEQ;
    const int WSZ = CDIM * CDIM;

    // 0) pre-split X and W (fp32 hi/lo)
    {
        const int xn4 = (int)((long long)M_ALL * CDIM / 4);
        split_kernel<<<(xn4 + 255) / 256, 256>>>(inp, xH, xL, xn4);
        const int wn4 = WSZ / 4;
        split_kernel<<<(wn4 + 255) / 256, 256>>>(W1, wH,           wL,           wn4);
        split_kernel<<<(wn4 + 255) / 256, 256>>>(W2, wH + WSZ,     wL + WSZ,     wn4);
        split_kernel<<<(wn4 + 255) / 256, 256>>>(W3, wH + 2 * WSZ, wL + 2 * WSZ, wn4);
    }
    // 1) projections: z=0,1 -> bf16 hi/lo (h1,h2); z=2 -> tf32 fp32 (h3)
    {
        dim3 g(CDIM / BN, M_ALL / BM, 3);
        gemm_pipe<0,2><<<g, NTHR, SM_HL>>>(xH, xL, wH, wL, h3, hbH, hbL,
                                           CDIM, CDIM, CDIM, CDIM,
                                           0LL, (long long)WSZ, 0LL);
    }
    // 2) scores: e = mask(leakyrelu(h1 h2^T)), 3x-bf16
    {
        dim3 g(NSEQ / BN, NSEQ / BM, BB);
        scores_bf16<<<g, NTHR, SM_BF>>>(hbH, hbL,
                                        hbH + (size_t)M_ALL * CDIM, hbL + (size_t)M_ALL * CDIM,
                                        adj, e);
    }
    // 3) softmax rows -> tf32-rounded attn in place
    softmax_kernel<<<BB * NSEQ, 256>>>(e);
    // 4) out = relu(attn @ h3), single-TF32
    {
        dim3 g(CDIM / BN, NSEQ / BM, BB);
        gemm_pipe<2,3><<<g, NTHR, SM_S>>>(e, nullptr, h3, nullptr, out, nullptr, nullptr,
                                          NSEQ, NSEQ, CDIM, CDIM,
                                          ES, BS, BS);
    }
}

// round 5
// speedup vs baseline: 1.6804x; 1.0136x over previous
#include <cuda_runtime.h>
#include <cuda_bf16.h>
#include <cstdint>

// ---------------------------------------------------------------------------
// GraphAttentionLayer on GB300 (sm_103a).
//  proj   : 3xTF32 mma m16n8k8, epilogue emits h1/h2 as bf16 hi/lo, h3 as tf32
//  scores : 3x-bf16 mma m16n8k16, operands via ldmatrix.x4, leakyrelu + mask
//  softmax: fp32 row softmax, result tf32-rounded in place
//  AV     : single-TF32 mma m16n8k8, 4-stage cp.async pipeline, relu
// ---------------------------------------------------------------------------

#define ALPHA_SLOPE 0.2f
#define NEG_INF_F  -1.0e12f

#define BB   8
#define NSEQ 2048
#define CDIM 256
#define M_ALL (BB * NSEQ)        // 16384

#define BM 128
#define BN 128
#define NTHR 256

// ---- fp32 tile geometry (proj / AV), BK=16 ----
#define BKF 16
#define APAD 20
#define BPAD 136
#define TILEA (BM * APAD)        // 2560 words
#define OFF_AH 0
#define OFF_AL TILEA
#define OFF_BH (2 * TILEA)
#define OFF_BL (3 * TILEA)
#define STG_HL (4 * TILEA)       // proj stage: 10240 words
#define SOFF_A 0
#define SOFF_B TILEA
#define STG_S  (2 * TILEA)       // AV stage: 5120 words

// ---- bf16 scores tile geometry, BK=32 ----
#define BKS 32
#define SP  40                   // bf16 pitch per row (80B) -> LDSM conflict-free
#define STILE (BM * SP)          // 5120 bf16 per array
#define SA_H 0
#define SA_L STILE
#define SB_H (2 * STILE)
#define SB_L (3 * STILE)
#define SSTG (4 * STILE)         // 20480 bf16 = 40960 B / stage

// ---- global scratch ----
__device__ float g_xH[(size_t)M_ALL * CDIM];
__device__ float g_xL[(size_t)M_ALL * CDIM];
__device__ float g_wH[3 * CDIM * CDIM];
__device__ float g_wL[3 * CDIM * CDIM];
__device__ __nv_bfloat16 g_hbH[2ull * M_ALL * CDIM];   // h1,h2 bf16 hi
__device__ __nv_bfloat16 g_hbL[2ull * M_ALL * CDIM];   // h1,h2 bf16 lo
__device__ float g_h3[(size_t)M_ALL * CDIM];           // h3 (tf32-rounded)
__device__ float g_e[(size_t)BB * NSEQ * NSEQ];        // e -> attn in place

// ---------------- helpers ----------------
__device__ __forceinline__ void mma_tf32(float c[4],
                                         uint32_t a0, uint32_t a1, uint32_t a2, uint32_t a3,
                                         uint32_t b0, uint32_t b1) {
    asm volatile(
        "mma.sync.aligned.m16n8k8.row.col.f32.tf32.tf32.f32 "
        "{%0,%1,%2,%3}, {%4,%5,%6,%7}, {%8,%9}, {%0,%1,%2,%3};\n"
        : "+f"(c[0]), "+f"(c[1]), "+f"(c[2]), "+f"(c[3])
        : "r"(a0), "r"(a1), "r"(a2), "r"(a3), "r"(b0), "r"(b1));
}

__device__ __forceinline__ void mma_bf16(float c[4],
                                         uint32_t a0, uint32_t a1, uint32_t a2, uint32_t a3,
                                         uint32_t b0, uint32_t b1) {
    asm volatile(
        "mma.sync.aligned.m16n8k16.row.col.f32.bf16.bf16.f32 "
        "{%0,%1,%2,%3}, {%4,%5,%6,%7}, {%8,%9}, {%0,%1,%2,%3};\n"
        : "+f"(c[0]), "+f"(c[1]), "+f"(c[2]), "+f"(c[3])
        : "r"(a0), "r"(a1), "r"(a2), "r"(a3), "r"(b0), "r"(b1));
}

__device__ __forceinline__ void ldsm_x4(uint32_t &r0, uint32_t &r1, uint32_t &r2, uint32_t &r3,
                                        uint32_t addr) {
    asm volatile("ldmatrix.sync.aligned.m8n8.x4.shared.b16 {%0,%1,%2,%3}, [%4];\n"
        : "=r"(r0), "=r"(r1), "=r"(r2), "=r"(r3) : "r"(addr));
}

__device__ __forceinline__ void split2(float x, float &hi, float &lo) {
    uint32_t h;
    asm("cvt.rna.tf32.f32 %0, %1;" : "=r"(h) : "f"(x));
    float r = x - __uint_as_float(h);
    uint32_t l;
    asm("cvt.rna.tf32.f32 %0, %1;" : "=r"(l) : "f"(r));
    hi = __uint_as_float(h);
    lo = __uint_as_float(l);
}

__device__ __forceinline__ float tf32r(float x) {
    uint32_t u;
    asm("cvt.rna.tf32.f32 %0, %1;" : "=r"(u) : "f"(x));
    return __uint_as_float(u);
}

__device__ __forceinline__ uint32_t fu(float x) { return __float_as_uint(x); }

__device__ __forceinline__ void cpa16(uint32_t dst, const void* src) {
    asm volatile("cp.async.cg.shared.global [%0], [%1], 16;\n" :: "r"(dst), "l"(src) : "memory");
}
__device__ __forceinline__ void cpa_commit() {
    asm volatile("cp.async.commit_group;\n" ::: "memory");
}
template<int N>
__device__ __forceinline__ void cpa_wait() {
    asm volatile("cp.async.wait_group %0;\n" :: "n"(N) : "memory");
}

// ---------------- split kernels ----------------
__global__ void __launch_bounds__(256)
split_kernel(const float* __restrict__ src, float* __restrict__ H, float* __restrict__ L, int n4)
{
    int i = blockIdx.x * blockDim.x + threadIdx.x;
    if (i >= n4) return;
    float4 v = ((const float4*)src)[i];
    float4 h4, l4;
    split2(v.x, h4.x, l4.x); split2(v.y, h4.y, l4.y);
    split2(v.z, h4.z, l4.z); split2(v.w, h4.w, l4.w);
    ((float4*)H)[i] = h4;
    ((float4*)L)[i] = l4;
}

__global__ void __launch_bounds__(256)
split_w_kernel(const float* __restrict__ W1, const float* __restrict__ W2,
               const float* __restrict__ W3, float* __restrict__ H, float* __restrict__ L)
{
    const int z = blockIdx.y;
    const float* src = (z == 0) ? W1 : (z == 1) ? W2 : W3;
    const int n4 = CDIM * CDIM / 4;
    int i = blockIdx.x * blockDim.x + threadIdx.x;
    if (i >= n4) return;
    float4 v = ((const float4*)src)[i];
    float4 h4, l4;
    split2(v.x, h4.x, l4.x); split2(v.y, h4.y, l4.y);
    split2(v.z, h4.z, l4.z); split2(v.w, h4.w, l4.w);
    ((float4*)(H + (size_t)z * CDIM * CDIM))[i] = h4;
    ((float4*)(L + (size_t)z * CDIM * CDIM))[i] = l4;
}

// ---------------- proj / AV pipelined GEMM (tf32) ----------------
// MODE 0: proj  C = X @ W_z, 3xTF32; z<2 -> bf16 split to CbH/CbL; z==2 -> tf32 to Cf
// MODE 2: AV    C = attn @ h3, single TF32; relu -> Cf
template<int MODE, int STAGES>
__global__ void __launch_bounds__(NTHR, 2)
gemm_pipe(const float* __restrict__ AH_, const float* __restrict__ AL_,
          const float* __restrict__ BH_, const float* __restrict__ BL_,
          float* __restrict__ Cf,
          __nv_bfloat16* __restrict__ CbH, __nv_bfloat16* __restrict__ CbL,
          int K, int lda, int ldb, int ldc,
          long long sA, long long sB, long long sC)
{
    extern __shared__ __align__(16) float smem[];
    constexpr int STG = (MODE == 2) ? STG_S : STG_HL;

    const int tid  = threadIdx.x;
    const int lane = tid & 31;
    const int warp = tid >> 5;
    const int wm = warp & 3, wn = warp >> 2;
    const int lr = lane >> 2, lc = lane & 3;
    const int n0 = blockIdx.x * BN;
    const int m0 = blockIdx.y * BM;
    const int z  = blockIdx.z;

    const float* ApH = AH_ + (long long)z * sA + (long long)m0 * lda;
    const float* ApL = (MODE == 0) ? (AL_ + (long long)z * sA + (long long)m0 * lda) : nullptr;
    const float* BpH = BH_ + (long long)z * sB + n0;
    const float* BpL = (MODE == 0) ? (BL_ + (long long)z * sB + n0) : nullptr;

    uint32_t sbase;
    asm("{ .reg .u64 t; cvta.to.shared.u64 t, %1; cvt.u32.u64 %0, t; }" : "=r"(sbase) : "l"(smem));

    const int arow = tid >> 2;            // 0..63
    const int acol = (tid & 3) << 2;      // 0,4,8,12
    const int bkr  = tid >> 5;            // 0..7
    const int bcol = lane << 2;           // 0..124

    auto issue = [&](int t) {
        const int buf = t % STAGES;
        const uint32_t sb = sbase + (uint32_t)(buf * STG) * 4u;
        const int kofs = t * BKF;
        #pragma unroll
        for (int i = 0; i < 2; i++) {
            const int r = arow + i * 64;
            const long long go = (long long)r * lda + kofs + acol;
            cpa16(sb + (uint32_t)((MODE == 2 ? SOFF_A : OFF_AH) + r * APAD + acol) * 4u, ApH + go);
            if (MODE == 0)
                cpa16(sb + (uint32_t)(OFF_AL + r * APAD + acol) * 4u, ApL + go);
        }
        #pragma unroll
        for (int i = 0; i < 2; i++) {
            const int kk = bkr + i * 8;
            const long long go = (long long)(kofs + kk) * ldb + bcol;
            cpa16(sb + (uint32_t)((MODE == 2 ? SOFF_B : OFF_BH) + kk * BPAD + bcol) * 4u, BpH + go);
            if (MODE == 0)
                cpa16(sb + (uint32_t)(OFF_BL + kk * BPAD + bcol) * 4u, BpL + go);
        }
        cpa_commit();
    };

    float acc[2][8][4];
    #pragma unroll
    for (int i = 0; i < 2; i++)
        #pragma unroll
        for (int j = 0; j < 8; j++)
            #pragma unroll
            for (int q = 0; q < 4; q++) acc[i][j][q] = 0.f;

    const int T = K / BKF;
    #pragma unroll
    for (int s = 0; s < STAGES - 1; s++) issue(s);

    for (int t = 0; t < T; t++) {
        cpa_wait<STAGES - 2>();          // oldest group (tile t) complete
        __syncthreads();
        const int tn = t + STAGES - 1;
        if (tn < T) issue(tn); else cpa_commit();   // keep group count constant

        const int buf = t % STAGES;
        const float* S   = smem + buf * STG;
        const float* AsH = S + (MODE == 2 ? SOFF_A : OFF_AH);
        const float* AsL = S + OFF_AL;
        const float* BsH = S + (MODE == 2 ? SOFF_B : OFF_BH);
        const float* BsL = S + OFF_BL;

        #pragma unroll
        for (int ks = 0; ks < 2; ks++) {
            const int kb = ks * 8;
            uint32_t aH[2][4], aL[2][4];
            #pragma unroll
            for (int mt = 0; mt < 2; mt++) {
                const int mb = (wm * 32 + mt * 16) * APAD;
                aH[mt][0] = fu(AsH[mb +      lr  * APAD + kb + lc    ]);
                aH[mt][1] = fu(AsH[mb + (8 + lr) * APAD + kb + lc    ]);
                aH[mt][2] = fu(AsH[mb +      lr  * APAD + kb + 4 + lc]);
                aH[mt][3] = fu(AsH[mb + (8 + lr) * APAD + kb + 4 + lc]);
                if (MODE == 0) {
                    aL[mt][0] = fu(AsL[mb +      lr  * APAD + kb + lc    ]);
                    aL[mt][1] = fu(AsL[mb + (8 + lr) * APAD + kb + lc    ]);
                    aL[mt][2] = fu(AsL[mb +      lr  * APAD + kb + 4 + lc]);
                    aL[mt][3] = fu(AsL[mb + (8 + lr) * APAD + kb + 4 + lc]);
                }
            }
            #pragma unroll
            for (int nt = 0; nt < 8; nt++) {
                const int nb = wn * 64 + nt * 8;
                const int base = (kb + lc) * BPAD + nb + lr;
                uint32_t bH0 = fu(BsH[base]);
                uint32_t bH1 = fu(BsH[base + 4 * BPAD]);
                #pragma unroll
                for (int mt = 0; mt < 2; mt++) {
                    if (MODE == 2) {
                        mma_tf32(acc[mt][nt], aH[mt][0], aH[mt][1], aH[mt][2], aH[mt][3], bH0, bH1);
                    } else {
                        uint32_t bL0 = fu(BsL[base]);
                        uint32_t bL1 = fu(BsL[base + 4 * BPAD]);
                        mma_tf32(acc[mt][nt], aH[mt][0], aH[mt][1], aH[mt][2], aH[mt][3], bL0, bL1);
                        mma_tf32(acc[mt][nt], aL[mt][0], aL[mt][1], aL[mt][2], aL[mt][3], bH0, bH1);
                        mma_tf32(acc[mt][nt], aH[mt][0], aH[mt][1], aH[mt][2], aH[mt][3], bH0, bH1);
                    }
                }
            }
        }
    }

    // ---- epilogue ----
    #pragma unroll
    for (int mt = 0; mt < 2; mt++) {
        #pragma unroll
        for (int nt = 0; nt < 8; nt++) {
            const int r0 = m0 + wm * 32 + mt * 16 + lr;
            const int c0 = n0 + wn * 64 + nt * 8 + lc * 2;
            if (MODE == 0 && z < 2) {
                __nv_bfloat16* DH = CbH + (size_t)z * M_ALL * CDIM;
                __nv_bfloat16* DL = CbL + (size_t)z * M_ALL * CDIM;
                #pragma unroll
                for (int rq = 0; rq < 2; rq++) {
                    const int r = r0 + rq * 8;
                    float v0 = acc[mt][nt][rq * 2 + 0];
                    float v1 = acc[mt][nt][rq * 2 + 1];
                    __nv_bfloat16 h0 = __float2bfloat16_rn(v0);
                    __nv_bfloat16 h1 = __float2bfloat16_rn(v1);
                    __nv_bfloat16 l0 = __float2bfloat16_rn(v0 - __bfloat162float(h0));
                    __nv_bfloat16 l1 = __float2bfloat16_rn(v1 - __bfloat162float(h1));
                    const size_t o = (size_t)r * ldc + c0;
                    *(__nv_bfloat162*)(DH + o) = __nv_bfloat162(h0, h1);
                    *(__nv_bfloat162*)(DL + o) = __nv_bfloat162(l0, l1);
                }
            } else {
                float* D = Cf + ((MODE == 2) ? (long long)z * sC : 0LL);
                #pragma unroll
                for (int q = 0; q < 4; q++) {
                    const int r = r0 + (q >> 1) * 8;
                    const int c = c0 + (q & 1);
                    float v = acc[mt][nt][q];
                    if (MODE == 2) v = (v > 0.f) ? v : 0.f;
                    else           v = tf32r(v);            // h3 for tf32 AV
                    D[(long long)r * ldc + c] = v;
                }
            }
        }
    }
}

// ---------------- scores GEMM: 3x-bf16 m16n8k16, ldmatrix operands ----------------
// e[b][n][m] = mask(leakyrelu( h1[b][n,:] . h2[b][m,:] ))
__global__ void __launch_bounds__(NTHR, 2)
scores_bf16(const __nv_bfloat16* __restrict__ h1H, const __nv_bfloat16* __restrict__ h1L,
            const __nv_bfloat16* __restrict__ h2H, const __nv_bfloat16* __restrict__ h2L,
            const int* __restrict__ adj, float* __restrict__ e)
{
    extern __shared__ __align__(16) __nv_bfloat16 smb[];
    constexpr int STAGES = 2;

    const int tid  = threadIdx.x;
    const int lane = tid & 31;
    const int warp = tid >> 5;
    const int wm = warp & 3, wn = warp >> 2;
    const int lr = lane >> 2, lc = lane & 3;
    const int n0 = blockIdx.x * BN;
    const int m0 = blockIdx.y * BM;
    const int z  = blockIdx.z;

    const long long BS = (long long)NSEQ * CDIM;
    const __nv_bfloat16* A_H = h1H + z * BS + (long long)m0 * CDIM;
    const __nv_bfloat16* A_L = h1L + z * BS + (long long)m0 * CDIM;
    const __nv_bfloat16* B_H = h2H + z * BS + (long long)n0 * CDIM;
    const __nv_bfloat16* B_L = h2L + z * BS + (long long)n0 * CDIM;

    uint32_t sbase;
    asm("{ .reg .u64 t; cvta.to.shared.u64 t, %1; cvt.u32.u64 %0, t; }" : "=r"(sbase) : "l"(smb));

    const int lrow = tid >> 1;            // 0..127 (cp.async row)
    const int lcb  = (tid & 1) * 16;      // bf16 col offset {0,16}

    // ldmatrix lane addressing: rows 0..15, col group 0/8
    const int qrow = lane & 15;
    const int qcol = (lane >> 4) << 3;

    auto issue = [&](int t) {
        const int buf = t % STAGES;
        const uint32_t sb = sbase + (uint32_t)(buf * SSTG) * 2u;
        const int kofs = t * BKS;
        const long long go0 = (long long)lrow * CDIM + kofs + lcb;
        const uint32_t d0 = (uint32_t)(lrow * SP + lcb) * 2u;
        cpa16(sb + (SA_H * 2u) + d0,      A_H + go0);
        cpa16(sb + (SA_H * 2u) + d0 + 16, A_H + go0 + 8);
        cpa16(sb + (SA_L * 2u) + d0,      A_L + go0);
        cpa16(sb + (SA_L * 2u) + d0 + 16, A_L + go0 + 8);
        cpa16(sb + (SB_H * 2u) + d0,      B_H + go0);
        cpa16(sb + (SB_H * 2u) + d0 + 16, B_H + go0 + 8);
        cpa16(sb + (SB_L * 2u) + d0,      B_L + go0);
        cpa16(sb + (SB_L * 2u) + d0 + 16, B_L + go0 + 8);
        cpa_commit();
    };

    float acc[2][8][4];
    #pragma unroll
    for (int i = 0; i < 2; i++)
        #pragma unroll
        for (int j = 0; j < 8; j++)
            #pragma unroll
            for (int q = 0; q < 4; q++) acc[i][j][q] = 0.f;

    const int T = CDIM / BKS;   // 8
    issue(0);

    for (int t = 0; t < T; t++) {
        cpa_wait<0>();
        __syncthreads();
        if (t + 1 < T) issue(t + 1); else cpa_commit();

        const int buf = t % STAGES;
        const uint32_t sb = sbase + (uint32_t)(buf * SSTG) * 2u;

        #pragma unroll
        for (int ks = 0; ks < 2; ks++) {
            const int kb = ks * 16;
            uint32_t aH[2][4], aL[2][4];
            #pragma unroll
            for (int mt = 0; mt < 2; mt++) {
                const uint32_t ro = (uint32_t)((wm * 32 + mt * 16 + qrow) * SP + kb + qcol) * 2u;
                ldsm_x4(aH[mt][0], aH[mt][1], aH[mt][2], aH[mt][3], sb + SA_H * 2u + ro);
                ldsm_x4(aL[mt][0], aL[mt][1], aL[mt][2], aL[mt][3], sb + SA_L * 2u + ro);
            }
            #pragma unroll
            for (int ng = 0; ng < 4; ng++) {
                const uint32_t bo = (uint32_t)((wn * 64 + ng * 16 + qrow) * SP + kb + qcol) * 2u;
                uint32_t bh[4], bl[4];
                ldsm_x4(bh[0], bh[1], bh[2], bh[3], sb + SB_H * 2u + bo);
                ldsm_x4(bl[0], bl[1], bl[2], bl[3], sb + SB_L * 2u + bo);
                #pragma unroll
                for (int sel = 0; sel < 2; sel++) {
                    const int nt = ng * 2 + sel;
                    const uint32_t bH0 = bh[sel], bH1 = bh[sel + 2];
                    const uint32_t bL0 = bl[sel], bL1 = bl[sel + 2];
                    #pragma unroll
                    for (int mt = 0; mt < 2; mt++) {
                        mma_bf16(acc[mt][nt], aH[mt][0], aH[mt][1], aH[mt][2], aH[mt][3], bL0, bL1);
                        mma_bf16(acc[mt][nt], aL[mt][0], aL[mt][1], aL[mt][2], aL[mt][3], bH0, bH1);
                        mma_bf16(acc[mt][nt], aH[mt][0], aH[mt][1], aH[mt][2], aH[mt][3], bH0, bH1);
                    }
                }
            }
        }
    }

    // ---- epilogue: leakyrelu + adj mask ----
    float* Cp = e + (long long)z * NSEQ * NSEQ;
    #pragma unroll
    for (int mt = 0; mt < 2; mt++) {
        #pragma unroll
        for (int nt = 0; nt < 8; nt++) {
            const int r0 = m0 + wm * 32 + mt * 16 + lr;
            const int c0 = n0 + wn * 64 + nt * 8 + lc * 2;
            #pragma unroll
            for (int q = 0; q < 4; q++) {
                const int r = r0 + (q >> 1) * 8;
                const int c = c0 + (q & 1);
                float v = acc[mt][nt][q];
                v = (v > 0.f) ? v : ALPHA_SLOPE * v;
                const int a = adj[(long long)r * NSEQ + c];
                Cp[(long long)r * NSEQ + c] = (a > 0) ? v : NEG_INF_F;
            }
        }
    }
}

// ---------------- row softmax: e -> tf32-rounded attn, in place ----------------
__global__ void __launch_bounds__(256)
softmax_kernel(float* __restrict__ e)
{
    const long long row = blockIdx.x;
    float4* p4 = (float4*)(e + row * (long long)NSEQ);
    const int tid = threadIdx.x;

    float4 v0 = p4[tid];
    float4 v1 = p4[tid + 256];

    float m = fmaxf(fmaxf(fmaxf(v0.x, v0.y), fmaxf(v0.z, v0.w)),
                    fmaxf(fmaxf(v1.x, v1.y), fmaxf(v1.z, v1.w)));

    __shared__ float red[8];
    #pragma unroll
    for (int o = 16; o > 0; o >>= 1) m = fmaxf(m, __shfl_xor_sync(0xffffffffu, m, o));
    if ((tid & 31) == 0) red[tid >> 5] = m;
    __syncthreads();
    m = red[0];
    #pragma unroll
    for (int i = 1; i < 8; i++) m = fmaxf(m, red[i]);
    __syncthreads();

    v0.x = __expf(v0.x - m); v0.y = __expf(v0.y - m);
    v0.z = __expf(v0.z - m); v0.w = __expf(v0.w - m);
    v1.x = __expf(v1.x - m); v1.y = __expf(v1.y - m);
    v1.z = __expf(v1.z - m); v1.w = __expf(v1.w - m);

    float s = v0.x + v0.y + v0.z + v0.w + v1.x + v1.y + v1.z + v1.w;
    #pragma unroll
    for (int o = 16; o > 0; o >>= 1) s += __shfl_xor_sync(0xffffffffu, s, o);
    if ((tid & 31) == 0) red[tid >> 5] = s;
    __syncthreads();
    s = red[0] + red[1] + red[2] + red[3] + red[4] + red[5] + red[6] + red[7];

    const float inv = 1.0f / s;
    v0.x = tf32r(v0.x * inv); v0.y = tf32r(v0.y * inv);
    v0.z = tf32r(v0.z * inv); v0.w = tf32r(v0.w * inv);
    v1.x = tf32r(v1.x * inv); v1.y = tf32r(v1.y * inv);
    v1.z = tf32r(v1.z * inv); v1.w = tf32r(v1.w * inv);

    p4[tid]       = v0;
    p4[tid + 256] = v1;
}

// ---------------- launcher ----------------
extern "C" void kernel_launch(void* const* d_in, const int* in_sizes, int n_in,
                              void* d_out, int out_size)
{
    const float* inp = (const float*)d_in[0];   // [8,2048,256] f32
    const int*   adj = (const int*)d_in[1];     // [2048,2048] i32
    const float* W1  = (const float*)d_in[2];   // [256,256] f32
    const float* W2  = (const float*)d_in[3];
    const float* W3  = (const float*)d_in[4];
    float* out = (float*)d_out;                 // [8,2048,256] f32

    float *xH, *xL, *wH, *wL, *h3, *e;
    __nv_bfloat16 *hbH, *hbL;
    cudaGetSymbolAddress((void**)&xH,  g_xH);
    cudaGetSymbolAddress((void**)&xL,  g_xL);
    cudaGetSymbolAddress((void**)&wH,  g_wH);
    cudaGetSymbolAddress((void**)&wL,  g_wL);
    cudaGetSymbolAddress((void**)&hbH, g_hbH);
    cudaGetSymbolAddress((void**)&hbL, g_hbL);
    cudaGetSymbolAddress((void**)&h3,  g_h3);
    cudaGetSymbolAddress((void**)&e,   g_e);

    const int SM_HL = STG_HL * 2 * 4;   // 81920 B (proj, 2 stages)
    const int SM_S  = STG_S  * 4 * 4;   // 81920 B (AV, 4 stages)
    const int SM_BF = SSTG   * 2 * 2;   // 81920 B (scores, 2 stages)
    cudaFuncSetAttribute(gemm_pipe<0,2>, cudaFuncAttributeMaxDynamicSharedMemorySize, SM_HL);
    cudaFuncSetAttribute(gemm_pipe<2,4>, cudaFuncAttributeMaxDynamicSharedMemorySize, SM_S);
    cudaFuncSetAttribute(scores_bf16,    cudaFuncAttributeMaxDynamicSharedMemorySize, SM_BF);

    const long long BS = (long long)NSEQ * CDIM;
    const long long ES = (long long)NSEQ * NSEQ;
    const int WSZ = CDIM * CDIM;

    // 0) pre-split X and W (fp32 hi/lo)
    {
        const int xn4 = (int)((long long)M_ALL * CDIM / 4);
        split_kernel<<<(xn4 + 255) / 256, 256>>>(inp, xH, xL, xn4);
        dim3 gw((WSZ / 4 + 255) / 256, 3);
        split_w_kernel<<<gw, 256>>>(W1, W2, W3, wH, wL);
    }
    // 1) projections: z=0,1 -> bf16 hi/lo (h1,h2); z=2 -> tf32 fp32 (h3)
    {
        dim3 g(CDIM / BN, M_ALL / BM, 3);
        gemm_pipe<0,2><<<g, NTHR, SM_HL>>>(xH, xL, wH, wL, h3, hbH, hbL,
                                           CDIM, CDIM, CDIM, CDIM,
                                           0LL, (long long)WSZ, 0LL);
    }
    // 2) scores: e = mask(leakyrelu(h1 h2^T)), 3x-bf16 + ldmatrix
    {
        dim3 g(NSEQ / BN, NSEQ / BM, BB);
        scores_bf16<<<g, NTHR, SM_BF>>>(hbH, hbL,
                                        hbH + (size_t)M_ALL * CDIM, hbL + (size_t)M_ALL * CDIM,
                                        adj, e);
    }
    // 3) softmax rows -> tf32-rounded attn in place
    softmax_kernel<<<BB * NSEQ, 256>>>(e);
    // 4) out = relu(attn @ h3), single-TF32, 4 stages
    {
        dim3 g(CDIM / BN, NSEQ / BM, BB);
        gemm_pipe<2,4><<<g, NTHR, SM_S>>>(e, nullptr, h3, nullptr, out, nullptr, nullptr,
                                          NSEQ, NSEQ, CDIM, CDIM,
                                          ES, BS, BS);
    }
}

// round 6
// speedup vs baseline: 1.9448x; 1.1573x over previous
#include <cuda_runtime.h>
#include <cuda_bf16.h>
#include <cuda_fp16.h>
#include <cstdint>

// ---------------------------------------------------------------------------
// GraphAttentionLayer on GB300 (sm_103a).
//  proj   : 3xTF32 mma m16n8k8 -> h1/h2 bf16 hi/lo, h3 fp16
//  scores : 3x-bf16 mma m16n8k16, ldmatrix operands, leakyrelu + mask -> e fp32
//  softmax: fp32 row softmax -> attn fp16
//  AV     : fp16 mma m16n8k16 (11-bit mantissa == tf32 accuracy), ldmatrix, relu
// ---------------------------------------------------------------------------

#define ALPHA_SLOPE 0.2f
#define NEG_INF_F  -1.0e12f

#define BB   8
#define NSEQ 2048
#define CDIM 256
#define M_ALL (BB * NSEQ)        // 16384

#define BM 128
#define BN 128
#define NTHR 256

// ---- fp32 proj tile geometry, BK=16 ----
#define BKF 16
#define APAD 20
#define BPAD 136
#define TILEA (BM * APAD)        // 2560 words
#define OFF_AH 0
#define OFF_AL TILEA
#define OFF_BH (2 * TILEA)
#define OFF_BL (3 * TILEA)
#define STG_HL (4 * TILEA)       // proj stage: 10240 words

// ---- bf16 scores tile geometry, BK=32 ----
#define BKS 32
#define SP  40                   // bf16 pitch (80B) -> LDSM conflict-free
#define STILE (BM * SP)          // 5120 bf16 per array
#define SA_H 0
#define SA_L STILE
#define SB_H (2 * STILE)
#define SB_L (3 * STILE)
#define SSTG (4 * STILE)         // 20480 bf16 = 40960 B / stage

// ---- fp16 AV tile geometry, BK=32 ----
#define AKP 40                   // attn tile pitch (fp16)
#define BKP 136                  // h3 tile pitch (fp16), rows 272B apart
#define AV_B_OFF (BM * AKP)      // 5120
#define AV_STG (BM * AKP + BKS * BKP)   // 5120 + 4352 = 9472 fp16 / stage
#define AV_STAGES 4

// ---- global scratch ----
__device__ float g_xH[(size_t)M_ALL * CDIM];
__device__ float g_xL[(size_t)M_ALL * CDIM];
__device__ float g_wH[3 * CDIM * CDIM];
__device__ float g_wL[3 * CDIM * CDIM];
__device__ __nv_bfloat16 g_hbH[2ull * M_ALL * CDIM];   // h1,h2 bf16 hi
__device__ __nv_bfloat16 g_hbL[2ull * M_ALL * CDIM];   // h1,h2 bf16 lo
__device__ __half g_h316[(size_t)M_ALL * CDIM];        // h3 fp16
__device__ float g_e[(size_t)BB * NSEQ * NSEQ];        // e fp32
__device__ __half g_attn16[(size_t)BB * NSEQ * NSEQ];  // attn fp16

// ---------------- helpers ----------------
__device__ __forceinline__ void mma_tf32(float c[4],
                                         uint32_t a0, uint32_t a1, uint32_t a2, uint32_t a3,
                                         uint32_t b0, uint32_t b1) {
    asm volatile(
        "mma.sync.aligned.m16n8k8.row.col.f32.tf32.tf32.f32 "
        "{%0,%1,%2,%3}, {%4,%5,%6,%7}, {%8,%9}, {%0,%1,%2,%3};\n"
        : "+f"(c[0]), "+f"(c[1]), "+f"(c[2]), "+f"(c[3])
        : "r"(a0), "r"(a1), "r"(a2), "r"(a3), "r"(b0), "r"(b1));
}

__device__ __forceinline__ void mma_bf16(float c[4],
                                         uint32_t a0, uint32_t a1, uint32_t a2, uint32_t a3,
                                         uint32_t b0, uint32_t b1) {
    asm volatile(
        "mma.sync.aligned.m16n8k16.row.col.f32.bf16.bf16.f32 "
        "{%0,%1,%2,%3}, {%4,%5,%6,%7}, {%8,%9}, {%0,%1,%2,%3};\n"
        : "+f"(c[0]), "+f"(c[1]), "+f"(c[2]), "+f"(c[3])
        : "r"(a0), "r"(a1), "r"(a2), "r"(a3), "r"(b0), "r"(b1));
}

__device__ __forceinline__ void mma_fp16(float c[4],
                                         uint32_t a0, uint32_t a1, uint32_t a2, uint32_t a3,
                                         uint32_t b0, uint32_t b1) {
    asm volatile(
        "mma.sync.aligned.m16n8k16.row.col.f32.f16.f16.f32 "
        "{%0,%1,%2,%3}, {%4,%5,%6,%7}, {%8,%9}, {%0,%1,%2,%3};\n"
        : "+f"(c[0]), "+f"(c[1]), "+f"(c[2]), "+f"(c[3])
        : "r"(a0), "r"(a1), "r"(a2), "r"(a3), "r"(b0), "r"(b1));
}

__device__ __forceinline__ void ldsm_x4(uint32_t &r0, uint32_t &r1, uint32_t &r2, uint32_t &r3,
                                        uint32_t addr) {
    asm volatile("ldmatrix.sync.aligned.m8n8.x4.shared.b16 {%0,%1,%2,%3}, [%4];\n"
        : "=r"(r0), "=r"(r1), "=r"(r2), "=r"(r3) : "r"(addr));
}

__device__ __forceinline__ void ldsm_x4_t(uint32_t &r0, uint32_t &r1, uint32_t &r2, uint32_t &r3,
                                          uint32_t addr) {
    asm volatile("ldmatrix.sync.aligned.m8n8.x4.trans.shared.b16 {%0,%1,%2,%3}, [%4];\n"
        : "=r"(r0), "=r"(r1), "=r"(r2), "=r"(r3) : "r"(addr));
}

__device__ __forceinline__ void split2(float x, float &hi, float &lo) {
    uint32_t h;
    asm("cvt.rna.tf32.f32 %0, %1;" : "=r"(h) : "f"(x));
    float r = x - __uint_as_float(h);
    uint32_t l;
    asm("cvt.rna.tf32.f32 %0, %1;" : "=r"(l) : "f"(r));
    hi = __uint_as_float(h);
    lo = __uint_as_float(l);
}

__device__ __forceinline__ uint32_t fu(float x) { return __float_as_uint(x); }

__device__ __forceinline__ void cpa16(uint32_t dst, const void* src) {
    asm volatile("cp.async.cg.shared.global [%0], [%1], 16;\n" :: "r"(dst), "l"(src) : "memory");
}
__device__ __forceinline__ void cpa_commit() {
    asm volatile("cp.async.commit_group;\n" ::: "memory");
}
template<int N>
__device__ __forceinline__ void cpa_wait() {
    asm volatile("cp.async.wait_group %0;\n" :: "n"(N) : "memory");
}

// ---------------- split kernels ----------------
__global__ void __launch_bounds__(256)
split_kernel(const float* __restrict__ src, float* __restrict__ H, float* __restrict__ L, int n4)
{
    int i = blockIdx.x * blockDim.x + threadIdx.x;
    if (i >= n4) return;
    float4 v = ((const float4*)src)[i];
    float4 h4, l4;
    split2(v.x, h4.x, l4.x); split2(v.y, h4.y, l4.y);
    split2(v.z, h4.z, l4.z); split2(v.w, h4.w, l4.w);
    ((float4*)H)[i] = h4;
    ((float4*)L)[i] = l4;
}

__global__ void __launch_bounds__(256)
split_w_kernel(const float* __restrict__ W1, const float* __restrict__ W2,
               const float* __restrict__ W3, float* __restrict__ H, float* __restrict__ L)
{
    const int z = blockIdx.y;
    const float* src = (z == 0) ? W1 : (z == 1) ? W2 : W3;
    const int n4 = CDIM * CDIM / 4;
    int i = blockIdx.x * blockDim.x + threadIdx.x;
    if (i >= n4) return;
    float4 v = ((const float4*)src)[i];
    float4 h4, l4;
    split2(v.x, h4.x, l4.x); split2(v.y, h4.y, l4.y);
    split2(v.z, h4.z, l4.z); split2(v.w, h4.w, l4.w);
    ((float4*)(H + (size_t)z * CDIM * CDIM))[i] = h4;
    ((float4*)(L + (size_t)z * CDIM * CDIM))[i] = l4;
}

// ---------------- projection GEMM (3xTF32) ----------------
// C = X @ W_z ; z<2 -> bf16 hi/lo (h1,h2), z==2 -> fp16 (h3)
__global__ void __launch_bounds__(NTHR, 2)
proj_pipe(const float* __restrict__ AH_, const float* __restrict__ AL_,
          const float* __restrict__ BH_, const float* __restrict__ BL_,
          __nv_bfloat16* __restrict__ CbH, __nv_bfloat16* __restrict__ CbL,
          __half* __restrict__ C16)
{
    extern __shared__ __align__(16) float smem[];
    constexpr int STAGES = 2;
    const int K = CDIM;

    const int tid  = threadIdx.x;
    const int lane = tid & 31;
    const int warp = tid >> 5;
    const int wm = warp & 3, wn = warp >> 2;
    const int lr = lane >> 2, lc = lane & 3;
    const int n0 = blockIdx.x * BN;
    const int m0 = blockIdx.y * BM;
    const int z  = blockIdx.z;

    const float* ApH = AH_ + (long long)m0 * CDIM;
    const float* ApL = AL_ + (long long)m0 * CDIM;
    const float* BpH = BH_ + (long long)z * CDIM * CDIM + n0;
    const float* BpL = BL_ + (long long)z * CDIM * CDIM + n0;

    uint32_t sbase;
    asm("{ .reg .u64 t; cvta.to.shared.u64 t, %1; cvt.u32.u64 %0, t; }" : "=r"(sbase) : "l"(smem));

    const int arow = tid >> 2;
    const int acol = (tid & 3) << 2;
    const int bkr  = tid >> 5;
    const int bcol = lane << 2;

    auto issue = [&](int t) {
        const int buf = t % STAGES;
        const uint32_t sb = sbase + (uint32_t)(buf * STG_HL) * 4u;
        const int kofs = t * BKF;
        #pragma unroll
        for (int i = 0; i < 2; i++) {
            const int r = arow + i * 64;
            const long long go = (long long)r * CDIM + kofs + acol;
            cpa16(sb + (uint32_t)(OFF_AH + r * APAD + acol) * 4u, ApH + go);
            cpa16(sb + (uint32_t)(OFF_AL + r * APAD + acol) * 4u, ApL + go);
        }
        #pragma unroll
        for (int i = 0; i < 2; i++) {
            const int kk = bkr + i * 8;
            const long long go = (long long)(kofs + kk) * CDIM + bcol;
            cpa16(sb + (uint32_t)(OFF_BH + kk * BPAD + bcol) * 4u, BpH + go);
            cpa16(sb + (uint32_t)(OFF_BL + kk * BPAD + bcol) * 4u, BpL + go);
        }
        cpa_commit();
    };

    float acc[2][8][4];
    #pragma unroll
    for (int i = 0; i < 2; i++)
        #pragma unroll
        for (int j = 0; j < 8; j++)
            #pragma unroll
            for (int q = 0; q < 4; q++) acc[i][j][q] = 0.f;

    const int T = K / BKF;
    issue(0);

    for (int t = 0; t < T; t++) {
        cpa_wait<0>();
        __syncthreads();
        if (t + 1 < T) issue(t + 1); else cpa_commit();

        const int buf = t % STAGES;
        const float* S   = smem + buf * STG_HL;
        const float* AsH = S + OFF_AH;
        const float* AsL = S + OFF_AL;
        const float* BsH = S + OFF_BH;
        const float* BsL = S + OFF_BL;

        #pragma unroll
        for (int ks = 0; ks < 2; ks++) {
            const int kb = ks * 8;
            uint32_t aH[2][4], aL[2][4];
            #pragma unroll
            for (int mt = 0; mt < 2; mt++) {
                const int mb = (wm * 32 + mt * 16) * APAD;
                aH[mt][0] = fu(AsH[mb +      lr  * APAD + kb + lc    ]);
                aH[mt][1] = fu(AsH[mb + (8 + lr) * APAD + kb + lc    ]);
                aH[mt][2] = fu(AsH[mb +      lr  * APAD + kb + 4 + lc]);
                aH[mt][3] = fu(AsH[mb + (8 + lr) * APAD + kb + 4 + lc]);
                aL[mt][0] = fu(AsL[mb +      lr  * APAD + kb + lc    ]);
                aL[mt][1] = fu(AsL[mb + (8 + lr) * APAD + kb + lc    ]);
                aL[mt][2] = fu(AsL[mb +      lr  * APAD + kb + 4 + lc]);
                aL[mt][3] = fu(AsL[mb + (8 + lr) * APAD + kb + 4 + lc]);
            }
            #pragma unroll
            for (int nt = 0; nt < 8; nt++) {
                const int nb = wn * 64 + nt * 8;
                const int base = (kb + lc) * BPAD + nb + lr;
                uint32_t bH0 = fu(BsH[base]);
                uint32_t bH1 = fu(BsH[base + 4 * BPAD]);
                uint32_t bL0 = fu(BsL[base]);
                uint32_t bL1 = fu(BsL[base + 4 * BPAD]);
                #pragma unroll
                for (int mt = 0; mt < 2; mt++) {
                    mma_tf32(acc[mt][nt], aH[mt][0], aH[mt][1], aH[mt][2], aH[mt][3], bL0, bL1);
                    mma_tf32(acc[mt][nt], aL[mt][0], aL[mt][1], aL[mt][2], aL[mt][3], bH0, bH1);
                    mma_tf32(acc[mt][nt], aH[mt][0], aH[mt][1], aH[mt][2], aH[mt][3], bH0, bH1);
                }
            }
        }
    }

    // ---- epilogue ----
    #pragma unroll
    for (int mt = 0; mt < 2; mt++) {
        #pragma unroll
        for (int nt = 0; nt < 8; nt++) {
            const int r0 = m0 + wm * 32 + mt * 16 + lr;
            const int c0 = n0 + wn * 64 + nt * 8 + lc * 2;
            if (z < 2) {
                __nv_bfloat16* DH = CbH + (size_t)z * M_ALL * CDIM;
                __nv_bfloat16* DL = CbL + (size_t)z * M_ALL * CDIM;
                #pragma unroll
                for (int rq = 0; rq < 2; rq++) {
                    const int r = r0 + rq * 8;
                    float v0 = acc[mt][nt][rq * 2 + 0];
                    float v1 = acc[mt][nt][rq * 2 + 1];
                    __nv_bfloat16 h0 = __float2bfloat16_rn(v0);
                    __nv_bfloat16 h1 = __float2bfloat16_rn(v1);
                    __nv_bfloat16 l0 = __float2bfloat16_rn(v0 - __bfloat162float(h0));
                    __nv_bfloat16 l1 = __float2bfloat16_rn(v1 - __bfloat162float(h1));
                    const size_t o = (size_t)r * CDIM + c0;
                    *(__nv_bfloat162*)(DH + o) = __nv_bfloat162(h0, h1);
                    *(__nv_bfloat162*)(DL + o) = __nv_bfloat162(l0, l1);
                }
            } else {
                #pragma unroll
                for (int rq = 0; rq < 2; rq++) {
                    const int r = r0 + rq * 8;
                    const size_t o = (size_t)r * CDIM + c0;
                    *(__half2*)(C16 + o) =
                        __floats2half2_rn(acc[mt][nt][rq * 2 + 0], acc[mt][nt][rq * 2 + 1]);
                }
            }
        }
    }
}

// ---------------- scores GEMM: 3x-bf16 m16n8k16, ldmatrix operands ----------------
__global__ void __launch_bounds__(NTHR, 2)
scores_bf16(const __nv_bfloat16* __restrict__ h1H, const __nv_bfloat16* __restrict__ h1L,
            const __nv_bfloat16* __restrict__ h2H, const __nv_bfloat16* __restrict__ h2L,
            const int* __restrict__ adj, float* __restrict__ e)
{
    extern __shared__ __align__(16) __nv_bfloat16 smb[];
    constexpr int STAGES = 2;

    const int tid  = threadIdx.x;
    const int lane = tid & 31;
    const int warp = tid >> 5;
    const int wm = warp & 3, wn = warp >> 2;
    const int lr = lane >> 2, lc = lane & 3;
    const int n0 = blockIdx.x * BN;
    const int m0 = blockIdx.y * BM;
    const int z  = blockIdx.z;

    const long long BS = (long long)NSEQ * CDIM;
    const __nv_bfloat16* A_H = h1H + z * BS + (long long)m0 * CDIM;
    const __nv_bfloat16* A_L = h1L + z * BS + (long long)m0 * CDIM;
    const __nv_bfloat16* B_H = h2H + z * BS + (long long)n0 * CDIM;
    const __nv_bfloat16* B_L = h2L + z * BS + (long long)n0 * CDIM;

    uint32_t sbase;
    asm("{ .reg .u64 t; cvta.to.shared.u64 t, %1; cvt.u32.u64 %0, t; }" : "=r"(sbase) : "l"(smb));

    const int lrow = tid >> 1;
    const int lcb  = (tid & 1) * 16;
    const int qrow = lane & 15;
    const int qcol = (lane >> 4) << 3;

    auto issue = [&](int t) {
        const int buf = t % STAGES;
        const uint32_t sb = sbase + (uint32_t)(buf * SSTG) * 2u;
        const int kofs = t * BKS;
        const long long go0 = (long long)lrow * CDIM + kofs + lcb;
        const uint32_t d0 = (uint32_t)(lrow * SP + lcb) * 2u;
        cpa16(sb + (SA_H * 2u) + d0,      A_H + go0);
        cpa16(sb + (SA_H * 2u) + d0 + 16, A_H + go0 + 8);
        cpa16(sb + (SA_L * 2u) + d0,      A_L + go0);
        cpa16(sb + (SA_L * 2u) + d0 + 16, A_L + go0 + 8);
        cpa16(sb + (SB_H * 2u) + d0,      B_H + go0);
        cpa16(sb + (SB_H * 2u) + d0 + 16, B_H + go0 + 8);
        cpa16(sb + (SB_L * 2u) + d0,      B_L + go0);
        cpa16(sb + (SB_L * 2u) + d0 + 16, B_L + go0 + 8);
        cpa_commit();
    };

    float acc[2][8][4];
    #pragma unroll
    for (int i = 0; i < 2; i++)
        #pragma unroll
        for (int j = 0; j < 8; j++)
            #pragma unroll
            for (int q = 0; q < 4; q++) acc[i][j][q] = 0.f;

    const int T = CDIM / BKS;   // 8
    issue(0);

    for (int t = 0; t < T; t++) {
        cpa_wait<0>();
        __syncthreads();
        if (t + 1 < T) issue(t + 1); else cpa_commit();

        const int buf = t % STAGES;
        const uint32_t sb = sbase + (uint32_t)(buf * SSTG) * 2u;

        #pragma unroll
        for (int ks = 0; ks < 2; ks++) {
            const int kb = ks * 16;
            uint32_t aH[2][4], aL[2][4];
            #pragma unroll
            for (int mt = 0; mt < 2; mt++) {
                const uint32_t ro = (uint32_t)((wm * 32 + mt * 16 + qrow) * SP + kb + qcol) * 2u;
                ldsm_x4(aH[mt][0], aH[mt][1], aH[mt][2], aH[mt][3], sb + SA_H * 2u + ro);
                ldsm_x4(aL[mt][0], aL[mt][1], aL[mt][2], aL[mt][3], sb + SA_L * 2u + ro);
            }
            #pragma unroll
            for (int ng = 0; ng < 4; ng++) {
                const uint32_t bo = (uint32_t)((wn * 64 + ng * 16 + qrow) * SP + kb + qcol) * 2u;
                uint32_t bh[4], bl[4];
                ldsm_x4(bh[0], bh[1], bh[2], bh[3], sb + SB_H * 2u + bo);
                ldsm_x4(bl[0], bl[1], bl[2], bl[3], sb + SB_L * 2u + bo);
                #pragma unroll
                for (int sel = 0; sel < 2; sel++) {
                    const int nt = ng * 2 + sel;
                    const uint32_t bH0 = bh[sel], bH1 = bh[sel + 2];
                    const uint32_t bL0 = bl[sel], bL1 = bl[sel + 2];
                    #pragma unroll
                    for (int mt = 0; mt < 2; mt++) {
                        mma_bf16(acc[mt][nt], aH[mt][0], aH[mt][1], aH[mt][2], aH[mt][3], bL0, bL1);
                        mma_bf16(acc[mt][nt], aL[mt][0], aL[mt][1], aL[mt][2], aL[mt][3], bH0, bH1);
                        mma_bf16(acc[mt][nt], aH[mt][0], aH[mt][1], aH[mt][2], aH[mt][3], bH0, bH1);
                    }
                }
            }
        }
    }

    // ---- epilogue: leakyrelu + adj mask ----
    float* Cp = e + (long long)z * NSEQ * NSEQ;
    #pragma unroll
    for (int mt = 0; mt < 2; mt++) {
        #pragma unroll
        for (int nt = 0; nt < 8; nt++) {
            const int r0 = m0 + wm * 32 + mt * 16 + lr;
            const int c0 = n0 + wn * 64 + nt * 8 + lc * 2;
            #pragma unroll
            for (int q = 0; q < 4; q++) {
                const int r = r0 + (q >> 1) * 8;
                const int c = c0 + (q & 1);
                float v = acc[mt][nt][q];
                v = (v > 0.f) ? v : ALPHA_SLOPE * v;
                const int a = adj[(long long)r * NSEQ + c];
                Cp[(long long)r * NSEQ + c] = (a > 0) ? v : NEG_INF_F;
            }
        }
    }
}

// ---------------- row softmax: e fp32 -> attn fp16 ----------------
__global__ void __launch_bounds__(256)
softmax_kernel(const float* __restrict__ e, __half* __restrict__ attn)
{
    const long long row = blockIdx.x;
    const float4* p4 = (const float4*)(e + row * (long long)NSEQ);
    __half2* a2 = (__half2*)(attn + row * (long long)NSEQ);
    const int tid = threadIdx.x;

    float4 v0 = p4[tid];
    float4 v1 = p4[tid + 256];

    float m = fmaxf(fmaxf(fmaxf(v0.x, v0.y), fmaxf(v0.z, v0.w)),
                    fmaxf(fmaxf(v1.x, v1.y), fmaxf(v1.z, v1.w)));

    __shared__ float red[8];
    #pragma unroll
    for (int o = 16; o > 0; o >>= 1) m = fmaxf(m, __shfl_xor_sync(0xffffffffu, m, o));
    if ((tid & 31) == 0) red[tid >> 5] = m;
    __syncthreads();
    m = red[0];
    #pragma unroll
    for (int i = 1; i < 8; i++) m = fmaxf(m, red[i]);
    __syncthreads();

    v0.x = __expf(v0.x - m); v0.y = __expf(v0.y - m);
    v0.z = __expf(v0.z - m); v0.w = __expf(v0.w - m);
    v1.x = __expf(v1.x - m); v1.y = __expf(v1.y - m);
    v1.z = __expf(v1.z - m); v1.w = __expf(v1.w - m);

    float s = v0.x + v0.y + v0.z + v0.w + v1.x + v1.y + v1.z + v1.w;
    #pragma unroll
    for (int o = 16; o > 0; o >>= 1) s += __shfl_xor_sync(0xffffffffu, s, o);
    if ((tid & 31) == 0) red[tid >> 5] = s;
    __syncthreads();
    s = red[0] + red[1] + red[2] + red[3] + red[4] + red[5] + red[6] + red[7];

    const float inv = 1.0f / s;
    a2[2 * tid]             = __floats2half2_rn(v0.x * inv, v0.y * inv);
    a2[2 * tid + 1]         = __floats2half2_rn(v0.z * inv, v0.w * inv);
    a2[2 * (tid + 256)]     = __floats2half2_rn(v1.x * inv, v1.y * inv);
    a2[2 * (tid + 256) + 1] = __floats2half2_rn(v1.z * inv, v1.w * inv);
}

// ---------------- AV GEMM: fp16 m16n8k16 ----------------
// out[q,d] = relu( sum_m attn[q,m] * h3[m,d] )
__global__ void __launch_bounds__(NTHR, 2)
av_fp16(const __half* __restrict__ attn, const __half* __restrict__ h3,
        float* __restrict__ out)
{
    extern __shared__ __align__(16) __half smh[];

    const int tid  = threadIdx.x;
    const int lane = tid & 31;
    const int warp = tid >> 5;
    const int wm = warp & 3, wn = warp >> 2;
    const int lr = lane >> 2, lc = lane & 3;
    const int n0 = blockIdx.x * BN;     // d offset
    const int m0 = blockIdx.y * BM;     // q offset
    const int z  = blockIdx.z;

    const __half* Ap = attn + (size_t)z * NSEQ * NSEQ + (size_t)m0 * NSEQ;
    const __half* Bp = h3 + (size_t)z * NSEQ * CDIM + n0;

    uint32_t sbase;
    asm("{ .reg .u64 t; cvta.to.shared.u64 t, %1; cvt.u32.u64 %0, t; }" : "=r"(sbase) : "l"(smh));

    const int arow = tid >> 1, acol = (tid & 1) * 16;   // 128 rows x 32 fp16
    const int brow = tid >> 3, bcol = (tid & 7) * 16;   // 32 rows x 128 fp16
    const int qrow = lane & 15;
    const int qcol = (lane >> 4) << 3;

    auto issue = [&](int t) {
        const int buf = t % AV_STAGES;
        const uint32_t sb = sbase + (uint32_t)(buf * AV_STG) * 2u;
        const int kofs = t * BKS;
        {
            const long long go = (long long)arow * NSEQ + kofs + acol;
            const uint32_t d0 = (uint32_t)(arow * AKP + acol) * 2u;
            cpa16(sb + d0,      Ap + go);
            cpa16(sb + d0 + 16, Ap + go + 8);
        }
        {
            const long long go = (long long)(kofs + brow) * CDIM + bcol;
            const uint32_t d0 = (uint32_t)(AV_B_OFF + brow * BKP + bcol) * 2u;
            cpa16(sb + d0,      Bp + go);
            cpa16(sb + d0 + 16, Bp + go + 8);
        }
        cpa_commit();
    };

    float acc[2][8][4];
    #pragma unroll
    for (int i = 0; i < 2; i++)
        #pragma unroll
        for (int j = 0; j < 8; j++)
            #pragma unroll
            for (int q = 0; q < 4; q++) acc[i][j][q] = 0.f;

    const int T = NSEQ / BKS;   // 64
    #pragma unroll
    for (int s = 0; s < AV_STAGES - 1; s++) issue(s);

    for (int t = 0; t < T; t++) {
        cpa_wait<AV_STAGES - 2>();
        __syncthreads();
        const int tn = t + AV_STAGES - 1;
        if (tn < T) issue(tn); else cpa_commit();

        const int buf = t % AV_STAGES;
        const uint32_t sb = sbase + (uint32_t)(buf * AV_STG) * 2u;

        #pragma unroll
        for (int ks = 0; ks < 2; ks++) {
            const int kb = ks * 16;
            uint32_t a[2][4];
            #pragma unroll
            for (int mt = 0; mt < 2; mt++) {
                const uint32_t ro = (uint32_t)((wm * 32 + mt * 16 + qrow) * AKP + kb + qcol) * 2u;
                ldsm_x4(a[mt][0], a[mt][1], a[mt][2], a[mt][3], sb + ro);
            }
            #pragma unroll
            for (int ng = 0; ng < 4; ng++) {
                const int nb = wn * 64 + ng * 16;
                const uint32_t bo =
                    (uint32_t)(AV_B_OFF + (kb + qrow) * BKP + nb + qcol) * 2u;
                uint32_t b[4];
                ldsm_x4_t(b[0], b[1], b[2], b[3], sb + bo);
                #pragma unroll
                for (int sel = 0; sel < 2; sel++) {
                    const int nt = ng * 2 + sel;
                    #pragma unroll
                    for (int mt = 0; mt < 2; mt++) {
                        mma_fp16(acc[mt][nt], a[mt][0], a[mt][1], a[mt][2], a[mt][3],
                                 b[2 * sel], b[2 * sel + 1]);
                    }
                }
            }
        }
    }

    // ---- epilogue: relu ----
    float* Cp = out + (size_t)z * NSEQ * CDIM;
    #pragma unroll
    for (int mt = 0; mt < 2; mt++) {
        #pragma unroll
        for (int nt = 0; nt < 8; nt++) {
            const int r0 = m0 + wm * 32 + mt * 16 + lr;
            const int c0 = n0 + wn * 64 + nt * 8 + lc * 2;
            #pragma unroll
            for (int q = 0; q < 4; q++) {
                const int r = r0 + (q >> 1) * 8;
                const int c = c0 + (q & 1);
                float v = acc[mt][nt][q];
                Cp[(size_t)r * CDIM + c] = (v > 0.f) ? v : 0.f;
            }
        }
    }
}

// ---------------- launcher ----------------
extern "C" void kernel_launch(void* const* d_in, const int* in_sizes, int n_in,
                              void* d_out, int out_size)
{
    const float* inp = (const float*)d_in[0];
    const int*   adj = (const int*)d_in[1];
    const float* W1  = (const float*)d_in[2];
    const float* W2  = (const float*)d_in[3];
    const float* W3  = (const float*)d_in[4];
    float* out = (float*)d_out;

    float *xH, *xL, *wH, *wL, *e;
    __nv_bfloat16 *hbH, *hbL;
    __half *h316, *attn16;
    cudaGetSymbolAddress((void**)&xH,     g_xH);
    cudaGetSymbolAddress((void**)&xL,     g_xL);
    cudaGetSymbolAddress((void**)&wH,     g_wH);
    cudaGetSymbolAddress((void**)&wL,     g_wL);
    cudaGetSymbolAddress((void**)&hbH,    g_hbH);
    cudaGetSymbolAddress((void**)&hbL,    g_hbL);
    cudaGetSymbolAddress((void**)&h316,   g_h316);
    cudaGetSymbolAddress((void**)&e,      g_e);
    cudaGetSymbolAddress((void**)&attn16, g_attn16);

    const int SM_HL = STG_HL * 2 * 4;        // 81920 B
    const int SM_BF = SSTG   * 2 * 2;        // 81920 B
    const int SM_AV = AV_STG * AV_STAGES * 2; // 75776 B
    cudaFuncSetAttribute(proj_pipe,   cudaFuncAttributeMaxDynamicSharedMemorySize, SM_HL);
    cudaFuncSetAttribute(scores_bf16, cudaFuncAttributeMaxDynamicSharedMemorySize, SM_BF);
    cudaFuncSetAttribute(av_fp16,     cudaFuncAttributeMaxDynamicSharedMemorySize, SM_AV);

    const int WSZ = CDIM * CDIM;

    // 0) pre-split X and W
    {
        const int xn4 = (int)((long long)M_ALL * CDIM / 4);
        split_kernel<<<(xn4 + 255) / 256, 256>>>(inp, xH, xL, xn4);
        dim3 gw((WSZ / 4 + 255) / 256, 3);
        split_w_kernel<<<gw, 256>>>(W1, W2, W3, wH, wL);
    }
    // 1) projections
    {
        dim3 g(CDIM / BN, M_ALL / BM, 3);
        proj_pipe<<<g, NTHR, SM_HL>>>(xH, xL, wH, wL, hbH, hbL, h316);
    }
    // 2) scores
    {
        dim3 g(NSEQ / BN, NSEQ / BM, BB);
        scores_bf16<<<g, NTHR, SM_BF>>>(hbH, hbL,
                                        hbH + (size_t)M_ALL * CDIM, hbL + (size_t)M_ALL * CDIM,
                                        adj, e);
    }
    // 3) softmax -> fp16 attn
    softmax_kernel<<<BB * NSEQ, 256>>>(e, attn16);
    // 4) AV fp16
    {
        dim3 g(CDIM / BN, NSEQ / BM, BB);
        av_fp16<<<g, NTHR, SM_AV>>>(attn16, h316, out);
    }
}

// round 8
// speedup vs baseline: 2.0472x; 1.0526x over previous
#include <cuda_runtime.h>
#include <cuda_bf16.h>
#include <cuda_fp16.h>
#include <cstdint>

// ---------------------------------------------------------------------------
// GraphAttentionLayer on GB300 (sm_103a; harness PTX target lacks 'a' suffix,
// so tcgen05 is unavailable -> mma.sync throughout).
//  proj   : 3x-bf16 mma m16n8k16 (W pre-transposed+split) -> h1/h2 bf16 hi/lo, h3 fp16
//  scores : 3x-bf16 mma m16n8k16, ldmatrix; epilogue: leakyrelu+mask -> e fp32,
//           plus per-(row,tile) max & sum-exp partials
//  combine: per-row softmax stats (m, 1/s) from partials
//  AV     : fused exp: stages e fp32, converts to p=exp(e-m)/s fp16 in smem,
//           fp16 mma m16n8k16, relu
// ---------------------------------------------------------------------------

#define ALPHA_SLOPE 0.2f
#define NEG_INF_F  -1.0e12f

#define BB   8
#define NSEQ 2048
#define CDIM 256
#define M_ALL (BB * NSEQ)        // 16384
#define NTILES 16                // NSEQ / 128

#define BM 128
#define BN 128
#define NTHR 256

// ---- bf16 GEMM tile geometry (proj & scores), BK=32 ----
#define BKS 32
#define SP  40                   // bf16 pitch (80B) -> LDSM conflict-free
#define STILE (BM * SP)          // 5120 bf16 per array
#define SA_H 0
#define SA_L STILE
#define SB_H (2 * STILE)
#define SB_L (3 * STILE)
#define SSTG (4 * STILE)         // 20480 bf16 = 40960 B / stage

// ---- AV fused geometry: BM=64, BN=256, BK=32 ----
#define AV_BM 64
#define AFP 36                                // fp32 pitch (A stage)
#define AV_A_BYTES (AV_BM * AFP * 4)          // 9216
#define BKP2 264                              // fp16 pitch (B tile, 256+8)
#define AV_B_BYTES (BKS * BKP2 * 2)           // 16896
#define AV_STG2 (AV_A_BYTES + AV_B_BYTES)     // 26112
#define AV_NSTG 3
#define ACONV_PITCH 40
#define ACONV_BYTES (AV_BM * ACONV_PITCH * 2) // 5120
#define SM_AV (AV_NSTG * AV_STG2 + 2 * ACONV_BYTES)  // 88576

// ---- global scratch ----
__device__ __nv_bfloat16 g_xbH[(size_t)M_ALL * CDIM];
__device__ __nv_bfloat16 g_xbL[(size_t)M_ALL * CDIM];
__device__ __nv_bfloat16 g_wtH[3 * CDIM * CDIM];       // W^T bf16 hi: [z][n][k]
__device__ __nv_bfloat16 g_wtL[3 * CDIM * CDIM];
__device__ __nv_bfloat16 g_hbH[2ull * M_ALL * CDIM];   // h1,h2 bf16 hi
__device__ __nv_bfloat16 g_hbL[2ull * M_ALL * CDIM];   // h1,h2 bf16 lo
__device__ __half g_h316[(size_t)M_ALL * CDIM];        // h3 fp16
__device__ float g_e[(size_t)BB * NSEQ * NSEQ];        // e fp32
__device__ float g_pm[(size_t)BB * NTILES * NSEQ];     // per-tile row max
__device__ float g_ps[(size_t)BB * NTILES * NSEQ];     // per-tile row sum-exp
__device__ float g_rm[(size_t)BB * NSEQ];              // row max
__device__ float g_ri[(size_t)BB * NSEQ];              // row 1/sum

// ---------------- helpers ----------------
__device__ __forceinline__ void mma_bf16(float c[4],
                                         uint32_t a0, uint32_t a1, uint32_t a2, uint32_t a3,
                                         uint32_t b0, uint32_t b1) {
    asm volatile(
        "mma.sync.aligned.m16n8k16.row.col.f32.bf16.bf16.f32 "
        "{%0,%1,%2,%3}, {%4,%5,%6,%7}, {%8,%9}, {%0,%1,%2,%3};\n"
        : "+f"(c[0]), "+f"(c[1]), "+f"(c[2]), "+f"(c[3])
        : "r"(a0), "r"(a1), "r"(a2), "r"(a3), "r"(b0), "r"(b1));
}

__device__ __forceinline__ void mma_fp16(float c[4],
                                         uint32_t a0, uint32_t a1, uint32_t a2, uint32_t a3,
                                         uint32_t b0, uint32_t b1) {
    asm volatile(
        "mma.sync.aligned.m16n8k16.row.col.f32.f16.f16.f32 "
        "{%0,%1,%2,%3}, {%4,%5,%6,%7}, {%8,%9}, {%0,%1,%2,%3};\n"
        : "+f"(c[0]), "+f"(c[1]), "+f"(c[2]), "+f"(c[3])
        : "r"(a0), "r"(a1), "r"(a2), "r"(a3), "r"(b0), "r"(b1));
}

__device__ __forceinline__ void ldsm_x4(uint32_t &r0, uint32_t &r1, uint32_t &r2, uint32_t &r3,
                                        uint32_t addr) {
    asm volatile("ldmatrix.sync.aligned.m8n8.x4.shared.b16 {%0,%1,%2,%3}, [%4];\n"
        : "=r"(r0), "=r"(r1), "=r"(r2), "=r"(r3) : "r"(addr));
}

__device__ __forceinline__ void ldsm_x4_t(uint32_t &r0, uint32_t &r1, uint32_t &r2, uint32_t &r3,
                                          uint32_t addr) {
    asm volatile("ldmatrix.sync.aligned.m8n8.x4.trans.shared.b16 {%0,%1,%2,%3}, [%4];\n"
        : "=r"(r0), "=r"(r1), "=r"(r2), "=r"(r3) : "r"(addr));
}

__device__ __forceinline__ void cpa16(uint32_t dst, const void* src) {
    asm volatile("cp.async.cg.shared.global [%0], [%1], 16;\n" :: "r"(dst), "l"(src) : "memory");
}
__device__ __forceinline__ void cpa_commit() {
    asm volatile("cp.async.commit_group;\n" ::: "memory");
}
template<int N>
__device__ __forceinline__ void cpa_wait() {
    asm volatile("cp.async.wait_group %0;\n" :: "n"(N) : "memory");
}

__device__ __forceinline__ uint32_t smem_u32(const void* p) {
    uint32_t a;
    asm("{ .reg .u64 t; cvta.to.shared.u64 t, %1; cvt.u32.u64 %0, t; }" : "=r"(a) : "l"(p));
    return a;
}

__device__ __forceinline__ void bsplit(float v, __nv_bfloat16 &h, __nv_bfloat16 &l) {
    h = __float2bfloat16_rn(v);
    l = __float2bfloat16_rn(v - __bfloat162float(h));
}

// ---------------- split kernels ----------------
__global__ void __launch_bounds__(256)
split_x_bf16(const float* __restrict__ src,
             __nv_bfloat16* __restrict__ H, __nv_bfloat16* __restrict__ L, int n4)
{
    int i = blockIdx.x * blockDim.x + threadIdx.x;
    if (i >= n4) return;
    float4 v = ((const float4*)src)[i];
    __nv_bfloat16 h0, h1, h2, h3, l0, l1, l2, l3;
    bsplit(v.x, h0, l0); bsplit(v.y, h1, l1);
    bsplit(v.z, h2, l2); bsplit(v.w, h3, l3);
    ((__nv_bfloat162*)H)[2 * i]     = __nv_bfloat162(h0, h1);
    ((__nv_bfloat162*)H)[2 * i + 1] = __nv_bfloat162(h2, h3);
    ((__nv_bfloat162*)L)[2 * i]     = __nv_bfloat162(l0, l1);
    ((__nv_bfloat162*)L)[2 * i + 1] = __nv_bfloat162(l2, l3);
}

// transpose + split W: wt[z][n][k] = W_z[k][n]
__global__ void __launch_bounds__(256)
split_wt_bf16(const float* __restrict__ W1, const float* __restrict__ W2,
              const float* __restrict__ W3,
              __nv_bfloat16* __restrict__ H, __nv_bfloat16* __restrict__ L)
{
    const int z = blockIdx.y;
    const float* src = (z == 0) ? W1 : (z == 1) ? W2 : W3;
    const int idx = blockIdx.x * 256 + threadIdx.x;   // 0..65535
    const int k = idx >> 8;
    const int n = idx & 255;
    float v = src[k * CDIM + n];
    __nv_bfloat16 h, l;
    bsplit(v, h, l);
    const size_t o = (size_t)z * CDIM * CDIM + (size_t)n * CDIM + k;
    H[o] = h;
    L[o] = l;
}

// ---------------- projection GEMM: 3x-bf16 m16n8k16 ----------------
// C = X @ W_z ; z<2 -> bf16 hi/lo (h1,h2), z==2 -> fp16 (h3)
__global__ void __launch_bounds__(NTHR, 2)
proj_bf16(const __nv_bfloat16* __restrict__ xH, const __nv_bfloat16* __restrict__ xL,
          const __nv_bfloat16* __restrict__ wtH, const __nv_bfloat16* __restrict__ wtL,
          __nv_bfloat16* __restrict__ CbH, __nv_bfloat16* __restrict__ CbL,
          __half* __restrict__ C16)
{
    extern __shared__ __align__(16) __nv_bfloat16 smb[];
    constexpr int STAGES = 2;

    const int tid  = threadIdx.x;
    const int lane = tid & 31;
    const int warp = tid >> 5;
    const int wm = warp & 3, wn = warp >> 2;
    const int lr = lane >> 2, lc = lane & 3;
    const int n0 = blockIdx.x * BN;
    const int m0 = blockIdx.y * BM;
    const int z  = blockIdx.z;

    const __nv_bfloat16* A_H = xH + (size_t)m0 * CDIM;
    const __nv_bfloat16* A_L = xL + (size_t)m0 * CDIM;
    const __nv_bfloat16* B_H = wtH + (size_t)z * CDIM * CDIM + (size_t)n0 * CDIM;
    const __nv_bfloat16* B_L = wtL + (size_t)z * CDIM * CDIM + (size_t)n0 * CDIM;

    uint32_t sbase = smem_u32(smb);

    const int lrow = tid >> 1;
    const int lcb  = (tid & 1) * 16;
    const int qrow = lane & 15;
    const int qcol = (lane >> 4) << 3;

    auto issue = [&](int t) {
        const int buf = t % STAGES;
        const uint32_t sb = sbase + (uint32_t)(buf * SSTG) * 2u;
        const int kofs = t * BKS;
        const long long go0 = (long long)lrow * CDIM + kofs + lcb;
        const uint32_t d0 = (uint32_t)(lrow * SP + lcb) * 2u;
        cpa16(sb + (SA_H * 2u) + d0,      A_H + go0);
        cpa16(sb + (SA_H * 2u) + d0 + 16, A_H + go0 + 8);
        cpa16(sb + (SA_L * 2u) + d0,      A_L + go0);
        cpa16(sb + (SA_L * 2u) + d0 + 16, A_L + go0 + 8);
        cpa16(sb + (SB_H * 2u) + d0,      B_H + go0);
        cpa16(sb + (SB_H * 2u) + d0 + 16, B_H + go0 + 8);
        cpa16(sb + (SB_L * 2u) + d0,      B_L + go0);
        cpa16(sb + (SB_L * 2u) + d0 + 16, B_L + go0 + 8);
        cpa_commit();
    };

    float acc[2][8][4];
    #pragma unroll
    for (int i = 0; i < 2; i++)
        #pragma unroll
        for (int j = 0; j < 8; j++)
            #pragma unroll
            for (int q = 0; q < 4; q++) acc[i][j][q] = 0.f;

    const int T = CDIM / BKS;   // 8
    issue(0);

    for (int t = 0; t < T; t++) {
        cpa_wait<0>();
        __syncthreads();
        if (t + 1 < T) issue(t + 1); else cpa_commit();

        const int buf = t % STAGES;
        const uint32_t sb = sbase + (uint32_t)(buf * SSTG) * 2u;

        #pragma unroll
        for (int ks = 0; ks < 2; ks++) {
            const int kb = ks * 16;
            uint32_t aH[2][4], aL[2][4];
            #pragma unroll
            for (int mt = 0; mt < 2; mt++) {
                const uint32_t ro = (uint32_t)((wm * 32 + mt * 16 + qrow) * SP + kb + qcol) * 2u;
                ldsm_x4(aH[mt][0], aH[mt][1], aH[mt][2], aH[mt][3], sb + SA_H * 2u + ro);
                ldsm_x4(aL[mt][0], aL[mt][1], aL[mt][2], aL[mt][3], sb + SA_L * 2u + ro);
            }
            #pragma unroll
            for (int ng = 0; ng < 4; ng++) {
                const uint32_t bo = (uint32_t)((wn * 64 + ng * 16 + qrow) * SP + kb + qcol) * 2u;
                uint32_t bh[4], bl[4];
                ldsm_x4(bh[0], bh[1], bh[2], bh[3], sb + SB_H * 2u + bo);
                ldsm_x4(bl[0], bl[1], bl[2], bl[3], sb + SB_L * 2u + bo);
                #pragma unroll
                for (int sel = 0; sel < 2; sel++) {
                    const int nt = ng * 2 + sel;
                    const uint32_t bH0 = bh[sel], bH1 = bh[sel + 2];
                    const uint32_t bL0 = bl[sel], bL1 = bl[sel + 2];
                    #pragma unroll
                    for (int mt = 0; mt < 2; mt++) {
                        mma_bf16(acc[mt][nt], aH[mt][0], aH[mt][1], aH[mt][2], aH[mt][3], bL0, bL1);
                        mma_bf16(acc[mt][nt], aL[mt][0], aL[mt][1], aL[mt][2], aL[mt][3], bH0, bH1);
                        mma_bf16(acc[mt][nt], aH[mt][0], aH[mt][1], aH[mt][2], aH[mt][3], bH0, bH1);
                    }
                }
            }
        }
    }

    // ---- epilogue ----
    #pragma unroll
    for (int mt = 0; mt < 2; mt++) {
        #pragma unroll
        for (int nt = 0; nt < 8; nt++) {
            const int r0 = m0 + wm * 32 + mt * 16 + lr;
            const int c0 = n0 + wn * 64 + nt * 8 + lc * 2;
            if (z < 2) {
                __nv_bfloat16* DH = CbH + (size_t)z * M_ALL * CDIM;
                __nv_bfloat16* DL = CbL + (size_t)z * M_ALL * CDIM;
                #pragma unroll
                for (int rq = 0; rq < 2; rq++) {
                    const int r = r0 + rq * 8;
                    float v0 = acc[mt][nt][rq * 2 + 0];
                    float v1 = acc[mt][nt][rq * 2 + 1];
                    __nv_bfloat16 h0, l0, h1, l1;
                    bsplit(v0, h0, l0);
                    bsplit(v1, h1, l1);
                    const size_t o = (size_t)r * CDIM + c0;
                    *(__nv_bfloat162*)(DH + o) = __nv_bfloat162(h0, h1);
                    *(__nv_bfloat162*)(DL + o) = __nv_bfloat162(l0, l1);
                }
            } else {
                #pragma unroll
                for (int rq = 0; rq < 2; rq++) {
                    const int r = r0 + rq * 8;
                    const size_t o = (size_t)r * CDIM + c0;
                    *(__half2*)(C16 + o) =
                        __floats2half2_rn(acc[mt][nt][rq * 2 + 0], acc[mt][nt][rq * 2 + 1]);
                }
            }
        }
    }
}

// ---------------- scores GEMM: 3x-bf16 + per-tile softmax partials ----------------
__global__ void __launch_bounds__(NTHR, 2)
scores_bf16(const __nv_bfloat16* __restrict__ h1H, const __nv_bfloat16* __restrict__ h1L,
            const __nv_bfloat16* __restrict__ h2H, const __nv_bfloat16* __restrict__ h2L,
            const int* __restrict__ adj, float* __restrict__ e,
            float* __restrict__ pm, float* __restrict__ ps)
{
    extern __shared__ __align__(16) __nv_bfloat16 smb[];
    constexpr int STAGES = 2;

    const int tid  = threadIdx.x;
    const int lane = tid & 31;
    const int warp = tid >> 5;
    const int wm = warp & 3, wn = warp >> 2;
    const int lr = lane >> 2, lc = lane & 3;
    const int n0 = blockIdx.x * BN;
    const int m0 = blockIdx.y * BM;
    const int z  = blockIdx.z;

    const long long BS = (long long)NSEQ * CDIM;
    const __nv_bfloat16* A_H = h1H + z * BS + (long long)m0 * CDIM;
    const __nv_bfloat16* A_L = h1L + z * BS + (long long)m0 * CDIM;
    const __nv_bfloat16* B_H = h2H + z * BS + (long long)n0 * CDIM;
    const __nv_bfloat16* B_L = h2L + z * BS + (long long)n0 * CDIM;

    uint32_t sbase = smem_u32(smb);

    const int lrow = tid >> 1;
    const int lcb  = (tid & 1) * 16;
    const int qrow = lane & 15;
    const int qcol = (lane >> 4) << 3;

    auto issue = [&](int t) {
        const int buf = t % STAGES;
        const uint32_t sb = sbase + (uint32_t)(buf * SSTG) * 2u;
        const int kofs = t * BKS;
        const long long go0 = (long long)lrow * CDIM + kofs + lcb;
        const uint32_t d0 = (uint32_t)(lrow * SP + lcb) * 2u;
        cpa16(sb + (SA_H * 2u) + d0,      A_H + go0);
        cpa16(sb + (SA_H * 2u) + d0 + 16, A_H + go0 + 8);
        cpa16(sb + (SA_L * 2u) + d0,      A_L + go0);
        cpa16(sb + (SA_L * 2u) + d0 + 16, A_L + go0 + 8);
        cpa16(sb + (SB_H * 2u) + d0,      B_H + go0);
        cpa16(sb + (SB_H * 2u) + d0 + 16, B_H + go0 + 8);
        cpa16(sb + (SB_L * 2u) + d0,      B_L + go0);
        cpa16(sb + (SB_L * 2u) + d0 + 16, B_L + go0 + 8);
        cpa_commit();
    };

    float acc[2][8][4];
    #pragma unroll
    for (int i = 0; i < 2; i++)
        #pragma unroll
        for (int j = 0; j < 8; j++)
            #pragma unroll
            for (int q = 0; q < 4; q++) acc[i][j][q] = 0.f;

    const int T = CDIM / BKS;   // 8
    issue(0);

    for (int t = 0; t < T; t++) {
        cpa_wait<0>();
        __syncthreads();
        if (t + 1 < T) issue(t + 1); else cpa_commit();

        const int buf = t % STAGES;
        const uint32_t sb = sbase + (uint32_t)(buf * SSTG) * 2u;

        #pragma unroll
        for (int ks = 0; ks < 2; ks++) {
            const int kb = ks * 16;
            uint32_t aH[2][4], aL[2][4];
            #pragma unroll
            for (int mt = 0; mt < 2; mt++) {
                const uint32_t ro = (uint32_t)((wm * 32 + mt * 16 + qrow) * SP + kb + qcol) * 2u;
                ldsm_x4(aH[mt][0], aH[mt][1], aH[mt][2], aH[mt][3], sb + SA_H * 2u + ro);
                ldsm_x4(aL[mt][0], aL[mt][1], aL[mt][2], aL[mt][3], sb + SA_L * 2u + ro);
            }
            #pragma unroll
            for (int ng = 0; ng < 4; ng++) {
                const uint32_t bo = (uint32_t)((wn * 64 + ng * 16 + qrow) * SP + kb + qcol) * 2u;
                uint32_t bh[4], bl[4];
                ldsm_x4(bh[0], bh[1], bh[2], bh[3], sb + SB_H * 2u + bo);
                ldsm_x4(bl[0], bl[1], bl[2], bl[3], sb + SB_L * 2u + bo);
                #pragma unroll
                for (int sel = 0; sel < 2; sel++) {
                    const int nt = ng * 2 + sel;
                    const uint32_t bH0 = bh[sel], bH1 = bh[sel + 2];
                    const uint32_t bL0 = bl[sel], bL1 = bl[sel + 2];
                    #pragma unroll
                    for (int mt = 0; mt < 2; mt++) {
                        mma_bf16(acc[mt][nt], aH[mt][0], aH[mt][1], aH[mt][2], aH[mt][3], bL0, bL1);
                        mma_bf16(acc[mt][nt], aL[mt][0], aL[mt][1], aL[mt][2], aL[mt][3], bH0, bH1);
                        mma_bf16(acc[mt][nt], aH[mt][0], aH[mt][1], aH[mt][2], aH[mt][3], bH0, bH1);
                    }
                }
            }
        }
    }

    // ---- epilogue pass A: leakyrelu + mask -> e (and masked values back to acc) ----
    float* Cp = e + (size_t)z * NSEQ * NSEQ;
    float mx[2][2];
    mx[0][0] = mx[0][1] = mx[1][0] = mx[1][1] = -3.0e38f;
    #pragma unroll
    for (int mt = 0; mt < 2; mt++) {
        #pragma unroll
        for (int nt = 0; nt < 8; nt++) {
            const int r0 = m0 + wm * 32 + mt * 16 + lr;
            const int c0 = n0 + wn * 64 + nt * 8 + lc * 2;
            #pragma unroll
            for (int q = 0; q < 4; q++) {
                const int r = r0 + (q >> 1) * 8;
                const int c = c0 + (q & 1);
                float v = acc[mt][nt][q];
                v = (v > 0.f) ? v : ALPHA_SLOPE * v;
                v = (adj[(size_t)r * NSEQ + c] > 0) ? v : NEG_INF_F;
                acc[mt][nt][q] = v;
                Cp[(size_t)r * NSEQ + c] = v;
                mx[mt][q >> 1] = fmaxf(mx[mt][q >> 1], v);
            }
        }
    }

    // ---- epilogue pass B: per-row tile max + sum-exp partials ----
    float* red = reinterpret_cast<float*>(smb);   // reuse stage smem: [2][128]
    __syncthreads();

    #pragma unroll
    for (int mt = 0; mt < 2; mt++)
        #pragma unroll
        for (int qr = 0; qr < 2; qr++) {
            float v = mx[mt][qr];
            v = fmaxf(v, __shfl_xor_sync(0xffffffffu, v, 1));
            v = fmaxf(v, __shfl_xor_sync(0xffffffffu, v, 2));
            mx[mt][qr] = v;
        }
    if (lc == 0) {
        #pragma unroll
        for (int mt = 0; mt < 2; mt++)
            #pragma unroll
            for (int qr = 0; qr < 2; qr++)
                red[wn * 128 + wm * 32 + mt * 16 + qr * 8 + lr] = mx[mt][qr];
    }
    __syncthreads();
    float M[2][2];
    #pragma unroll
    for (int mt = 0; mt < 2; mt++)
        #pragma unroll
        for (int qr = 0; qr < 2; qr++) {
            const int lro = wm * 32 + mt * 16 + qr * 8 + lr;
            M[mt][qr] = fmaxf(red[lro], red[128 + lro]);
        }
    __syncthreads();

    float Ss[2][2];
    #pragma unroll
    for (int mt = 0; mt < 2; mt++)
        #pragma unroll
        for (int qr = 0; qr < 2; qr++) {
            float s = 0.f;
            #pragma unroll
            for (int nt = 0; nt < 8; nt++) {
                s += __expf(acc[mt][nt][qr * 2 + 0] - M[mt][qr]);
                s += __expf(acc[mt][nt][qr * 2 + 1] - M[mt][qr]);
            }
            s += __shfl_xor_sync(0xffffffffu, s, 1);
            s += __shfl_xor_sync(0xffffffffu, s, 2);
            Ss[mt][qr] = s;
        }
    if (lc == 0) {
        #pragma unroll
        for (int mt = 0; mt < 2; mt++)
            #pragma unroll
            for (int qr = 0; qr < 2; qr++)
                red[wn * 128 + wm * 32 + mt * 16 + qr * 8 + lr] = Ss[mt][qr];
    }
    __syncthreads();
    if (wn == 0 && lc == 0) {
        #pragma unroll
        for (int mt = 0; mt < 2; mt++)
            #pragma unroll
            for (int qr = 0; qr < 2; qr++) {
                const int lro = wm * 32 + mt * 16 + qr * 8 + lr;
                const size_t o = ((size_t)z * NTILES + blockIdx.x) * NSEQ + m0 + lro;
                pm[o] = M[mt][qr];
                ps[o] = red[lro] + red[128 + lro];
            }
    }
}

// ---------------- combine: per-row softmax stats ----------------
__global__ void __launch_bounds__(256)
combine_kernel(const float* __restrict__ pm, const float* __restrict__ ps,
               float* __restrict__ rm, float* __restrict__ ri)
{
    const int g = blockIdx.x * 256 + threadIdx.x;   // 0..16383
    const int z = g >> 11;
    const int row = g & 2047;
    const float* pmz = pm + (size_t)z * NTILES * NSEQ + row;
    const float* psz = ps + (size_t)z * NTILES * NSEQ + row;

    float m = -3.0e38f;
    #pragma unroll
    for (int t = 0; t < NTILES; t++) m = fmaxf(m, pmz[(size_t)t * NSEQ]);
    float s = 0.f;
    #pragma unroll
    for (int t = 0; t < NTILES; t++)
        s += psz[(size_t)t * NSEQ] * __expf(pmz[(size_t)t * NSEQ] - m);
    rm[g] = m;
    ri[g] = 1.0f / s;
}

// ---------------- AV fused: p = exp(e-m)/s on the fly, fp16 mma ----------------
// out[q,d] = relu( sum_k p[q,k] * h3[k,d] ),  BM=64 x BN=256 per CTA
__global__ void __launch_bounds__(NTHR, 2)
av_fused(const float* __restrict__ e, const __half* __restrict__ h3,
         const float* __restrict__ rm, const float* __restrict__ ri,
         float* __restrict__ out)
{
    extern __shared__ __align__(16) uint8_t avs[];

    const int tid  = threadIdx.x;
    const int lane = tid & 31;
    const int warp = tid >> 5;
    const int wm = warp & 1;        // 2 warps over 64 rows
    const int wn = warp >> 1;       // 4 warps over 256 cols
    const int lr = lane >> 2, lc = lane & 3;
    const int m0 = blockIdx.x * AV_BM;
    const int z  = blockIdx.y;

    const float*  Ap = e  + (size_t)z * NSEQ * NSEQ + (size_t)m0 * NSEQ;
    const __half* Bp = h3 + (size_t)z * NSEQ * CDIM;

    uint32_t sbase = smem_u32(avs);

    const int qrow = lane & 15;
    const int qcol = (lane >> 4) << 3;

    // convert-thread row and its softmax stats
    const int crow = tid >> 2;      // 0..63
    const int cq   = tid & 3;       // quarter of 32 cols
    const float mrow = rm[(size_t)z * NSEQ + m0 + crow];
    const float irow = ri[(size_t)z * NSEQ + m0 + crow];

    auto issue = [&](int t) {
        const int buf = t % AV_NSTG;
        const uint32_t sA = sbase + (uint32_t)(buf * AV_STG2);
        const uint32_t sB = sA + AV_A_BYTES;
        const int kofs = t * BKS;
        {   // A: e fp32, 64x32
            const float* src = Ap + (size_t)crow * NSEQ + kofs + cq * 8;
            const uint32_t d = sA + (uint32_t)(crow * AFP + cq * 8) * 4u;
            cpa16(d,      src);
            cpa16(d + 16, src + 4);
        }
        {   // B: h3 fp16, 32x256
            const int brow = tid >> 3, bq = tid & 7;
            const __half* src = Bp + (size_t)(kofs + brow) * CDIM + bq * 32;
            const uint32_t d = sB + (uint32_t)(brow * BKP2 + bq * 32) * 2u;
            cpa16(d,      src);
            cpa16(d + 16, src + 8);
            cpa16(d + 32, src + 16);
            cpa16(d + 48, src + 24);
        }
        cpa_commit();
    };

    float acc[2][8][4];
    #pragma unroll
    for (int i = 0; i < 2; i++)
        #pragma unroll
        for (int j = 0; j < 8; j++)
            #pragma unroll
            for (int q = 0; q < 4; q++) acc[i][j][q] = 0.f;

    const int T = NSEQ / BKS;   // 64
    issue(0);
    issue(1);

    for (int t = 0; t < T; t++) {
        cpa_wait<AV_NSTG - 2>();     // tile t's data complete
        __syncthreads();

        // ---- convert A tile t: fp32 -> p fp16 ----
        {
            const float* af = (const float*)(avs + (size_t)(t % AV_NSTG) * AV_STG2);
            const float* rowp = af + crow * AFP + cq * 8;
            float4 u0 = *(const float4*)(rowp);
            float4 u1 = *(const float4*)(rowp + 4);
            __half2 p0 = __floats2half2_rn(__expf(u0.x - mrow) * irow,
                                           __expf(u0.y - mrow) * irow);
            __half2 p1 = __floats2half2_rn(__expf(u0.z - mrow) * irow,
                                           __expf(u0.w - mrow) * irow);
            __half2 p2 = __floats2half2_rn(__expf(u1.x - mrow) * irow,
                                           __expf(u1.y - mrow) * irow);
            __half2 p3 = __floats2half2_rn(__expf(u1.z - mrow) * irow,
                                           __expf(u1.w - mrow) * irow);
            uint4 w;
            w.x = *(uint32_t*)&p0; w.y = *(uint32_t*)&p1;
            w.z = *(uint32_t*)&p2; w.w = *(uint32_t*)&p3;
            uint4* cw = (uint4*)(avs + AV_NSTG * AV_STG2 + (size_t)(t & 1) * ACONV_BYTES
                                 + (size_t)(crow * ACONV_PITCH + cq * 8) * 2);
            *cw = w;
        }
        __syncthreads();

        if (t + 2 < T) issue(t + 2); else cpa_commit();

        // ---- mma: A from conv buf, B from stage ----
        const uint32_t convb = sbase + (uint32_t)(AV_NSTG * AV_STG2) + (uint32_t)((t & 1) * ACONV_BYTES);
        const uint32_t sB    = sbase + (uint32_t)((t % AV_NSTG) * AV_STG2) + AV_A_BYTES;

        #pragma unroll
        for (int ks = 0; ks < 2; ks++) {
            const int kb = ks * 16;
            uint32_t a[2][4];
            #pragma unroll
            for (int mt = 0; mt < 2; mt++) {
                const uint32_t ro = (uint32_t)((wm * 32 + mt * 16 + qrow) * ACONV_PITCH + kb + qcol) * 2u;
                ldsm_x4(a[mt][0], a[mt][1], a[mt][2], a[mt][3], convb + ro);
            }
            #pragma unroll
            for (int ng = 0; ng < 4; ng++) {
                const int nb = wn * 64 + ng * 16;
                const uint32_t bo = (uint32_t)((kb + qrow) * BKP2 + nb + qcol) * 2u;
                uint32_t b[4];
                ldsm_x4_t(b[0], b[1], b[2], b[3], sB + bo);
                #pragma unroll
                for (int sel = 0; sel < 2; sel++) {
                    const int nt = ng * 2 + sel;
                    #pragma unroll
                    for (int mt = 0; mt < 2; mt++) {
                        mma_fp16(acc[mt][nt], a[mt][0], a[mt][1], a[mt][2], a[mt][3],
                                 b[2 * sel], b[2 * sel + 1]);
                    }
                }
            }
        }
    }

    // ---- epilogue: relu ----
    float* Cp = out + (size_t)z * NSEQ * CDIM;
    #pragma unroll
    for (int mt = 0; mt < 2; mt++) {
        #pragma unroll
        for (int nt = 0; nt < 8; nt++) {
            const int r0 = m0 + wm * 32 + mt * 16 + lr;
            const int c0 = wn * 64 + nt * 8 + lc * 2;
            #pragma unroll
            for (int q = 0; q < 4; q++) {
                const int r = r0 + (q >> 1) * 8;
                const int c = c0 + (q & 1);
                float v = acc[mt][nt][q];
                Cp[(size_t)r * CDIM + c] = (v > 0.f) ? v : 0.f;
            }
        }
    }
}

// ---------------- launcher ----------------
extern "C" void kernel_launch(void* const* d_in, const int* in_sizes, int n_in,
                              void* d_out, int out_size)
{
    const float* inp = (const float*)d_in[0];
    const int*   adj = (const int*)d_in[1];
    const float* W1  = (const float*)d_in[2];
    const float* W2  = (const float*)d_in[3];
    const float* W3  = (const float*)d_in[4];
    float* out = (float*)d_out;

    __nv_bfloat16 *xbH, *xbL, *wtH, *wtL, *hbH, *hbL;
    __half *h316;
    float *e, *pm, *ps, *rm, *ri;
    cudaGetSymbolAddress((void**)&xbH,  g_xbH);
    cudaGetSymbolAddress((void**)&xbL,  g_xbL);
    cudaGetSymbolAddress((void**)&wtH,  g_wtH);
    cudaGetSymbolAddress((void**)&wtL,  g_wtL);
    cudaGetSymbolAddress((void**)&hbH,  g_hbH);
    cudaGetSymbolAddress((void**)&hbL,  g_hbL);
    cudaGetSymbolAddress((void**)&h316, g_h316);
    cudaGetSymbolAddress((void**)&e,    g_e);
    cudaGetSymbolAddress((void**)&pm,   g_pm);
    cudaGetSymbolAddress((void**)&ps,   g_ps);
    cudaGetSymbolAddress((void**)&rm,   g_rm);
    cudaGetSymbolAddress((void**)&ri,   g_ri);

    const int SM_BF = SSTG * 2 * 2;     // 81920 B
    cudaFuncSetAttribute(proj_bf16,   cudaFuncAttributeMaxDynamicSharedMemorySize, SM_BF);
    cudaFuncSetAttribute(scores_bf16, cudaFuncAttributeMaxDynamicSharedMemorySize, SM_BF);
    cudaFuncSetAttribute(av_fused,    cudaFuncAttributeMaxDynamicSharedMemorySize, SM_AV);

    // 0) split X (bf16 hi/lo) and W^T (bf16 hi/lo)
    {
        const int xn4 = (int)((size_t)M_ALL * CDIM / 4);
        split_x_bf16<<<(xn4 + 255) / 256, 256>>>(inp, xbH, xbL, xn4);
        dim3 gw(CDIM * CDIM / 256, 3);
        split_wt_bf16<<<gw, 256>>>(W1, W2, W3, wtH, wtL);
    }
    // 1) projections: z=0,1 -> bf16 hi/lo (h1,h2); z=2 -> fp16 (h3)
    {
        dim3 g(CDIM / BN, M_ALL / BM, 3);
        proj_bf16<<<g, NTHR, SM_BF>>>(xbH, xbL, wtH, wtL, hbH, hbL, h316);
    }
    // 2) scores + per-tile softmax partials
    {
        dim3 g(NSEQ / BN, NSEQ / BM, BB);
        scores_bf16<<<g, NTHR, SM_BF>>>(hbH, hbL,
                                        hbH + (size_t)M_ALL * CDIM, hbL + (size_t)M_ALL * CDIM,
                                        adj, e, pm, ps);
    }
    // 3) combine partials -> per-row (max, 1/sum)
    combine_kernel<<<(BB * NSEQ) / 256, 256>>>(pm, ps, rm, ri);
    // 4) AV with fused exp
    {
        dim3 g(NSEQ / AV_BM, BB);
        av_fused<<<g, NTHR, SM_AV>>>(e, h316, rm, ri, out);
    }
}

// round 9
// speedup vs baseline: 2.1578x; 1.0540x over previous
#include <cuda_runtime.h>
#include <cuda_bf16.h>
#include <cuda_fp16.h>
#include <cstdint>

// ---------------------------------------------------------------------------
// GraphAttentionLayer on GB300 (sm_103a; harness PTX target lacks 'a' suffix,
// so tcgen05 is unavailable -> mma.sync throughout).
//  proj   : 3x-bf16 mma m16n8k16 -> h1/h2 bf16 hi/lo, h3 fp16
//  scores : 3x-bf16 mma m16n8k16; epilogue: leakyrelu+mask, per-tile softmax
//           partials, stores p_t = fp16(exp(e - m_tile))  (no fp32 e tensor!)
//  combine: per-row softmax stats (m_row, 1/s_row)
//  AV     : stages p_t fp16; in-place scale by s_qt = exp(m_tile-m_row)/s_row
//           (precomputed per-CTA table), fp16 mma m16n8k16, relu
// ---------------------------------------------------------------------------

#define ALPHA_SLOPE 0.2f
#define NEG_INF_F  -1.0e12f

#define BB   8
#define NSEQ 2048
#define CDIM 256
#define M_ALL (BB * NSEQ)        // 16384
#define NTILES 16                // NSEQ / 128

#define BM 128
#define BN 128
#define NTHR 256

// ---- bf16 GEMM tile geometry (proj & scores), BK=32 ----
#define BKS 32
#define SP  40                   // bf16 pitch (80B) -> LDSM conflict-free
#define STILE (BM * SP)          // 5120 bf16 per array
#define SA_H 0
#define SA_L STILE
#define SB_H (2 * STILE)
#define SB_L (3 * STILE)
#define SSTG (4 * STILE)         // 20480 bf16 = 40960 B / stage

// ---- AV fused geometry: BM=64, BN=256, BK=32 ----
#define AV_BM 64
#define APT 40                                // p_t stage pitch (fp16)
#define AV_A_BYTES (AV_BM * APT * 2)          // 5120
#define BKP2 264                              // h3 tile pitch (fp16, 256+8)
#define AV_B_BYTES (BKS * BKP2 * 2)           // 16896
#define AV_STG2 (AV_A_BYTES + AV_B_BYTES)     // 22016
#define AV_NSTG 4
#define AV_STAB (AV_NSTG * AV_STG2)           // 88064
#define SM_AV (AV_STAB + AV_BM * NTILES * 4)  // + 4KB scale table = 92160

// ---- global scratch ----
__device__ __nv_bfloat16 g_xbH[(size_t)M_ALL * CDIM];
__device__ __nv_bfloat16 g_xbL[(size_t)M_ALL * CDIM];
__device__ __nv_bfloat16 g_wtH[3 * CDIM * CDIM];       // W^T bf16 hi: [z][n][k]
__device__ __nv_bfloat16 g_wtL[3 * CDIM * CDIM];
__device__ __nv_bfloat16 g_hbH[2ull * M_ALL * CDIM];   // h1,h2 bf16 hi
__device__ __nv_bfloat16 g_hbL[2ull * M_ALL * CDIM];   // h1,h2 bf16 lo
__device__ __half g_h316[(size_t)M_ALL * CDIM];        // h3 fp16
__device__ __half g_pt[(size_t)BB * NSEQ * NSEQ];      // p_t = exp(e - m_tile) fp16
__device__ float g_pm[(size_t)BB * NTILES * NSEQ];     // per-tile row max
__device__ float g_ps[(size_t)BB * NTILES * NSEQ];     // per-tile row sum-exp
__device__ float g_rm[(size_t)BB * NSEQ];              // row max
__device__ float g_ri[(size_t)BB * NSEQ];              // row 1/sum

// ---------------- helpers ----------------
__device__ __forceinline__ void mma_bf16(float c[4],
                                         uint32_t a0, uint32_t a1, uint32_t a2, uint32_t a3,
                                         uint32_t b0, uint32_t b1) {
    asm volatile(
        "mma.sync.aligned.m16n8k16.row.col.f32.bf16.bf16.f32 "
        "{%0,%1,%2,%3}, {%4,%5,%6,%7}, {%8,%9}, {%0,%1,%2,%3};\n"
        : "+f"(c[0]), "+f"(c[1]), "+f"(c[2]), "+f"(c[3])
        : "r"(a0), "r"(a1), "r"(a2), "r"(a3), "r"(b0), "r"(b1));
}

__device__ __forceinline__ void mma_fp16(float c[4],
                                         uint32_t a0, uint32_t a1, uint32_t a2, uint32_t a3,
                                         uint32_t b0, uint32_t b1) {
    asm volatile(
        "mma.sync.aligned.m16n8k16.row.col.f32.f16.f16.f32 "
        "{%0,%1,%2,%3}, {%4,%5,%6,%7}, {%8,%9}, {%0,%1,%2,%3};\n"
        : "+f"(c[0]), "+f"(c[1]), "+f"(c[2]), "+f"(c[3])
        : "r"(a0), "r"(a1), "r"(a2), "r"(a3), "r"(b0), "r"(b1));
}

__device__ __forceinline__ void ldsm_x4(uint32_t &r0, uint32_t &r1, uint32_t &r2, uint32_t &r3,
                                        uint32_t addr) {
    asm volatile("ldmatrix.sync.aligned.m8n8.x4.shared.b16 {%0,%1,%2,%3}, [%4];\n"
        : "=r"(r0), "=r"(r1), "=r"(r2), "=r"(r3) : "r"(addr));
}

__device__ __forceinline__ void ldsm_x4_t(uint32_t &r0, uint32_t &r1, uint32_t &r2, uint32_t &r3,
                                          uint32_t addr) {
    asm volatile("ldmatrix.sync.aligned.m8n8.x4.trans.shared.b16 {%0,%1,%2,%3}, [%4];\n"
        : "=r"(r0), "=r"(r1), "=r"(r2), "=r"(r3) : "r"(addr));
}

__device__ __forceinline__ void cpa16(uint32_t dst, const void* src) {
    asm volatile("cp.async.cg.shared.global [%0], [%1], 16;\n" :: "r"(dst), "l"(src) : "memory");
}
__device__ __forceinline__ void cpa_commit() {
    asm volatile("cp.async.commit_group;\n" ::: "memory");
}
template<int N>
__device__ __forceinline__ void cpa_wait() {
    asm volatile("cp.async.wait_group %0;\n" :: "n"(N) : "memory");
}

__device__ __forceinline__ uint32_t smem_u32(const void* p) {
    uint32_t a;
    asm("{ .reg .u64 t; cvta.to.shared.u64 t, %1; cvt.u32.u64 %0, t; }" : "=r"(a) : "l"(p));
    return a;
}

__device__ __forceinline__ void bsplit(float v, __nv_bfloat16 &h, __nv_bfloat16 &l) {
    h = __float2bfloat16_rn(v);
    l = __float2bfloat16_rn(v - __bfloat162float(h));
}

// ---------------- split kernels ----------------
__global__ void __launch_bounds__(256)
split_x_bf16(const float* __restrict__ src,
             __nv_bfloat16* __restrict__ H, __nv_bfloat16* __restrict__ L, int n4)
{
    int i = blockIdx.x * blockDim.x + threadIdx.x;
    if (i >= n4) return;
    float4 v = ((const float4*)src)[i];
    __nv_bfloat16 h0, h1, h2, h3, l0, l1, l2, l3;
    bsplit(v.x, h0, l0); bsplit(v.y, h1, l1);
    bsplit(v.z, h2, l2); bsplit(v.w, h3, l3);
    ((__nv_bfloat162*)H)[2 * i]     = __nv_bfloat162(h0, h1);
    ((__nv_bfloat162*)H)[2 * i + 1] = __nv_bfloat162(h2, h3);
    ((__nv_bfloat162*)L)[2 * i]     = __nv_bfloat162(l0, l1);
    ((__nv_bfloat162*)L)[2 * i + 1] = __nv_bfloat162(l2, l3);
}

// transpose + split W: wt[z][n][k] = W_z[k][n]
__global__ void __launch_bounds__(256)
split_wt_bf16(const float* __restrict__ W1, const float* __restrict__ W2,
              const float* __restrict__ W3,
              __nv_bfloat16* __restrict__ H, __nv_bfloat16* __restrict__ L)
{
    const int z = blockIdx.y;
    const float* src = (z == 0) ? W1 : (z == 1) ? W2 : W3;
    const int idx = blockIdx.x * 256 + threadIdx.x;
    const int k = idx >> 8;
    const int n = idx & 255;
    float v = src[k * CDIM + n];
    __nv_bfloat16 h, l;
    bsplit(v, h, l);
    const size_t o = (size_t)z * CDIM * CDIM + (size_t)n * CDIM + k;
    H[o] = h;
    L[o] = l;
}

// ---------------- projection GEMM: 3x-bf16 m16n8k16 ----------------
__global__ void __launch_bounds__(NTHR, 2)
proj_bf16(const __nv_bfloat16* __restrict__ xH, const __nv_bfloat16* __restrict__ xL,
          const __nv_bfloat16* __restrict__ wtH, const __nv_bfloat16* __restrict__ wtL,
          __nv_bfloat16* __restrict__ CbH, __nv_bfloat16* __restrict__ CbL,
          __half* __restrict__ C16)
{
    extern __shared__ __align__(16) __nv_bfloat16 smb[];
    constexpr int STAGES = 2;

    const int tid  = threadIdx.x;
    const int lane = tid & 31;
    const int warp = tid >> 5;
    const int wm = warp & 3, wn = warp >> 2;
    const int lr = lane >> 2, lc = lane & 3;
    const int n0 = blockIdx.x * BN;
    const int m0 = blockIdx.y * BM;
    const int z  = blockIdx.z;

    const __nv_bfloat16* A_H = xH + (size_t)m0 * CDIM;
    const __nv_bfloat16* A_L = xL + (size_t)m0 * CDIM;
    const __nv_bfloat16* B_H = wtH + (size_t)z * CDIM * CDIM + (size_t)n0 * CDIM;
    const __nv_bfloat16* B_L = wtL + (size_t)z * CDIM * CDIM + (size_t)n0 * CDIM;

    uint32_t sbase = smem_u32(smb);

    const int lrow = tid >> 1;
    const int lcb  = (tid & 1) * 16;
    const int qrow = lane & 15;
    const int qcol = (lane >> 4) << 3;

    auto issue = [&](int t) {
        const int buf = t % STAGES;
        const uint32_t sb = sbase + (uint32_t)(buf * SSTG) * 2u;
        const int kofs = t * BKS;
        const long long go0 = (long long)lrow * CDIM + kofs + lcb;
        const uint32_t d0 = (uint32_t)(lrow * SP + lcb) * 2u;
        cpa16(sb + (SA_H * 2u) + d0,      A_H + go0);
        cpa16(sb + (SA_H * 2u) + d0 + 16, A_H + go0 + 8);
        cpa16(sb + (SA_L * 2u) + d0,      A_L + go0);
        cpa16(sb + (SA_L * 2u) + d0 + 16, A_L + go0 + 8);
        cpa16(sb + (SB_H * 2u) + d0,      B_H + go0);
        cpa16(sb + (SB_H * 2u) + d0 + 16, B_H + go0 + 8);
        cpa16(sb + (SB_L * 2u) + d0,      B_L + go0);
        cpa16(sb + (SB_L * 2u) + d0 + 16, B_L + go0 + 8);
        cpa_commit();
    };

    float acc[2][8][4];
    #pragma unroll
    for (int i = 0; i < 2; i++)
        #pragma unroll
        for (int j = 0; j < 8; j++)
            #pragma unroll
            for (int q = 0; q < 4; q++) acc[i][j][q] = 0.f;

    const int T = CDIM / BKS;   // 8
    issue(0);

    for (int t = 0; t < T; t++) {
        cpa_wait<0>();
        __syncthreads();
        if (t + 1 < T) issue(t + 1); else cpa_commit();

        const int buf = t % STAGES;
        const uint32_t sb = sbase + (uint32_t)(buf * SSTG) * 2u;

        #pragma unroll
        for (int ks = 0; ks < 2; ks++) {
            const int kb = ks * 16;
            uint32_t aH[2][4], aL[2][4];
            #pragma unroll
            for (int mt = 0; mt < 2; mt++) {
                const uint32_t ro = (uint32_t)((wm * 32 + mt * 16 + qrow) * SP + kb + qcol) * 2u;
                ldsm_x4(aH[mt][0], aH[mt][1], aH[mt][2], aH[mt][3], sb + SA_H * 2u + ro);
                ldsm_x4(aL[mt][0], aL[mt][1], aL[mt][2], aL[mt][3], sb + SA_L * 2u + ro);
            }
            #pragma unroll
            for (int ng = 0; ng < 4; ng++) {
                const uint32_t bo = (uint32_t)((wn * 64 + ng * 16 + qrow) * SP + kb + qcol) * 2u;
                uint32_t bh[4], bl[4];
                ldsm_x4(bh[0], bh[1], bh[2], bh[3], sb + SB_H * 2u + bo);
                ldsm_x4(bl[0], bl[1], bl[2], bl[3], sb + SB_L * 2u + bo);
                #pragma unroll
                for (int sel = 0; sel < 2; sel++) {
                    const int nt = ng * 2 + sel;
                    const uint32_t bH0 = bh[sel], bH1 = bh[sel + 2];
                    const uint32_t bL0 = bl[sel], bL1 = bl[sel + 2];
                    #pragma unroll
                    for (int mt = 0; mt < 2; mt++) {
                        mma_bf16(acc[mt][nt], aH[mt][0], aH[mt][1], aH[mt][2], aH[mt][3], bL0, bL1);
                        mma_bf16(acc[mt][nt], aL[mt][0], aL[mt][1], aL[mt][2], aL[mt][3], bH0, bH1);
                        mma_bf16(acc[mt][nt], aH[mt][0], aH[mt][1], aH[mt][2], aH[mt][3], bH0, bH1);
                    }
                }
            }
        }
    }

    // ---- epilogue ----
    #pragma unroll
    for (int mt = 0; mt < 2; mt++) {
        #pragma unroll
        for (int nt = 0; nt < 8; nt++) {
            const int r0 = m0 + wm * 32 + mt * 16 + lr;
            const int c0 = n0 + wn * 64 + nt * 8 + lc * 2;
            if (z < 2) {
                __nv_bfloat16* DH = CbH + (size_t)z * M_ALL * CDIM;
                __nv_bfloat16* DL = CbL + (size_t)z * M_ALL * CDIM;
                #pragma unroll
                for (int rq = 0; rq < 2; rq++) {
                    const int r = r0 + rq * 8;
                    float v0 = acc[mt][nt][rq * 2 + 0];
                    float v1 = acc[mt][nt][rq * 2 + 1];
                    __nv_bfloat16 h0, l0, h1, l1;
                    bsplit(v0, h0, l0);
                    bsplit(v1, h1, l1);
                    const size_t o = (size_t)r * CDIM + c0;
                    *(__nv_bfloat162*)(DH + o) = __nv_bfloat162(h0, h1);
                    *(__nv_bfloat162*)(DL + o) = __nv_bfloat162(l0, l1);
                }
            } else {
                #pragma unroll
                for (int rq = 0; rq < 2; rq++) {
                    const int r = r0 + rq * 8;
                    const size_t o = (size_t)r * CDIM + c0;
                    *(__half2*)(C16 + o) =
                        __floats2half2_rn(acc[mt][nt][rq * 2 + 0], acc[mt][nt][rq * 2 + 1]);
                }
            }
        }
    }
}

// ---------------- scores GEMM: 3x-bf16; stores p_t fp16 + softmax partials ----------------
__global__ void __launch_bounds__(NTHR, 2)
scores_bf16(const __nv_bfloat16* __restrict__ h1H, const __nv_bfloat16* __restrict__ h1L,
            const __nv_bfloat16* __restrict__ h2H, const __nv_bfloat16* __restrict__ h2L,
            const int* __restrict__ adj, __half* __restrict__ pt,
            float* __restrict__ pm, float* __restrict__ ps)
{
    extern __shared__ __align__(16) __nv_bfloat16 smb[];
    constexpr int STAGES = 2;

    const int tid  = threadIdx.x;
    const int lane = tid & 31;
    const int warp = tid >> 5;
    const int wm = warp & 3, wn = warp >> 2;
    const int lr = lane >> 2, lc = lane & 3;
    const int n0 = blockIdx.x * BN;
    const int m0 = blockIdx.y * BM;
    const int z  = blockIdx.z;

    const long long BS = (long long)NSEQ * CDIM;
    const __nv_bfloat16* A_H = h1H + z * BS + (long long)m0 * CDIM;
    const __nv_bfloat16* A_L = h1L + z * BS + (long long)m0 * CDIM;
    const __nv_bfloat16* B_H = h2H + z * BS + (long long)n0 * CDIM;
    const __nv_bfloat16* B_L = h2L + z * BS + (long long)n0 * CDIM;

    uint32_t sbase = smem_u32(smb);

    const int lrow = tid >> 1;
    const int lcb  = (tid & 1) * 16;
    const int qrow = lane & 15;
    const int qcol = (lane >> 4) << 3;

    auto issue = [&](int t) {
        const int buf = t % STAGES;
        const uint32_t sb = sbase + (uint32_t)(buf * SSTG) * 2u;
        const int kofs = t * BKS;
        const long long go0 = (long long)lrow * CDIM + kofs + lcb;
        const uint32_t d0 = (uint32_t)(lrow * SP + lcb) * 2u;
        cpa16(sb + (SA_H * 2u) + d0,      A_H + go0);
        cpa16(sb + (SA_H * 2u) + d0 + 16, A_H + go0 + 8);
        cpa16(sb + (SA_L * 2u) + d0,      A_L + go0);
        cpa16(sb + (SA_L * 2u) + d0 + 16, A_L + go0 + 8);
        cpa16(sb + (SB_H * 2u) + d0,      B_H + go0);
        cpa16(sb + (SB_H * 2u) + d0 + 16, B_H + go0 + 8);
        cpa16(sb + (SB_L * 2u) + d0,      B_L + go0);
        cpa16(sb + (SB_L * 2u) + d0 + 16, B_L + go0 + 8);
        cpa_commit();
    };

    float acc[2][8][4];
    #pragma unroll
    for (int i = 0; i < 2; i++)
        #pragma unroll
        for (int j = 0; j < 8; j++)
            #pragma unroll
            for (int q = 0; q < 4; q++) acc[i][j][q] = 0.f;

    const int T = CDIM / BKS;   // 8
    issue(0);

    for (int t = 0; t < T; t++) {
        cpa_wait<0>();
        __syncthreads();
        if (t + 1 < T) issue(t + 1); else cpa_commit();

        const int buf = t % STAGES;
        const uint32_t sb = sbase + (uint32_t)(buf * SSTG) * 2u;

        #pragma unroll
        for (int ks = 0; ks < 2; ks++) {
            const int kb = ks * 16;
            uint32_t aH[2][4], aL[2][4];
            #pragma unroll
            for (int mt = 0; mt < 2; mt++) {
                const uint32_t ro = (uint32_t)((wm * 32 + mt * 16 + qrow) * SP + kb + qcol) * 2u;
                ldsm_x4(aH[mt][0], aH[mt][1], aH[mt][2], aH[mt][3], sb + SA_H * 2u + ro);
                ldsm_x4(aL[mt][0], aL[mt][1], aL[mt][2], aL[mt][3], sb + SA_L * 2u + ro);
            }
            #pragma unroll
            for (int ng = 0; ng < 4; ng++) {
                const uint32_t bo = (uint32_t)((wn * 64 + ng * 16 + qrow) * SP + kb + qcol) * 2u;
                uint32_t bh[4], bl[4];
                ldsm_x4(bh[0], bh[1], bh[2], bh[3], sb + SB_H * 2u + bo);
                ldsm_x4(bl[0], bl[1], bl[2], bl[3], sb + SB_L * 2u + bo);
                #pragma unroll
                for (int sel = 0; sel < 2; sel++) {
                    const int nt = ng * 2 + sel;
                    const uint32_t bH0 = bh[sel], bH1 = bh[sel + 2];
                    const uint32_t bL0 = bl[sel], bL1 = bl[sel + 2];
                    #pragma unroll
                    for (int mt = 0; mt < 2; mt++) {
                        mma_bf16(acc[mt][nt], aH[mt][0], aH[mt][1], aH[mt][2], aH[mt][3], bL0, bL1);
                        mma_bf16(acc[mt][nt], aL[mt][0], aL[mt][1], aL[mt][2], aL[mt][3], bH0, bH1);
                        mma_bf16(acc[mt][nt], aH[mt][0], aH[mt][1], aH[mt][2], aH[mt][3], bH0, bH1);
                    }
                }
            }
        }
    }

    // ---- epilogue pass A: leakyrelu + mask into acc, track per-row tile max ----
    float mx[2][2];
    mx[0][0] = mx[0][1] = mx[1][0] = mx[1][1] = -3.0e38f;
    #pragma unroll
    for (int mt = 0; mt < 2; mt++) {
        #pragma unroll
        for (int nt = 0; nt < 8; nt++) {
            const int r0 = m0 + wm * 32 + mt * 16 + lr;
            const int c0 = n0 + wn * 64 + nt * 8 + lc * 2;
            #pragma unroll
            for (int q = 0; q < 4; q++) {
                const int r = r0 + (q >> 1) * 8;
                const int c = c0 + (q & 1);
                float v = acc[mt][nt][q];
                v = (v > 0.f) ? v : ALPHA_SLOPE * v;
                v = (adj[(size_t)r * NSEQ + c] > 0) ? v : NEG_INF_F;
                acc[mt][nt][q] = v;
                mx[mt][q >> 1] = fmaxf(mx[mt][q >> 1], v);
            }
        }
    }

    // ---- tile-row max reduction ----
    float* red = reinterpret_cast<float*>(smb);   // reuse stage smem: [2][128]
    __syncthreads();

    #pragma unroll
    for (int mt = 0; mt < 2; mt++)
        #pragma unroll
        for (int qr = 0; qr < 2; qr++) {
            float v = mx[mt][qr];
            v = fmaxf(v, __shfl_xor_sync(0xffffffffu, v, 1));
            v = fmaxf(v, __shfl_xor_sync(0xffffffffu, v, 2));
            mx[mt][qr] = v;
        }
    if (lc == 0) {
        #pragma unroll
        for (int mt = 0; mt < 2; mt++)
            #pragma unroll
            for (int qr = 0; qr < 2; qr++)
                red[wn * 128 + wm * 32 + mt * 16 + qr * 8 + lr] = mx[mt][qr];
    }
    __syncthreads();
    float M[2][2];
    #pragma unroll
    for (int mt = 0; mt < 2; mt++)
        #pragma unroll
        for (int qr = 0; qr < 2; qr++) {
            const int lro = wm * 32 + mt * 16 + qr * 8 + lr;
            M[mt][qr] = fmaxf(red[lro], red[128 + lro]);
        }
    __syncthreads();

    // ---- pass B: exp, store p_t fp16, accumulate sum partials ----
    __half* Pp = pt + (size_t)z * NSEQ * NSEQ;
    float Ss[2][2];
    #pragma unroll
    for (int mt = 0; mt < 2; mt++)
        #pragma unroll
        for (int qr = 0; qr < 2; qr++) {
            float s = 0.f;
            const int r = m0 + wm * 32 + mt * 16 + qr * 8 + lr;
            #pragma unroll
            for (int nt = 0; nt < 8; nt++) {
                float pe0 = __expf(acc[mt][nt][qr * 2 + 0] - M[mt][qr]);
                float pe1 = __expf(acc[mt][nt][qr * 2 + 1] - M[mt][qr]);
                s += pe0 + pe1;
                const int c = n0 + wn * 64 + nt * 8 + lc * 2;
                *(__half2*)(Pp + (size_t)r * NSEQ + c) = __floats2half2_rn(pe0, pe1);
            }
            s += __shfl_xor_sync(0xffffffffu, s, 1);
            s += __shfl_xor_sync(0xffffffffu, s, 2);
            Ss[mt][qr] = s;
        }
    if (lc == 0) {
        #pragma unroll
        for (int mt = 0; mt < 2; mt++)
            #pragma unroll
            for (int qr = 0; qr < 2; qr++)
                red[wn * 128 + wm * 32 + mt * 16 + qr * 8 + lr] = Ss[mt][qr];
    }
    __syncthreads();
    if (wn == 0 && lc == 0) {
        #pragma unroll
        for (int mt = 0; mt < 2; mt++)
            #pragma unroll
            for (int qr = 0; qr < 2; qr++) {
                const int lro = wm * 32 + mt * 16 + qr * 8 + lr;
                const size_t o = ((size_t)z * NTILES + blockIdx.x) * NSEQ + m0 + lro;
                pm[o] = M[mt][qr];
                ps[o] = red[lro] + red[128 + lro];
            }
    }
}

// ---------------- combine: per-row softmax stats ----------------
__global__ void __launch_bounds__(256)
combine_kernel(const float* __restrict__ pm, const float* __restrict__ ps,
               float* __restrict__ rm, float* __restrict__ ri)
{
    const int g = blockIdx.x * 256 + threadIdx.x;
    const int z = g >> 11;
    const int row = g & 2047;
    const float* pmz = pm + (size_t)z * NTILES * NSEQ + row;
    const float* psz = ps + (size_t)z * NTILES * NSEQ + row;

    float m = -3.0e38f;
    #pragma unroll
    for (int t = 0; t < NTILES; t++) m = fmaxf(m, pmz[(size_t)t * NSEQ]);
    float s = 0.f;
    #pragma unroll
    for (int t = 0; t < NTILES; t++)
        s += psz[(size_t)t * NSEQ] * __expf(pmz[(size_t)t * NSEQ] - m);
    rm[g] = m;
    ri[g] = 1.0f / s;
}

// ---------------- AV: p_t fp16 staged, in-place scale, fp16 mma ----------------
// out[q,d] = relu( sum_k (p_t[q,k] * s_q,tile(k)) * h3[k,d] )
__global__ void __launch_bounds__(NTHR, 2)
av_fused(const __half* __restrict__ pt, const __half* __restrict__ h3,
         const float* __restrict__ pm,
         const float* __restrict__ rm, const float* __restrict__ ri,
         float* __restrict__ out)
{
    extern __shared__ __align__(16) uint8_t avs[];

    const int tid  = threadIdx.x;
    const int lane = tid & 31;
    const int warp = tid >> 5;
    const int wm = warp & 1;        // 2 warps over 64 rows
    const int wn = warp >> 1;       // 4 warps over 256 cols
    const int lr = lane >> 2, lc = lane & 3;
    const int m0 = blockIdx.x * AV_BM;
    const int z  = blockIdx.y;

    const __half* Ap = pt + (size_t)z * NSEQ * NSEQ + (size_t)m0 * NSEQ;
    const __half* Bp = h3 + (size_t)z * NSEQ * CDIM;

    uint32_t sbase = smem_u32(avs);

    const int qrow = lane & 15;
    const int qcol = (lane >> 4) << 3;

    // ---- precompute per-(row,tile) scale table: 64 x 16 half2 ----
    __half2* stab = (__half2*)(avs + AV_STAB);
    {
        const int rr  = tid & 63;
        const int kt0 = (tid >> 6) * 4;
        const float mrow_ = rm[(size_t)z * NSEQ + m0 + rr];
        const float irow_ = ri[(size_t)z * NSEQ + m0 + rr];
        #pragma unroll
        for (int j = 0; j < 4; j++) {
            const float pmv = pm[((size_t)z * NTILES + kt0 + j) * NSEQ + m0 + rr];
            const float s = __expf(pmv - mrow_) * irow_;
            stab[rr * NTILES + kt0 + j] = __float2half2_rn(s);
        }
    }

    const int crow = tid >> 2;      // 0..63
    const int cq   = tid & 3;

    auto issue = [&](int t) {
        const int buf = t % AV_NSTG;
        const uint32_t sA = sbase + (uint32_t)(buf * AV_STG2);
        const uint32_t sB = sA + AV_A_BYTES;
        const int kofs = t * BKS;
        {   // A: p_t fp16, 64x32
            const __half* src = Ap + (size_t)crow * NSEQ + kofs + cq * 8;
            cpa16(sA + (uint32_t)(crow * APT + cq * 8) * 2u, src);
        }
        {   // B: h3 fp16, 32x256
            const int brow = tid >> 3, bq = tid & 7;
            const __half* src = Bp + (size_t)(kofs + brow) * CDIM + bq * 32;
            const uint32_t d = sB + (uint32_t)(brow * BKP2 + bq * 32) * 2u;
            cpa16(d,      src);
            cpa16(d + 16, src + 8);
            cpa16(d + 32, src + 16);
            cpa16(d + 48, src + 24);
        }
        cpa_commit();
    };

    float acc[2][8][4];
    #pragma unroll
    for (int i = 0; i < 2; i++)
        #pragma unroll
        for (int j = 0; j < 8; j++)
            #pragma unroll
            for (int q = 0; q < 4; q++) acc[i][j][q] = 0.f;

    const int T = NSEQ / BKS;   // 64
    issue(0);
    issue(1);
    issue(2);
    __syncthreads();            // stab visible to all

    for (int t = 0; t < T; t++) {
        cpa_wait<AV_NSTG - 2>();
        __syncthreads();
        if (t + 3 < T) issue(t + 3); else cpa_commit();

        // ---- in-place scale of p_t tile t ----
        {
            uint8_t* aptr = avs + (size_t)(t % AV_NSTG) * AV_STG2
                          + (size_t)(crow * APT + cq * 8) * 2;
            const __half2 s2 = stab[crow * NTILES + (t >> 2)];
            uint4 w = *(uint4*)aptr;
            __half2* h = (__half2*)&w;
            h[0] = __hmul2(h[0], s2);
            h[1] = __hmul2(h[1], s2);
            h[2] = __hmul2(h[2], s2);
            h[3] = __hmul2(h[3], s2);
            *(uint4*)aptr = w;
        }
        __syncthreads();

        // ---- mma: A from stage (scaled), B from stage ----
        const uint32_t sA = sbase + (uint32_t)((t % AV_NSTG) * AV_STG2);
        const uint32_t sB = sA + AV_A_BYTES;

        #pragma unroll
        for (int ks = 0; ks < 2; ks++) {
            const int kb = ks * 16;
            uint32_t a[2][4];
            #pragma unroll
            for (int mt = 0; mt < 2; mt++) {
                const uint32_t ro = (uint32_t)((wm * 32 + mt * 16 + qrow) * APT + kb + qcol) * 2u;
                ldsm_x4(a[mt][0], a[mt][1], a[mt][2], a[mt][3], sA + ro);
            }
            #pragma unroll
            for (int ng = 0; ng < 4; ng++) {
                const int nb = wn * 64 + ng * 16;
                const uint32_t bo = (uint32_t)((kb + qrow) * BKP2 + nb + qcol) * 2u;
                uint32_t b[4];
                ldsm_x4_t(b[0], b[1], b[2], b[3], sB + bo);
                #pragma unroll
                for (int sel = 0; sel < 2; sel++) {
                    const int nt = ng * 2 + sel;
                    #pragma unroll
                    for (int mt = 0; mt < 2; mt++) {
                        mma_fp16(acc[mt][nt], a[mt][0], a[mt][1], a[mt][2], a[mt][3],
                                 b[2 * sel], b[2 * sel + 1]);
                    }
                }
            }
        }
    }

    // ---- epilogue: relu ----
    float* Cp = out + (size_t)z * NSEQ * CDIM;
    #pragma unroll
    for (int mt = 0; mt < 2; mt++) {
        #pragma unroll
        for (int nt = 0; nt < 8; nt++) {
            const int r0 = m0 + wm * 32 + mt * 16 + lr;
            const int c0 = wn * 64 + nt * 8 + lc * 2;
            #pragma unroll
            for (int q = 0; q < 4; q++) {
                const int r = r0 + (q >> 1) * 8;
                const int c = c0 + (q & 1);
                float v = acc[mt][nt][q];
                Cp[(size_t)r * CDIM + c] = (v > 0.f) ? v : 0.f;
            }
        }
    }
}

// ---------------- launcher ----------------
extern "C" void kernel_launch(void* const* d_in, const int* in_sizes, int n_in,
                              void* d_out, int out_size)
{
    const float* inp = (const float*)d_in[0];
    const int*   adj = (const int*)d_in[1];
    const float* W1  = (const float*)d_in[2];
    const float* W2  = (const float*)d_in[3];
    const float* W3  = (const float*)d_in[4];
    float* out = (float*)d_out;

    __nv_bfloat16 *xbH, *xbL, *wtH, *wtL, *hbH, *hbL;
    __half *h316, *pt;
    float *pm, *ps, *rm, *ri;
    cudaGetSymbolAddress((void**)&xbH,  g_xbH);
    cudaGetSymbolAddress((void**)&xbL,  g_xbL);
    cudaGetSymbolAddress((void**)&wtH,  g_wtH);
    cudaGetSymbolAddress((void**)&wtL,  g_wtL);
    cudaGetSymbolAddress((void**)&hbH,  g_hbH);
    cudaGetSymbolAddress((void**)&hbL,  g_hbL);
    cudaGetSymbolAddress((void**)&h316, g_h316);
    cudaGetSymbolAddress((void**)&pt,   g_pt);
    cudaGetSymbolAddress((void**)&pm,   g_pm);
    cudaGetSymbolAddress((void**)&ps,   g_ps);
    cudaGetSymbolAddress((void**)&rm,   g_rm);
    cudaGetSymbolAddress((void**)&ri,   g_ri);

    const int SM_BF = SSTG * 2 * 2;     // 81920 B
    cudaFuncSetAttribute(proj_bf16,   cudaFuncAttributeMaxDynamicSharedMemorySize, SM_BF);
    cudaFuncSetAttribute(scores_bf16, cudaFuncAttributeMaxDynamicSharedMemorySize, SM_BF);
    cudaFuncSetAttribute(av_fused,    cudaFuncAttributeMaxDynamicSharedMemorySize, SM_AV);

    // 0) split X (bf16 hi/lo) and W^T (bf16 hi/lo)
    {
        const int xn4 = (int)((size_t)M_ALL * CDIM / 4);
        split_x_bf16<<<(xn4 + 255) / 256, 256>>>(inp, xbH, xbL, xn4);
        dim3 gw(CDIM * CDIM / 256, 3);
        split_wt_bf16<<<gw, 256>>>(W1, W2, W3, wtH, wtL);
    }
    // 1) projections: z=0,1 -> bf16 hi/lo (h1,h2); z=2 -> fp16 (h3)
    {
        dim3 g(CDIM / BN, M_ALL / BM, 3);
        proj_bf16<<<g, NTHR, SM_BF>>>(xbH, xbL, wtH, wtL, hbH, hbL, h316);
    }
    // 2) scores -> p_t fp16 + per-tile softmax partials
    {
        dim3 g(NSEQ / BN, NSEQ / BM, BB);
        scores_bf16<<<g, NTHR, SM_BF>>>(hbH, hbL,
                                        hbH + (size_t)M_ALL * CDIM, hbL + (size_t)M_ALL * CDIM,
                                        adj, pt, pm, ps);
    }
    // 3) combine partials -> per-row (max, 1/sum)
    combine_kernel<<<(BB * NSEQ) / 256, 256>>>(pm, ps, rm, ri);
    // 4) AV with staged p_t and in-place scaling
    {
        dim3 g(NSEQ / AV_BM, BB);
        av_fused<<<g, NTHR, SM_AV>>>(pt, h316, pm, rm, ri, out);
    }
}